// round 11
// baseline (speedup 1.0000x reference)
#include <cuda_runtime.h>
#include <cuda_bf16.h>
#include <math.h>
#include <cstdint>

// Problem constants
#define BB 8
#define SS 1024
#define DD 512
#define HH 8
#define DKK 64
#define MM (BB*SS)   // 8192 rows
#define NELEM ((size_t)MM * DD)

// ---------------- scratch (static __device__: allocation-guard safe) --------
__device__ __nv_bfloat16 g_Xqh[NELEM], g_Xql[NELEM];
__device__ __nv_bfloat16 g_Xkh[NELEM], g_Xkl[NELEM];
__device__ __nv_bfloat16 g_Xvh[NELEM], g_Xvl[NELEM];
__device__ __nv_bfloat16 g_Qh[NELEM], g_Ql[NELEM];
__device__ __nv_bfloat16 g_Kh[NELEM], g_Kl[NELEM];
__device__ __nv_bfloat16 g_Vh[NELEM], g_Vl[NELEM];
__device__ __nv_bfloat16 g_Oh[NELEM], g_Ol[NELEM];
__device__ __nv_bfloat16 g_Wqh[DD * DD], g_Wql[DD * DD];
__device__ __nv_bfloat16 g_Wvh[DD * DD], g_Wvl[DD * DD];
__device__ __nv_bfloat16 g_Woh[DD * DD], g_Wol[DD * DD];
__device__ unsigned long long g_mbits[(size_t)MM * 16];
__device__ int g_lncnt[64];   // per-128-row-block completion counters

// ---------------- PTX helpers (base sm_103-safe) -----------------------------
__device__ __forceinline__ uint32_t smem_u32(const void* p) {
    uint32_t a;
    asm("{ .reg .u64 t; cvta.to.shared.u64 t, %1; cvt.u32.u64 %0, t; }" : "=r"(a) : "l"(p));
    return a;
}
#define CP_ASYNC16(dst, src) \
    asm volatile("cp.async.cg.shared.global [%0], [%1], 16;" :: "r"(dst), "l"(src) : "memory")
#define CP_COMMIT() asm volatile("cp.async.commit_group;" ::: "memory")
#define CP_WAIT1()  asm volatile("cp.async.wait_group 1;" ::: "memory")
#define CP_WAIT0()  asm volatile("cp.async.wait_group 0;" ::: "memory")

__device__ __forceinline__ void ldm_x4(uint32_t& r0, uint32_t& r1, uint32_t& r2,
                                       uint32_t& r3, uint32_t addr) {
    asm volatile("ldmatrix.sync.aligned.m8n8.x4.shared.b16 {%0,%1,%2,%3}, [%4];"
                 : "=r"(r0), "=r"(r1), "=r"(r2), "=r"(r3) : "r"(addr));
}
__device__ __forceinline__ void ldm_x4t(uint32_t& r0, uint32_t& r1, uint32_t& r2,
                                        uint32_t& r3, uint32_t addr) {
    asm volatile("ldmatrix.sync.aligned.m8n8.x4.trans.shared.b16 {%0,%1,%2,%3}, [%4];"
                 : "=r"(r0), "=r"(r1), "=r"(r2), "=r"(r3) : "r"(addr));
}
__device__ __forceinline__ void mma16816(float* d, const uint32_t* a, const uint32_t* b) {
    asm volatile("mma.sync.aligned.m16n8k16.row.col.f32.bf16.bf16.f32 "
                 "{%0,%1,%2,%3}, {%4,%5,%6,%7}, {%8,%9}, {%0,%1,%2,%3};"
                 : "+f"(d[0]), "+f"(d[1]), "+f"(d[2]), "+f"(d[3])
                 : "r"(a[0]), "r"(a[1]), "r"(a[2]), "r"(a[3]), "r"(b[0]), "r"(b[1]));
}
__device__ __forceinline__ uint32_t pack_bf2(float a, float b) {
    __nv_bfloat162 t = __floats2bfloat162_rn(a, b);
    return *(uint32_t*)&t;
}
__device__ __forceinline__ void split2(float a, float b, uint32_t& hi, uint32_t& lo) {
    const __nv_bfloat16 ha = __float2bfloat16(a), hb = __float2bfloat16(b);
    const float ra = a - __bfloat162float(ha), rb = b - __bfloat162float(hb);
    __nv_bfloat162 th; th.x = ha; th.y = hb;
    hi = *(uint32_t*)&th;
    lo = pack_bf2(ra, rb);
}

// ---------------------------------------------------------------------------
// Fused prepass kernel: split3 + wsplit3 + pack_mask + counter reset.
// ---------------------------------------------------------------------------
#define PREP_SPLIT_B 12288
#define PREP_WSPL_B  768
#define PREP_MASK_B  16384
#define PREP_TOTAL_B (PREP_SPLIT_B + PREP_WSPL_B + PREP_MASK_B)

__global__ __launch_bounds__(256) void prep_kernel(
    const float* __restrict__ Xq, const float* __restrict__ Xk,
    const float* __restrict__ Xv,
    __nv_bfloat16* __restrict__ Xqh, __nv_bfloat16* __restrict__ Xql,
    __nv_bfloat16* __restrict__ Xkh, __nv_bfloat16* __restrict__ Xkl,
    __nv_bfloat16* __restrict__ Xvh, __nv_bfloat16* __restrict__ Xvl,
    const float* __restrict__ Wq, const float* __restrict__ Wv,
    const float* __restrict__ Wo,
    __nv_bfloat16* __restrict__ Wqh, __nv_bfloat16* __restrict__ Wql,
    __nv_bfloat16* __restrict__ Wvh, __nv_bfloat16* __restrict__ Wvl,
    __nv_bfloat16* __restrict__ Woh, __nv_bfloat16* __restrict__ Wol,
    const int* __restrict__ smask, unsigned long long* __restrict__ bits)
{
    __shared__ float tile[32][33];
    const int bid = blockIdx.x;
    const int tid = threadIdx.x;

    if (bid == 0 && tid < 64) g_lncnt[tid] = 0;   // reset LN counters

    if (bid < PREP_SPLIT_B) {
        const int s = bid / 4096;
        const int blk = bid - s * 4096;
        const float* X = (s == 0) ? Xq : (s == 1) ? Xk : Xv;
        __nv_bfloat16* H = (s == 0) ? Xqh : (s == 1) ? Xkh : Xvh;
        __nv_bfloat16* L = (s == 0) ? Xql : (s == 1) ? Xkl : Xvl;
        const size_t i = ((size_t)blk * 256 + tid) * 4;
        float4 v = *(const float4*)(X + i);
        __nv_bfloat16 h[4], l[4];
        float x[4] = {v.x, v.y, v.z, v.w};
#pragma unroll
        for (int j = 0; j < 4; j++) {
            h[j] = __float2bfloat16(x[j]);
            l[j] = __float2bfloat16(x[j] - __bfloat162float(h[j]));
        }
        *(uint2*)(H + i) = *(uint2*)h;
        *(uint2*)(L + i) = *(uint2*)l;
    } else if (bid < PREP_SPLIT_B + PREP_WSPL_B) {
        const int w = bid - PREP_SPLIT_B;
        const int s = w / 256;
        const int rem = w - s * 256;
        const int bx = rem & 15, by = rem >> 4;
        const float* W = (s == 0) ? Wq : (s == 1) ? Wv : Wo;
        __nv_bfloat16* Ht = (s == 0) ? Wqh : (s == 1) ? Wvh : Woh;
        __nv_bfloat16* Lt = (s == 0) ? Wql : (s == 1) ? Wvl : Wol;
        const int tx = tid & 31, ty = tid >> 5;
        const int k0 = by * 32, n0 = bx * 32;
#pragma unroll
        for (int r = 0; r < 4; r++)
            tile[ty * 4 + r][tx] = W[(size_t)(k0 + ty * 4 + r) * DD + n0 + tx];
        __syncthreads();
#pragma unroll
        for (int r = 0; r < 4; r++) {
            const int n = n0 + ty * 4 + r;
            const float x = tile[tx][ty * 4 + r];
            const __nv_bfloat16 h = __float2bfloat16(x);
            Ht[(size_t)n * DD + k0 + tx] = h;
            Lt[(size_t)n * DD + k0 + tx] = __float2bfloat16(x - __bfloat162float(h));
        }
    } else {
        const int pb = bid - PREP_SPLIT_B - PREP_WSPL_B;
        const int gw = pb * 8 + (tid >> 5);
        const int lane = tid & 31;
        const int word = gw & 15;
        const int row  = gw >> 4;
        const int* p = smask + (size_t)row * SS + word * 64;
        const unsigned lo = __ballot_sync(0xffffffffu, p[lane] != 0);
        const unsigned hi = __ballot_sync(0xffffffffu, p[lane + 32] != 0);
        if (lane == 0)
            bits[(size_t)row * 16 + word] = ((unsigned long long)hi << 32) | lo;
    }
}

// ---------------------------------------------------------------------------
// mma.sync bf16x3 GEMM (256 threads, warp tile 32x64), K-chunk 32, cp.async
// double buffer. grid.z selects operand set. Optional fused LayerNorm in the
// fp32-output path: last CTA of each 128-row block normalizes it in place.
// ---------------------------------------------------------------------------
#define LDSP 40
#define OPB  (128 * LDSP * 2)
#define STAGE_B (4 * OPB)
#define MMG_SMEM (2 * STAGE_B)

extern __shared__ char mm_sm[];

__global__ __launch_bounds__(256) void mma_gemm_kernel(
    const __nv_bfloat16* __restrict__ Ah0, const __nv_bfloat16* __restrict__ Al0,
    const __nv_bfloat16* __restrict__ Ah1, const __nv_bfloat16* __restrict__ Al1,
    const __nv_bfloat16* __restrict__ Ah2, const __nv_bfloat16* __restrict__ Al2,
    const __nv_bfloat16* __restrict__ Bh0, const __nv_bfloat16* __restrict__ Bl0,
    const __nv_bfloat16* __restrict__ Bh1, const __nv_bfloat16* __restrict__ Bl1,
    const float* __restrict__ bias0, const float* __restrict__ bias1,
    const float* __restrict__ resid,
    float* __restrict__ C,
    __nv_bfloat16* __restrict__ Ch0, __nv_bfloat16* __restrict__ Cl0,
    __nv_bfloat16* __restrict__ Ch1, __nv_bfloat16* __restrict__ Cl1,
    __nv_bfloat16* __restrict__ Ch2, __nv_bfloat16* __restrict__ Cl2,
    const float* __restrict__ lng, const float* __restrict__ lnb)
{
    __shared__ int lnflag;
    const uint32_t smb = smem_u32(mm_sm);
    const int tid  = threadIdx.x;
    const int wid  = tid >> 5;
    const int lane = tid & 31;
    const int wm   = wid & 3;
    const int wn   = wid >> 2;
    const int m0 = blockIdx.y * 128, n0 = blockIdx.x * 128;
    const int z = blockIdx.z;
    const __nv_bfloat16* Ah = (z == 0) ? Ah0 : (z == 1) ? Ah1 : Ah2;
    const __nv_bfloat16* Al = (z == 0) ? Al0 : (z == 1) ? Al1 : Al2;
    const __nv_bfloat16* Bh = (z == 2) ? Bh1 : Bh0;
    const __nv_bfloat16* Bl = (z == 2) ? Bl1 : Bl0;
    const float* bias = (z == 2) ? bias1 : bias0;
    __nv_bfloat16* Ch = (z == 0) ? Ch0 : (z == 1) ? Ch1 : Ch2;
    __nv_bfloat16* Cl = (z == 0) ? Cl0 : (z == 1) ? Cl1 : Cl2;

    const char* srcs[4] = {
        (const char*)(Ah + (size_t)m0 * DD),
        (const char*)(Al + (size_t)m0 * DD),
        (const char*)(Bh + (size_t)n0 * DD),
        (const char*)(Bl + (size_t)n0 * DD)
    };

    int l_op[8], l_row[8], l_seg[8];
#pragma unroll
    for (int i = 0; i < 8; i++) {
        const int idx = tid + i * 256;
        l_op[i]  = idx >> 9;
        l_row[i] = (idx & 511) >> 2;
        l_seg[i] = idx & 3;
    }

    float acc[2][8][4];
#pragma unroll
    for (int mt = 0; mt < 2; mt++)
#pragma unroll
        for (int nt = 0; nt < 8; nt++)
#pragma unroll
            for (int r = 0; r < 4; r++) acc[mt][nt][r] = 0.f;

    const int lrow = lane & 15;
    const int lkof = (lane >> 4) * 8;

#pragma unroll
    for (int i = 0; i < 8; i++) {
        CP_ASYNC16(smb + l_op[i] * OPB + l_row[i] * 80 + l_seg[i] * 16,
                   srcs[l_op[i]] + (size_t)l_row[i] * 1024 + l_seg[i] * 16);
    }
    CP_COMMIT();

    for (int c = 0; c < 16; c++) {
        if (c + 1 < 16) {
            const uint32_t sb = smb + ((c + 1) & 1) * STAGE_B;
            const int koff = (c + 1) * 64;
#pragma unroll
            for (int i = 0; i < 8; i++) {
                CP_ASYNC16(sb + l_op[i] * OPB + l_row[i] * 80 + l_seg[i] * 16,
                           srcs[l_op[i]] + (size_t)l_row[i] * 1024 + koff + l_seg[i] * 16);
            }
            CP_COMMIT();
            CP_WAIT1();
        } else {
            CP_WAIT0();
        }
        __syncthreads();

        const uint32_t sb = smb + (c & 1) * STAGE_B;
#pragma unroll
        for (int ks = 0; ks < 32; ks += 16) {
            uint32_t ah[2][4], al[2][4];
#pragma unroll
            for (int mt = 0; mt < 2; mt++) {
                const int r = wm * 32 + mt * 16 + lrow;
                const uint32_t ad = sb + r * 80 + (ks + lkof) * 2;
                ldm_x4(ah[mt][0], ah[mt][1], ah[mt][2], ah[mt][3], ad);
                ldm_x4(al[mt][0], al[mt][1], al[mt][2], al[mt][3], ad + OPB);
            }
            uint32_t bh[8][2], bl[8][2];
#pragma unroll
            for (int np = 0; np < 4; np++) {
                const int r = wn * 64 + np * 16 + lrow;
                const uint32_t bd = sb + 2 * OPB + r * 80 + (ks + lkof) * 2;
                uint32_t t0, t1, t2, t3;
                ldm_x4(t0, t1, t2, t3, bd);
                bh[np * 2][0] = t0; bh[np * 2][1] = t2;
                bh[np * 2 + 1][0] = t1; bh[np * 2 + 1][1] = t3;
                ldm_x4(t0, t1, t2, t3, bd + OPB);
                bl[np * 2][0] = t0; bl[np * 2][1] = t2;
                bl[np * 2 + 1][0] = t1; bl[np * 2 + 1][1] = t3;
            }
#pragma unroll
            for (int mt = 0; mt < 2; mt++)
#pragma unroll
                for (int nt = 0; nt < 8; nt++)
                    mma16816(acc[mt][nt], ah[mt], bh[nt]);
#pragma unroll
            for (int mt = 0; mt < 2; mt++)
#pragma unroll
                for (int nt = 0; nt < 8; nt++)
                    mma16816(acc[mt][nt], ah[mt], bl[nt]);
#pragma unroll
            for (int mt = 0; mt < 2; mt++)
#pragma unroll
                for (int nt = 0; nt < 8; nt++)
                    mma16816(acc[mt][nt], al[mt], bh[nt]);
        }
        __syncthreads();
    }

    const int qr = lane >> 2;
    const int qc = (lane & 3) * 2;
#pragma unroll
    for (int mt = 0; mt < 2; mt++) {
#pragma unroll
        for (int nt = 0; nt < 8; nt++) {
            const int col = n0 + wn * 64 + nt * 8 + qc;
            const float2 bv = *(const float2*)(bias + col);
#pragma unroll
            for (int half = 0; half < 2; half++) {
                const int row = m0 + wm * 32 + mt * 16 + qr + half * 8;
                float ox = acc[mt][nt][half * 2 + 0] + bv.x;
                float oy = acc[mt][nt][half * 2 + 1] + bv.y;
                if (Ch) {
                    uint32_t hi, lo;
                    split2(ox, oy, hi, lo);
                    *(uint32_t*)(Ch + (size_t)row * DD + col) = hi;
                    *(uint32_t*)(Cl + (size_t)row * DD + col) = lo;
                } else {
                    if (resid) {
                        const float2 rv = *(const float2*)(resid + (size_t)row * DD + col);
                        ox += rv.x; oy += rv.y;
                    }
                    float2 o; o.x = ox; o.y = oy;
                    *(float2*)(C + (size_t)row * DD + col) = o;
                }
            }
        }
    }

    // ---- fused LayerNorm: last CTA of this 128-row block normalizes it ----
    if (!Ch && lng) {
        __threadfence();
        __syncthreads();
        if (tid == 0) {
            const int done = atomicAdd(&g_lncnt[blockIdx.y], 1);
            lnflag = (done == 3) ? 1 : 0;
        }
        __syncthreads();
        if (lnflag) {
            const int warp = tid >> 5;
            for (int rr = warp; rr < 128; rr += 8) {
                float* xr = C + (size_t)(m0 + rr) * DD;
                float4 v[4];
                float s = 0.f, s2 = 0.f;
#pragma unroll
                for (int w = 0; w < 4; w++) {
                    v[w] = *(const float4*)(xr + w * 128 + lane * 4);
                    s  += v[w].x + v[w].y + v[w].z + v[w].w;
                    s2 += v[w].x * v[w].x + v[w].y * v[w].y +
                          v[w].z * v[w].z + v[w].w * v[w].w;
                }
#pragma unroll
                for (int o = 16; o > 0; o >>= 1) {
                    s  += __shfl_xor_sync(0xffffffffu, s,  o);
                    s2 += __shfl_xor_sync(0xffffffffu, s2, o);
                }
                const float mu  = s * (1.f / DD);
                const float var = s2 * (1.f / DD) - mu * mu;
                const float inv = rsqrtf(var + 1e-5f);
#pragma unroll
                for (int w = 0; w < 4; w++) {
                    const int cc = w * 128 + lane * 4;
                    float4 gv = *(const float4*)(lng + cc);
                    float4 bv2 = *(const float4*)(lnb + cc);
                    float4 o;
                    o.x = (v[w].x - mu) * inv * gv.x + bv2.x;
                    o.y = (v[w].y - mu) * inv * gv.y + bv2.y;
                    o.z = (v[w].z - mu) * inv * gv.z + bv2.z;
                    o.w = (v[w].w - mu) * inv * gv.w + bv2.w;
                    *(float4*)(xr + cc) = o;
                }
            }
        }
    }
}

// ---------------------------------------------------------------------------
// Tensor-core dual-score causal flash attention v4.1 (active-guard restored).
// CTA = 64 q-rows, 128 threads (4 warps x 16 rows); K-tile 32; 3 CTAs/SM.
// ---------------------------------------------------------------------------
#define ATS   144
#define QOP   9216
#define KOP   4608
#define STG   (6 * KOP)
#define AT_SMEM (2 * QOP + 2 * STG)

extern __shared__ char at_sm[];

__device__ __forceinline__ void at_load_tile32(
    uint32_t smb, int buf, int tid, int b, int kt0, int hc,
    const __nv_bfloat16* Kh, const __nv_bfloat16* Kl,
    const __nv_bfloat16* Rkh, const __nv_bfloat16* Rkl,
    const __nv_bfloat16* Vh, const __nv_bfloat16* Vl)
{
    const char* srcs[6] = {(const char*)Kh, (const char*)Kl, (const char*)Rkh,
                           (const char*)Rkl, (const char*)Vh, (const char*)Vl};
    const uint32_t base = smb + 2 * QOP + buf * STG;
#pragma unroll
    for (int i = 0; i < 12; i++) {
        const int idx = tid + i * 128;
        const int op = idx >> 8, r = (idx >> 3) & 31, seg = idx & 7;
        CP_ASYNC16(base + op * KOP + r * ATS + seg * 16,
                   srcs[op] + ((size_t)(b * SS + kt0 + r) * DD + hc) * 2 + seg * 16);
    }
}

__global__ __launch_bounds__(128, 3) void attn_mma_kernel(
    const __nv_bfloat16* __restrict__ Qh, const __nv_bfloat16* __restrict__ Ql,
    const __nv_bfloat16* __restrict__ Kh, const __nv_bfloat16* __restrict__ Kl,
    const __nv_bfloat16* __restrict__ Vh, const __nv_bfloat16* __restrict__ Vl,
    const __nv_bfloat16* __restrict__ Rqh, const __nv_bfloat16* __restrict__ Rql,
    const __nv_bfloat16* __restrict__ Rkh, const __nv_bfloat16* __restrict__ Rkl,
    const unsigned long long* __restrict__ mbits, const float* __restrict__ gammas,
    __nv_bfloat16* __restrict__ Oh, __nv_bfloat16* __restrict__ Ol)
{
    const uint32_t smb = smem_u32(at_sm);
    const int tid = threadIdx.x, lane = tid & 31, w = tid >> 5;
    const int bh = blockIdx.x & 63;
    const int q0 = (15 - (blockIdx.x >> 6)) * 64;
    const int b  = bh >> 3, h = bh & 7;
    const int hc = h * DKK;

    float g  = gammas[h];
    float sp = (g > 20.f) ? g : log1pf(__expf(g));
    float te = __expf(-sp);
    te = fminf(fmaxf(te, 1e-5f), 1e5f);
    const float f1 = 0.125f;
    const float f2 = te * rsqrtf((float)DD);
    const float f2f1 = f2 * 8.0f;

    const int qcb = (lane & 3) * 2;
    const int gg = lane >> 3, l8 = lane & 7;
    const int mrw = w * 16 + ((gg & 1) << 3) + l8;
    const int r1 = q0 + w * 16 + (lane >> 2);
    const int r2 = r1 + 8;

    {
        const char* qsrc[4] = {(const char*)Qh, (const char*)Ql,
                               (const char*)Rqh, (const char*)Rql};
#pragma unroll
        for (int i = 0; i < 16; i++) {
            const int idx = tid + i * 128;
            const int op = idx >> 9, r = (idx >> 3) & 63, seg = idx & 7;
            const uint32_t base = (op < 2) ? (smb + 2 * QOP + op * QOP)
                                           : (smb + (op - 2) * QOP);
            CP_ASYNC16(base + r * ATS + seg * 16,
                       qsrc[op] + ((size_t)(b * SS + q0 + r) * DD + hc) * 2 + seg * 16);
        }
        CP_COMMIT(); CP_WAIT0();
        __syncthreads();
    }
    uint32_t qph[4][4], qpl[4][4];
#pragma unroll
    for (int ks = 0; ks < 4; ks++) {
        const uint32_t qa = smb + 2 * QOP + mrw * ATS +
                            (ks * 16 + ((gg >> 1) << 3)) * 2;
        ldm_x4(qph[ks][0], qph[ks][1], qph[ks][2], qph[ks][3], qa);
        ldm_x4(qpl[ks][0], qpl[ks][1], qpl[ks][2], qpl[ks][3], qa + QOP);
    }
    __syncthreads();

    float oacc[8][4];
#pragma unroll
    for (int nt = 0; nt < 8; nt++)
#pragma unroll
        for (int e = 0; e < 4; e++) oacc[nt][e] = 0.f;
    float mrow[2] = {-1e30f, -1e30f};
    float lsum[2] = {0.f, 0.f};

    const int T = q0 / 32 + 2;

    at_load_tile32(smb, 0, tid, b, 0, hc, Kh, Kl, Rkh, Rkl, Vh, Vl);
    CP_COMMIT();

    for (int t = 0; t < T; t++) {
        const int kt0 = t * 32;
        if (t + 1 < T) {
            at_load_tile32(smb, (t + 1) & 1, tid, b, kt0 + 32, hc, Kh, Kl, Rkh, Rkl, Vh, Vl);
            CP_COMMIT(); CP_WAIT1();
        } else {
            CP_WAIT0();
        }
        __syncthreads();

        const uint32_t sb = smb + 2 * QOP + (t & 1) * STG;
        const bool active = (kt0 < q0 + w * 16 + 16);

        if (active) {
            float sc[4][4];
#pragma unroll
            for (int nt = 0; nt < 4; nt++)
#pragma unroll
                for (int e = 0; e < 4; e++) sc[nt][e] = 0.f;

            // ---- s2: raw scores ----
#pragma unroll
            for (int ks = 0; ks < 4; ks++) {
                uint32_t qh4[4], ql4[4];
                const uint32_t qa = smb + mrw * ATS + (ks * 16 + ((gg >> 1) << 3)) * 2;
                ldm_x4(qh4[0], qh4[1], qh4[2], qh4[3], qa);
                ldm_x4(ql4[0], ql4[1], ql4[2], ql4[3], qa + QOP);
                uint32_t bh2[4][2], bl2[4][2];
#pragma unroll
                for (int np = 0; np < 2; np++) {
                    const uint32_t ad = sb + 2 * KOP +
                        (np * 16 + ((gg >> 1) << 3) + l8) * ATS +
                        (ks * 16 + ((gg & 1) << 3)) * 2;
                    uint32_t t0, t1, t2, t3;
                    ldm_x4(t0, t1, t2, t3, ad);
                    bh2[np*2][0] = t0; bh2[np*2][1] = t1;
                    bh2[np*2+1][0] = t2; bh2[np*2+1][1] = t3;
                    ldm_x4(t0, t1, t2, t3, ad + KOP);
                    bl2[np*2][0] = t0; bl2[np*2][1] = t1;
                    bl2[np*2+1][0] = t2; bl2[np*2+1][1] = t3;
                }
#pragma unroll
                for (int nt = 0; nt < 4; nt++)
                    mma16816(sc[nt], qh4, bh2[nt]);
#pragma unroll
                for (int nt = 0; nt < 4; nt++)
                    mma16816(sc[nt], qh4, bl2[nt]);
#pragma unroll
                for (int nt = 0; nt < 4; nt++)
                    mma16816(sc[nt], ql4, bh2[nt]);
            }

            // ---- gate s2 by packed mask ----
            const unsigned long long mw1 =
                mbits[(size_t)(b * SS + r1) * 16 + (kt0 >> 6)];
            const unsigned long long mw2 =
                mbits[(size_t)(b * SS + r2) * 16 + (kt0 >> 6)];
            const int msh = kt0 & 32;
#pragma unroll
            for (int nt = 0; nt < 4; nt++) {
                const int j0 = msh + nt * 8 + qcb;
                sc[nt][0] = ((mw1 >> j0) & 1)       ? sc[nt][0] * f2f1 : 0.f;
                sc[nt][1] = ((mw1 >> (j0 + 1)) & 1) ? sc[nt][1] * f2f1 : 0.f;
                sc[nt][2] = ((mw2 >> j0) & 1)       ? sc[nt][2] * f2f1 : 0.f;
                sc[nt][3] = ((mw2 >> (j0 + 1)) & 1) ? sc[nt][3] * f2f1 : 0.f;
            }

            // ---- s1: projected scores ----
#pragma unroll
            for (int ks = 0; ks < 4; ks++) {
                uint32_t bh2[4][2], bl2[4][2];
#pragma unroll
                for (int np = 0; np < 2; np++) {
                    const uint32_t ad = sb +
                        (np * 16 + ((gg >> 1) << 3) + l8) * ATS +
                        (ks * 16 + ((gg & 1) << 3)) * 2;
                    uint32_t t0, t1, t2, t3;
                    ldm_x4(t0, t1, t2, t3, ad);
                    bh2[np*2][0] = t0; bh2[np*2][1] = t1;
                    bh2[np*2+1][0] = t2; bh2[np*2+1][1] = t3;
                    ldm_x4(t0, t1, t2, t3, ad + KOP);
                    bl2[np*2][0] = t0; bl2[np*2][1] = t1;
                    bl2[np*2+1][0] = t2; bl2[np*2+1][1] = t3;
                }
#pragma unroll
                for (int nt = 0; nt < 4; nt++)
                    mma16816(sc[nt], qph[ks], bh2[nt]);
#pragma unroll
                for (int nt = 0; nt < 4; nt++)
                    mma16816(sc[nt], qph[ks], bl2[nt]);
#pragma unroll
                for (int nt = 0; nt < 4; nt++)
                    mma16816(sc[nt], qpl[ks], bh2[nt]);
            }

            // ---- causal mask + final scale ----
#pragma unroll
            for (int nt = 0; nt < 4; nt++) {
                const int gj0 = kt0 + nt * 8 + qcb;
                sc[nt][0] = (gj0     < r1) ? sc[nt][0] * f1 : -INFINITY;
                sc[nt][1] = (gj0 + 1 < r1) ? sc[nt][1] * f1 : -INFINITY;
                sc[nt][2] = (gj0     < r2) ? sc[nt][2] * f1 : -INFINITY;
                sc[nt][3] = (gj0 + 1 < r2) ? sc[nt][3] * f1 : -INFINITY;
            }

            // ---- online softmax ----
            float rm1 = -INFINITY, rm2 = -INFINITY;
#pragma unroll
            for (int nt = 0; nt < 4; nt++) {
                rm1 = fmaxf(rm1, fmaxf(sc[nt][0], sc[nt][1]));
                rm2 = fmaxf(rm2, fmaxf(sc[nt][2], sc[nt][3]));
            }
            rm1 = fmaxf(rm1, __shfl_xor_sync(0xffffffffu, rm1, 1));
            rm1 = fmaxf(rm1, __shfl_xor_sync(0xffffffffu, rm1, 2));
            rm2 = fmaxf(rm2, __shfl_xor_sync(0xffffffffu, rm2, 1));
            rm2 = fmaxf(rm2, __shfl_xor_sync(0xffffffffu, rm2, 2));
            const float mn1 = fmaxf(mrow[0], rm1);
            const float mn2 = fmaxf(mrow[1], rm2);
            const float scl1 = __expf(mrow[0] - mn1);
            const float scl2 = __expf(mrow[1] - mn2);
            mrow[0] = mn1; mrow[1] = mn2;

            float ps1 = 0.f, ps2 = 0.f;
#pragma unroll
            for (int nt = 0; nt < 4; nt++) {
                sc[nt][0] = __expf(sc[nt][0] - mn1);
                sc[nt][1] = __expf(sc[nt][1] - mn1);
                sc[nt][2] = __expf(sc[nt][2] - mn2);
                sc[nt][3] = __expf(sc[nt][3] - mn2);
                ps1 += sc[nt][0] + sc[nt][1];
                ps2 += sc[nt][2] + sc[nt][3];
            }
            ps1 += __shfl_xor_sync(0xffffffffu, ps1, 1);
            ps1 += __shfl_xor_sync(0xffffffffu, ps1, 2);
            ps2 += __shfl_xor_sync(0xffffffffu, ps2, 1);
            ps2 += __shfl_xor_sync(0xffffffffu, ps2, 2);
            lsum[0] = lsum[0] * scl1 + ps1;
            lsum[1] = lsum[1] * scl2 + ps2;

#pragma unroll
            for (int nt = 0; nt < 8; nt++) {
                oacc[nt][0] *= scl1; oacc[nt][1] *= scl1;
                oacc[nt][2] *= scl2; oacc[nt][3] *= scl2;
            }

            uint32_t pha[2][4], pla[2][4];
#pragma unroll
            for (int j = 0; j < 2; j++) {
                split2(sc[2*j][0],   sc[2*j][1],   pha[j][0], pla[j][0]);
                split2(sc[2*j][2],   sc[2*j][3],   pha[j][1], pla[j][1]);
                split2(sc[2*j+1][0], sc[2*j+1][1], pha[j][2], pla[j][2]);
                split2(sc[2*j+1][2], sc[2*j+1][3], pha[j][3], pla[j][3]);
            }

            // ---- PV (bf16x3) ----
#pragma unroll
            for (int j = 0; j < 2; j++) {
                uint32_t vh2[8][2], vl2[8][2];
#pragma unroll
                for (int np = 0; np < 4; np++) {
                    const uint32_t ad = sb + 4 * KOP +
                        (j * 16 + ((gg & 1) << 3) + l8) * ATS +
                        (np * 16 + ((gg >> 1) << 3)) * 2;
                    uint32_t t0, t1, t2, t3;
                    ldm_x4t(t0, t1, t2, t3, ad);
                    vh2[np*2][0] = t0; vh2[np*2][1] = t1;
                    vh2[np*2+1][0] = t2; vh2[np*2+1][1] = t3;
                    ldm_x4t(t0, t1, t2, t3, ad + KOP);
                    vl2[np*2][0] = t0; vl2[np*2][1] = t1;
                    vl2[np*2+1][0] = t2; vl2[np*2+1][1] = t3;
                }
#pragma unroll
                for (int nt = 0; nt < 8; nt++)
                    mma16816(oacc[nt], pha[j], vh2[nt]);
#pragma unroll
                for (int nt = 0; nt < 8; nt++)
                    mma16816(oacc[nt], pha[j], vl2[nt]);
#pragma unroll
                for (int nt = 0; nt < 8; nt++)
                    mma16816(oacc[nt], pla[j], vh2[nt]);
            }
        }
        __syncthreads();
    }

    const float rr1 = (lsum[0] > 0.f) ? (1.f / lsum[0]) : 0.f;
    const float rr2 = (lsum[1] > 0.f) ? (1.f / lsum[1]) : 0.f;
    const size_t base1 = (size_t)(b * SS + r1) * DD + hc;
    const size_t base2 = (size_t)(b * SS + r2) * DD + hc;
#pragma unroll
    for (int nt = 0; nt < 8; nt++) {
        const int co = nt * 8 + qcb;
        uint32_t hi, lo;
        split2(oacc[nt][0] * rr1, oacc[nt][1] * rr1, hi, lo);
        *(uint32_t*)(Oh + base1 + co) = hi;
        *(uint32_t*)(Ol + base1 + co) = lo;
        split2(oacc[nt][2] * rr2, oacc[nt][3] * rr2, hi, lo);
        *(uint32_t*)(Oh + base2 + co) = hi;
        *(uint32_t*)(Ol + base2 + co) = lo;
    }
}

// ---------------------------------------------------------------------------
extern "C" void kernel_launch(void* const* d_in, const int* in_sizes, int n_in,
                              void* d_out, int out_size)
{
    const float* q_in  = (const float*)d_in[0];
    const float* k_in  = (const float*)d_in[1];
    const float* v_in  = (const float*)d_in[2];
    const int*   smask = (const int*)  d_in[3];
    const float* Wq    = (const float*)d_in[4];
    const float* bq    = (const float*)d_in[5];
    const float* Wv    = (const float*)d_in[6];
    const float* bv    = (const float*)d_in[7];
    const float* Wo    = (const float*)d_in[8];
    const float* bo    = (const float*)d_in[9];
    const float* gam   = (const float*)d_in[10];
    const float* ln_g  = (const float*)d_in[11];
    const float* ln_b  = (const float*)d_in[12];
    float* out = (float*)d_out;

    __nv_bfloat16 *Xqh, *Xql, *Xkh, *Xkl, *Xvh, *Xvl;
    __nv_bfloat16 *Qh, *Ql, *Kh, *Kl, *Vh, *Vl, *Oh, *Ol;
    __nv_bfloat16 *Wqh, *Wql, *Wvh, *Wvl, *Woh, *Wol;
    unsigned long long* mbits;
    cudaGetSymbolAddress((void**)&Xqh, g_Xqh); cudaGetSymbolAddress((void**)&Xql, g_Xql);
    cudaGetSymbolAddress((void**)&Xkh, g_Xkh); cudaGetSymbolAddress((void**)&Xkl, g_Xkl);
    cudaGetSymbolAddress((void**)&Xvh, g_Xvh); cudaGetSymbolAddress((void**)&Xvl, g_Xvl);
    cudaGetSymbolAddress((void**)&Qh, g_Qh);   cudaGetSymbolAddress((void**)&Ql, g_Ql);
    cudaGetSymbolAddress((void**)&Kh, g_Kh);   cudaGetSymbolAddress((void**)&Kl, g_Kl);
    cudaGetSymbolAddress((void**)&Vh, g_Vh);   cudaGetSymbolAddress((void**)&Vl, g_Vl);
    cudaGetSymbolAddress((void**)&Oh, g_Oh);   cudaGetSymbolAddress((void**)&Ol, g_Ol);
    cudaGetSymbolAddress((void**)&Wqh, g_Wqh); cudaGetSymbolAddress((void**)&Wql, g_Wql);
    cudaGetSymbolAddress((void**)&Wvh, g_Wvh); cudaGetSymbolAddress((void**)&Wvl, g_Wvl);
    cudaGetSymbolAddress((void**)&Woh, g_Woh); cudaGetSymbolAddress((void**)&Wol, g_Wol);
    cudaGetSymbolAddress((void**)&mbits, g_mbits);

    cudaFuncSetAttribute(mma_gemm_kernel, cudaFuncAttributeMaxDynamicSharedMemorySize,
                         (int)MMG_SMEM);
    cudaFuncSetAttribute(attn_mma_kernel, cudaFuncAttributeMaxDynamicSharedMemorySize,
                         (int)AT_SMEM);

    const dim3 gb(256);

    // fused prepasses: splits + weight transpose/split + mask pack + cnt reset
    prep_kernel<<<PREP_TOTAL_B, gb>>>(
        q_in, k_in, v_in, Xqh, Xql, Xkh, Xkl, Xvh, Xvl,
        Wq, Wv, Wo, Wqh, Wql, Wvh, Wvl, Woh, Wol,
        smask, mbits);

    // Q + K + V projections fused in one launch (grid.z = 3)
    const dim3 ggrid3(DD / 128, MM / 128, 3);
    mma_gemm_kernel<<<ggrid3, gb, MMG_SMEM>>>(
        Xqh, Xql, Xkh, Xkl, Xvh, Xvl,
        Wqh, Wql, Wvh, Wvl,
        bq, bv, nullptr, nullptr,
        Qh, Ql, Kh, Kl, Vh, Vl,
        nullptr, nullptr);

    // tensor-core attention: 1024 CTAs, heavy-first, 3 CTAs/SM
    attn_mma_kernel<<<1024, 128, AT_SMEM>>>(Qh, Ql, Kh, Kl, Vh, Vl,
                                            Xqh, Xql, Xkh, Xkl, mbits, gam, Oh, Ol);

    // output projection + bias + residual + fused LayerNorm -> fp32 out
    const dim3 ggrid(DD / 128, MM / 128, 1);
    mma_gemm_kernel<<<ggrid, gb, MMG_SMEM>>>(
        Oh, Ol, Oh, Ol, Oh, Ol,
        Woh, Wol, Woh, Wol,
        bo, bo, q_in, out,
        nullptr, nullptr, nullptr, nullptr, nullptr, nullptr,
        ln_g, ln_b);
}

// round 12
// speedup vs baseline: 1.0222x; 1.0222x over previous
#include <cuda_runtime.h>
#include <cuda_bf16.h>
#include <math.h>
#include <cstdint>

// Problem constants
#define BB 8
#define SS 1024
#define DD 512
#define HH 8
#define DKK 64
#define MM (BB*SS)   // 8192 rows
#define NELEM ((size_t)MM * DD)

// ---------------- scratch (static __device__: allocation-guard safe) --------
__device__ __nv_bfloat16 g_Xqh[NELEM], g_Xql[NELEM];
__device__ __nv_bfloat16 g_Xkh[NELEM], g_Xkl[NELEM];
__device__ __nv_bfloat16 g_Xvh[NELEM], g_Xvl[NELEM];
__device__ __nv_bfloat16 g_Qh[NELEM], g_Ql[NELEM];
__device__ __nv_bfloat16 g_Kh[NELEM], g_Kl[NELEM];
__device__ __nv_bfloat16 g_Vh[NELEM], g_Vl[NELEM];
__device__ __nv_bfloat16 g_Oh[NELEM], g_Ol[NELEM];
__device__ __nv_bfloat16 g_Wqh[DD * DD], g_Wql[DD * DD];
__device__ __nv_bfloat16 g_Wvh[DD * DD], g_Wvl[DD * DD];
__device__ __nv_bfloat16 g_Woh[DD * DD], g_Wol[DD * DD];
__device__ unsigned long long g_mbits[(size_t)MM * 16];

// ---------------- PTX helpers (base sm_103-safe) -----------------------------
__device__ __forceinline__ uint32_t smem_u32(const void* p) {
    uint32_t a;
    asm("{ .reg .u64 t; cvta.to.shared.u64 t, %1; cvt.u32.u64 %0, t; }" : "=r"(a) : "l"(p));
    return a;
}
#define CP_ASYNC16(dst, src) \
    asm volatile("cp.async.cg.shared.global [%0], [%1], 16;" :: "r"(dst), "l"(src) : "memory")
#define CP_COMMIT() asm volatile("cp.async.commit_group;" ::: "memory")
#define CP_WAIT1()  asm volatile("cp.async.wait_group 1;" ::: "memory")
#define CP_WAIT0()  asm volatile("cp.async.wait_group 0;" ::: "memory")

__device__ __forceinline__ void ldm_x4(uint32_t& r0, uint32_t& r1, uint32_t& r2,
                                       uint32_t& r3, uint32_t addr) {
    asm volatile("ldmatrix.sync.aligned.m8n8.x4.shared.b16 {%0,%1,%2,%3}, [%4];"
                 : "=r"(r0), "=r"(r1), "=r"(r2), "=r"(r3) : "r"(addr));
}
__device__ __forceinline__ void ldm_x4t(uint32_t& r0, uint32_t& r1, uint32_t& r2,
                                        uint32_t& r3, uint32_t addr) {
    asm volatile("ldmatrix.sync.aligned.m8n8.x4.trans.shared.b16 {%0,%1,%2,%3}, [%4];"
                 : "=r"(r0), "=r"(r1), "=r"(r2), "=r"(r3) : "r"(addr));
}
__device__ __forceinline__ void mma16816(float* d, const uint32_t* a, const uint32_t* b) {
    asm volatile("mma.sync.aligned.m16n8k16.row.col.f32.bf16.bf16.f32 "
                 "{%0,%1,%2,%3}, {%4,%5,%6,%7}, {%8,%9}, {%0,%1,%2,%3};"
                 : "+f"(d[0]), "+f"(d[1]), "+f"(d[2]), "+f"(d[3])
                 : "r"(a[0]), "r"(a[1]), "r"(a[2]), "r"(a[3]), "r"(b[0]), "r"(b[1]));
}
__device__ __forceinline__ uint32_t pack_bf2(float a, float b) {
    __nv_bfloat162 t = __floats2bfloat162_rn(a, b);
    return *(uint32_t*)&t;
}
__device__ __forceinline__ void split2(float a, float b, uint32_t& hi, uint32_t& lo) {
    const __nv_bfloat16 ha = __float2bfloat16(a), hb = __float2bfloat16(b);
    const float ra = a - __bfloat162float(ha), rb = b - __bfloat162float(hb);
    __nv_bfloat162 th; th.x = ha; th.y = hb;
    hi = *(uint32_t*)&th;
    lo = pack_bf2(ra, rb);
}

// ---------------------------------------------------------------------------
// Fused prepass kernel: split3 + wsplit3 + pack_mask.
// ---------------------------------------------------------------------------
#define PREP_SPLIT_B 12288
#define PREP_WSPL_B  768
#define PREP_MASK_B  16384
#define PREP_TOTAL_B (PREP_SPLIT_B + PREP_WSPL_B + PREP_MASK_B)

__global__ __launch_bounds__(256) void prep_kernel(
    const float* __restrict__ Xq, const float* __restrict__ Xk,
    const float* __restrict__ Xv,
    __nv_bfloat16* __restrict__ Xqh, __nv_bfloat16* __restrict__ Xql,
    __nv_bfloat16* __restrict__ Xkh, __nv_bfloat16* __restrict__ Xkl,
    __nv_bfloat16* __restrict__ Xvh, __nv_bfloat16* __restrict__ Xvl,
    const float* __restrict__ Wq, const float* __restrict__ Wv,
    const float* __restrict__ Wo,
    __nv_bfloat16* __restrict__ Wqh, __nv_bfloat16* __restrict__ Wql,
    __nv_bfloat16* __restrict__ Wvh, __nv_bfloat16* __restrict__ Wvl,
    __nv_bfloat16* __restrict__ Woh, __nv_bfloat16* __restrict__ Wol,
    const int* __restrict__ smask, unsigned long long* __restrict__ bits)
{
    __shared__ float tile[32][33];
    const int bid = blockIdx.x;
    const int tid = threadIdx.x;

    if (bid < PREP_SPLIT_B) {
        const int s = bid / 4096;
        const int blk = bid - s * 4096;
        const float* X = (s == 0) ? Xq : (s == 1) ? Xk : Xv;
        __nv_bfloat16* H = (s == 0) ? Xqh : (s == 1) ? Xkh : Xvh;
        __nv_bfloat16* L = (s == 0) ? Xql : (s == 1) ? Xkl : Xvl;
        const size_t i = ((size_t)blk * 256 + tid) * 4;
        float4 v = *(const float4*)(X + i);
        __nv_bfloat16 h[4], l[4];
        float x[4] = {v.x, v.y, v.z, v.w};
#pragma unroll
        for (int j = 0; j < 4; j++) {
            h[j] = __float2bfloat16(x[j]);
            l[j] = __float2bfloat16(x[j] - __bfloat162float(h[j]));
        }
        *(uint2*)(H + i) = *(uint2*)h;
        *(uint2*)(L + i) = *(uint2*)l;
    } else if (bid < PREP_SPLIT_B + PREP_WSPL_B) {
        const int w = bid - PREP_SPLIT_B;
        const int s = w / 256;
        const int rem = w - s * 256;
        const int bx = rem & 15, by = rem >> 4;
        const float* W = (s == 0) ? Wq : (s == 1) ? Wv : Wo;
        __nv_bfloat16* Ht = (s == 0) ? Wqh : (s == 1) ? Wvh : Woh;
        __nv_bfloat16* Lt = (s == 0) ? Wql : (s == 1) ? Wvl : Wol;
        const int tx = tid & 31, ty = tid >> 5;
        const int k0 = by * 32, n0 = bx * 32;
#pragma unroll
        for (int r = 0; r < 4; r++)
            tile[ty * 4 + r][tx] = W[(size_t)(k0 + ty * 4 + r) * DD + n0 + tx];
        __syncthreads();
#pragma unroll
        for (int r = 0; r < 4; r++) {
            const int n = n0 + ty * 4 + r;
            const float x = tile[tx][ty * 4 + r];
            const __nv_bfloat16 h = __float2bfloat16(x);
            Ht[(size_t)n * DD + k0 + tx] = h;
            Lt[(size_t)n * DD + k0 + tx] = __float2bfloat16(x - __bfloat162float(h));
        }
    } else {
        const int pb = bid - PREP_SPLIT_B - PREP_WSPL_B;
        const int gw = pb * 8 + (tid >> 5);
        const int lane = tid & 31;
        const int word = gw & 15;
        const int row  = gw >> 4;
        const int* p = smask + (size_t)row * SS + word * 64;
        const unsigned lo = __ballot_sync(0xffffffffu, p[lane] != 0);
        const unsigned hi = __ballot_sync(0xffffffffu, p[lane + 32] != 0);
        if (lane == 0)
            bits[(size_t)row * 16 + word] = ((unsigned long long)hi << 32) | lo;
    }
}

// ---------------------------------------------------------------------------
// mma.sync bf16x3 GEMM (256 threads, warp tile 32x64), K-chunk 32, cp.async
// double buffer. grid.z selects operand set.
// ---------------------------------------------------------------------------
#define LDSP 40
#define OPB  (128 * LDSP * 2)
#define STAGE_B (4 * OPB)
#define MMG_SMEM (2 * STAGE_B)

extern __shared__ char mm_sm[];

__global__ __launch_bounds__(256) void mma_gemm_kernel(
    const __nv_bfloat16* __restrict__ Ah0, const __nv_bfloat16* __restrict__ Al0,
    const __nv_bfloat16* __restrict__ Ah1, const __nv_bfloat16* __restrict__ Al1,
    const __nv_bfloat16* __restrict__ Ah2, const __nv_bfloat16* __restrict__ Al2,
    const __nv_bfloat16* __restrict__ Bh0, const __nv_bfloat16* __restrict__ Bl0,
    const __nv_bfloat16* __restrict__ Bh1, const __nv_bfloat16* __restrict__ Bl1,
    const float* __restrict__ bias0, const float* __restrict__ bias1,
    const float* __restrict__ resid,
    float* __restrict__ C,
    __nv_bfloat16* __restrict__ Ch0, __nv_bfloat16* __restrict__ Cl0,
    __nv_bfloat16* __restrict__ Ch1, __nv_bfloat16* __restrict__ Cl1,
    __nv_bfloat16* __restrict__ Ch2, __nv_bfloat16* __restrict__ Cl2)
{
    const uint32_t smb = smem_u32(mm_sm);
    const int tid  = threadIdx.x;
    const int wid  = tid >> 5;
    const int lane = tid & 31;
    const int wm   = wid & 3;
    const int wn   = wid >> 2;
    const int m0 = blockIdx.y * 128, n0 = blockIdx.x * 128;
    const int z = blockIdx.z;
    const __nv_bfloat16* Ah = (z == 0) ? Ah0 : (z == 1) ? Ah1 : Ah2;
    const __nv_bfloat16* Al = (z == 0) ? Al0 : (z == 1) ? Al1 : Al2;
    const __nv_bfloat16* Bh = (z == 2) ? Bh1 : Bh0;
    const __nv_bfloat16* Bl = (z == 2) ? Bl1 : Bl0;
    const float* bias = (z == 2) ? bias1 : bias0;
    __nv_bfloat16* Ch = (z == 0) ? Ch0 : (z == 1) ? Ch1 : Ch2;
    __nv_bfloat16* Cl = (z == 0) ? Cl0 : (z == 1) ? Cl1 : Cl2;

    const char* srcs[4] = {
        (const char*)(Ah + (size_t)m0 * DD),
        (const char*)(Al + (size_t)m0 * DD),
        (const char*)(Bh + (size_t)n0 * DD),
        (const char*)(Bl + (size_t)n0 * DD)
    };

    int l_op[8], l_row[8], l_seg[8];
#pragma unroll
    for (int i = 0; i < 8; i++) {
        const int idx = tid + i * 256;
        l_op[i]  = idx >> 9;
        l_row[i] = (idx & 511) >> 2;
        l_seg[i] = idx & 3;
    }

    float acc[2][8][4];
#pragma unroll
    for (int mt = 0; mt < 2; mt++)
#pragma unroll
        for (int nt = 0; nt < 8; nt++)
#pragma unroll
            for (int r = 0; r < 4; r++) acc[mt][nt][r] = 0.f;

    const int lrow = lane & 15;
    const int lkof = (lane >> 4) * 8;

#pragma unroll
    for (int i = 0; i < 8; i++) {
        CP_ASYNC16(smb + l_op[i] * OPB + l_row[i] * 80 + l_seg[i] * 16,
                   srcs[l_op[i]] + (size_t)l_row[i] * 1024 + l_seg[i] * 16);
    }
    CP_COMMIT();

    for (int c = 0; c < 16; c++) {
        if (c + 1 < 16) {
            const uint32_t sb = smb + ((c + 1) & 1) * STAGE_B;
            const int koff = (c + 1) * 64;
#pragma unroll
            for (int i = 0; i < 8; i++) {
                CP_ASYNC16(sb + l_op[i] * OPB + l_row[i] * 80 + l_seg[i] * 16,
                           srcs[l_op[i]] + (size_t)l_row[i] * 1024 + koff + l_seg[i] * 16);
            }
            CP_COMMIT();
            CP_WAIT1();
        } else {
            CP_WAIT0();
        }
        __syncthreads();

        const uint32_t sb = smb + (c & 1) * STAGE_B;
#pragma unroll
        for (int ks = 0; ks < 32; ks += 16) {
            uint32_t ah[2][4], al[2][4];
#pragma unroll
            for (int mt = 0; mt < 2; mt++) {
                const int r = wm * 32 + mt * 16 + lrow;
                const uint32_t ad = sb + r * 80 + (ks + lkof) * 2;
                ldm_x4(ah[mt][0], ah[mt][1], ah[mt][2], ah[mt][3], ad);
                ldm_x4(al[mt][0], al[mt][1], al[mt][2], al[mt][3], ad + OPB);
            }
            uint32_t bh[8][2], bl[8][2];
#pragma unroll
            for (int np = 0; np < 4; np++) {
                const int r = wn * 64 + np * 16 + lrow;
                const uint32_t bd = sb + 2 * OPB + r * 80 + (ks + lkof) * 2;
                uint32_t t0, t1, t2, t3;
                ldm_x4(t0, t1, t2, t3, bd);
                bh[np * 2][0] = t0; bh[np * 2][1] = t2;
                bh[np * 2 + 1][0] = t1; bh[np * 2 + 1][1] = t3;
                ldm_x4(t0, t1, t2, t3, bd + OPB);
                bl[np * 2][0] = t0; bl[np * 2][1] = t2;
                bl[np * 2 + 1][0] = t1; bl[np * 2 + 1][1] = t3;
            }
#pragma unroll
            for (int mt = 0; mt < 2; mt++)
#pragma unroll
                for (int nt = 0; nt < 8; nt++)
                    mma16816(acc[mt][nt], ah[mt], bh[nt]);
#pragma unroll
            for (int mt = 0; mt < 2; mt++)
#pragma unroll
                for (int nt = 0; nt < 8; nt++)
                    mma16816(acc[mt][nt], ah[mt], bl[nt]);
#pragma unroll
            for (int mt = 0; mt < 2; mt++)
#pragma unroll
                for (int nt = 0; nt < 8; nt++)
                    mma16816(acc[mt][nt], al[mt], bh[nt]);
        }
        __syncthreads();
    }

    const int qr = lane >> 2;
    const int qc = (lane & 3) * 2;
#pragma unroll
    for (int mt = 0; mt < 2; mt++) {
#pragma unroll
        for (int nt = 0; nt < 8; nt++) {
            const int col = n0 + wn * 64 + nt * 8 + qc;
            const float2 bv = *(const float2*)(bias + col);
#pragma unroll
            for (int half = 0; half < 2; half++) {
                const int row = m0 + wm * 32 + mt * 16 + qr + half * 8;
                float ox = acc[mt][nt][half * 2 + 0] + bv.x;
                float oy = acc[mt][nt][half * 2 + 1] + bv.y;
                if (Ch) {
                    uint32_t hi, lo;
                    split2(ox, oy, hi, lo);
                    *(uint32_t*)(Ch + (size_t)row * DD + col) = hi;
                    *(uint32_t*)(Cl + (size_t)row * DD + col) = lo;
                } else {
                    if (resid) {
                        const float2 rv = *(const float2*)(resid + (size_t)row * DD + col);
                        ox += rv.x; oy += rv.y;
                    }
                    float2 o; o.x = ox; o.y = oy;
                    *(float2*)(C + (size_t)row * DD + col) = o;
                }
            }
        }
    }
}

// ---------------------------------------------------------------------------
// Tensor-core dual-score causal flash attention v4.1 (K-tile 32, 3 CTAs/SM,
// heavy-first, per-warp active guard).
// ---------------------------------------------------------------------------
#define ATS   144
#define QOP   9216
#define KOP   4608
#define STG   (6 * KOP)
#define AT_SMEM (2 * QOP + 2 * STG)

extern __shared__ char at_sm[];

__device__ __forceinline__ void at_load_tile32(
    uint32_t smb, int buf, int tid, int b, int kt0, int hc,
    const __nv_bfloat16* Kh, const __nv_bfloat16* Kl,
    const __nv_bfloat16* Rkh, const __nv_bfloat16* Rkl,
    const __nv_bfloat16* Vh, const __nv_bfloat16* Vl)
{
    const char* srcs[6] = {(const char*)Kh, (const char*)Kl, (const char*)Rkh,
                           (const char*)Rkl, (const char*)Vh, (const char*)Vl};
    const uint32_t base = smb + 2 * QOP + buf * STG;
#pragma unroll
    for (int i = 0; i < 12; i++) {
        const int idx = tid + i * 128;
        const int op = idx >> 8, r = (idx >> 3) & 31, seg = idx & 7;
        CP_ASYNC16(base + op * KOP + r * ATS + seg * 16,
                   srcs[op] + ((size_t)(b * SS + kt0 + r) * DD + hc) * 2 + seg * 16);
    }
}

__global__ __launch_bounds__(128, 3) void attn_mma_kernel(
    const __nv_bfloat16* __restrict__ Qh, const __nv_bfloat16* __restrict__ Ql,
    const __nv_bfloat16* __restrict__ Kh, const __nv_bfloat16* __restrict__ Kl,
    const __nv_bfloat16* __restrict__ Vh, const __nv_bfloat16* __restrict__ Vl,
    const __nv_bfloat16* __restrict__ Rqh, const __nv_bfloat16* __restrict__ Rql,
    const __nv_bfloat16* __restrict__ Rkh, const __nv_bfloat16* __restrict__ Rkl,
    const unsigned long long* __restrict__ mbits, const float* __restrict__ gammas,
    __nv_bfloat16* __restrict__ Oh, __nv_bfloat16* __restrict__ Ol)
{
    const uint32_t smb = smem_u32(at_sm);
    const int tid = threadIdx.x, lane = tid & 31, w = tid >> 5;
    const int bh = blockIdx.x & 63;
    const int q0 = (15 - (blockIdx.x >> 6)) * 64;
    const int b  = bh >> 3, h = bh & 7;
    const int hc = h * DKK;

    float g  = gammas[h];
    float sp = (g > 20.f) ? g : log1pf(__expf(g));
    float te = __expf(-sp);
    te = fminf(fmaxf(te, 1e-5f), 1e5f);
    const float f1 = 0.125f;
    const float f2 = te * rsqrtf((float)DD);
    const float f2f1 = f2 * 8.0f;

    const int qcb = (lane & 3) * 2;
    const int gg = lane >> 3, l8 = lane & 7;
    const int mrw = w * 16 + ((gg & 1) << 3) + l8;
    const int r1 = q0 + w * 16 + (lane >> 2);
    const int r2 = r1 + 8;

    {
        const char* qsrc[4] = {(const char*)Qh, (const char*)Ql,
                               (const char*)Rqh, (const char*)Rql};
#pragma unroll
        for (int i = 0; i < 16; i++) {
            const int idx = tid + i * 128;
            const int op = idx >> 9, r = (idx >> 3) & 63, seg = idx & 7;
            const uint32_t base = (op < 2) ? (smb + 2 * QOP + op * QOP)
                                           : (smb + (op - 2) * QOP);
            CP_ASYNC16(base + r * ATS + seg * 16,
                       qsrc[op] + ((size_t)(b * SS + q0 + r) * DD + hc) * 2 + seg * 16);
        }
        CP_COMMIT(); CP_WAIT0();
        __syncthreads();
    }
    uint32_t qph[4][4], qpl[4][4];
#pragma unroll
    for (int ks = 0; ks < 4; ks++) {
        const uint32_t qa = smb + 2 * QOP + mrw * ATS +
                            (ks * 16 + ((gg >> 1) << 3)) * 2;
        ldm_x4(qph[ks][0], qph[ks][1], qph[ks][2], qph[ks][3], qa);
        ldm_x4(qpl[ks][0], qpl[ks][1], qpl[ks][2], qpl[ks][3], qa + QOP);
    }
    __syncthreads();

    float oacc[8][4];
#pragma unroll
    for (int nt = 0; nt < 8; nt++)
#pragma unroll
        for (int e = 0; e < 4; e++) oacc[nt][e] = 0.f;
    float mrow[2] = {-1e30f, -1e30f};
    float lsum[2] = {0.f, 0.f};

    const int T = q0 / 32 + 2;

    at_load_tile32(smb, 0, tid, b, 0, hc, Kh, Kl, Rkh, Rkl, Vh, Vl);
    CP_COMMIT();

    for (int t = 0; t < T; t++) {
        const int kt0 = t * 32;
        if (t + 1 < T) {
            at_load_tile32(smb, (t + 1) & 1, tid, b, kt0 + 32, hc, Kh, Kl, Rkh, Rkl, Vh, Vl);
            CP_COMMIT(); CP_WAIT1();
        } else {
            CP_WAIT0();
        }
        __syncthreads();

        const uint32_t sb = smb + 2 * QOP + (t & 1) * STG;
        const bool active = (kt0 < q0 + w * 16 + 16);

        if (active) {
            float sc[4][4];
#pragma unroll
            for (int nt = 0; nt < 4; nt++)
#pragma unroll
                for (int e = 0; e < 4; e++) sc[nt][e] = 0.f;

            // ---- s2: raw scores ----
#pragma unroll
            for (int ks = 0; ks < 4; ks++) {
                uint32_t qh4[4], ql4[4];
                const uint32_t qa = smb + mrw * ATS + (ks * 16 + ((gg >> 1) << 3)) * 2;
                ldm_x4(qh4[0], qh4[1], qh4[2], qh4[3], qa);
                ldm_x4(ql4[0], ql4[1], ql4[2], ql4[3], qa + QOP);
                uint32_t bh2[4][2], bl2[4][2];
#pragma unroll
                for (int np = 0; np < 2; np++) {
                    const uint32_t ad = sb + 2 * KOP +
                        (np * 16 + ((gg >> 1) << 3) + l8) * ATS +
                        (ks * 16 + ((gg & 1) << 3)) * 2;
                    uint32_t t0, t1, t2, t3;
                    ldm_x4(t0, t1, t2, t3, ad);
                    bh2[np*2][0] = t0; bh2[np*2][1] = t1;
                    bh2[np*2+1][0] = t2; bh2[np*2+1][1] = t3;
                    ldm_x4(t0, t1, t2, t3, ad + KOP);
                    bl2[np*2][0] = t0; bl2[np*2][1] = t1;
                    bl2[np*2+1][0] = t2; bl2[np*2+1][1] = t3;
                }
#pragma unroll
                for (int nt = 0; nt < 4; nt++)
                    mma16816(sc[nt], qh4, bh2[nt]);
#pragma unroll
                for (int nt = 0; nt < 4; nt++)
                    mma16816(sc[nt], qh4, bl2[nt]);
#pragma unroll
                for (int nt = 0; nt < 4; nt++)
                    mma16816(sc[nt], ql4, bh2[nt]);
            }

            // ---- gate s2 by packed mask ----
            const unsigned long long mw1 =
                mbits[(size_t)(b * SS + r1) * 16 + (kt0 >> 6)];
            const unsigned long long mw2 =
                mbits[(size_t)(b * SS + r2) * 16 + (kt0 >> 6)];
            const int msh = kt0 & 32;
#pragma unroll
            for (int nt = 0; nt < 4; nt++) {
                const int j0 = msh + nt * 8 + qcb;
                sc[nt][0] = ((mw1 >> j0) & 1)       ? sc[nt][0] * f2f1 : 0.f;
                sc[nt][1] = ((mw1 >> (j0 + 1)) & 1) ? sc[nt][1] * f2f1 : 0.f;
                sc[nt][2] = ((mw2 >> j0) & 1)       ? sc[nt][2] * f2f1 : 0.f;
                sc[nt][3] = ((mw2 >> (j0 + 1)) & 1) ? sc[nt][3] * f2f1 : 0.f;
            }

            // ---- s1: projected scores ----
#pragma unroll
            for (int ks = 0; ks < 4; ks++) {
                uint32_t bh2[4][2], bl2[4][2];
#pragma unroll
                for (int np = 0; np < 2; np++) {
                    const uint32_t ad = sb +
                        (np * 16 + ((gg >> 1) << 3) + l8) * ATS +
                        (ks * 16 + ((gg & 1) << 3)) * 2;
                    uint32_t t0, t1, t2, t3;
                    ldm_x4(t0, t1, t2, t3, ad);
                    bh2[np*2][0] = t0; bh2[np*2][1] = t1;
                    bh2[np*2+1][0] = t2; bh2[np*2+1][1] = t3;
                    ldm_x4(t0, t1, t2, t3, ad + KOP);
                    bl2[np*2][0] = t0; bl2[np*2][1] = t1;
                    bl2[np*2+1][0] = t2; bl2[np*2+1][1] = t3;
                }
#pragma unroll
                for (int nt = 0; nt < 4; nt++)
                    mma16816(sc[nt], qph[ks], bh2[nt]);
#pragma unroll
                for (int nt = 0; nt < 4; nt++)
                    mma16816(sc[nt], qph[ks], bl2[nt]);
#pragma unroll
                for (int nt = 0; nt < 4; nt++)
                    mma16816(sc[nt], qpl[ks], bh2[nt]);
            }

            // ---- causal mask + final scale ----
#pragma unroll
            for (int nt = 0; nt < 4; nt++) {
                const int gj0 = kt0 + nt * 8 + qcb;
                sc[nt][0] = (gj0     < r1) ? sc[nt][0] * f1 : -INFINITY;
                sc[nt][1] = (gj0 + 1 < r1) ? sc[nt][1] * f1 : -INFINITY;
                sc[nt][2] = (gj0     < r2) ? sc[nt][2] * f1 : -INFINITY;
                sc[nt][3] = (gj0 + 1 < r2) ? sc[nt][3] * f1 : -INFINITY;
            }

            // ---- online softmax ----
            float rm1 = -INFINITY, rm2 = -INFINITY;
#pragma unroll
            for (int nt = 0; nt < 4; nt++) {
                rm1 = fmaxf(rm1, fmaxf(sc[nt][0], sc[nt][1]));
                rm2 = fmaxf(rm2, fmaxf(sc[nt][2], sc[nt][3]));
            }
            rm1 = fmaxf(rm1, __shfl_xor_sync(0xffffffffu, rm1, 1));
            rm1 = fmaxf(rm1, __shfl_xor_sync(0xffffffffu, rm1, 2));
            rm2 = fmaxf(rm2, __shfl_xor_sync(0xffffffffu, rm2, 1));
            rm2 = fmaxf(rm2, __shfl_xor_sync(0xffffffffu, rm2, 2));
            const float mn1 = fmaxf(mrow[0], rm1);
            const float mn2 = fmaxf(mrow[1], rm2);
            const float scl1 = __expf(mrow[0] - mn1);
            const float scl2 = __expf(mrow[1] - mn2);
            mrow[0] = mn1; mrow[1] = mn2;

            float ps1 = 0.f, ps2 = 0.f;
#pragma unroll
            for (int nt = 0; nt < 4; nt++) {
                sc[nt][0] = __expf(sc[nt][0] - mn1);
                sc[nt][1] = __expf(sc[nt][1] - mn1);
                sc[nt][2] = __expf(sc[nt][2] - mn2);
                sc[nt][3] = __expf(sc[nt][3] - mn2);
                ps1 += sc[nt][0] + sc[nt][1];
                ps2 += sc[nt][2] + sc[nt][3];
            }
            ps1 += __shfl_xor_sync(0xffffffffu, ps1, 1);
            ps1 += __shfl_xor_sync(0xffffffffu, ps1, 2);
            ps2 += __shfl_xor_sync(0xffffffffu, ps2, 1);
            ps2 += __shfl_xor_sync(0xffffffffu, ps2, 2);
            lsum[0] = lsum[0] * scl1 + ps1;
            lsum[1] = lsum[1] * scl2 + ps2;

#pragma unroll
            for (int nt = 0; nt < 8; nt++) {
                oacc[nt][0] *= scl1; oacc[nt][1] *= scl1;
                oacc[nt][2] *= scl2; oacc[nt][3] *= scl2;
            }

            uint32_t pha[2][4], pla[2][4];
#pragma unroll
            for (int j = 0; j < 2; j++) {
                split2(sc[2*j][0],   sc[2*j][1],   pha[j][0], pla[j][0]);
                split2(sc[2*j][2],   sc[2*j][3],   pha[j][1], pla[j][1]);
                split2(sc[2*j+1][0], sc[2*j+1][1], pha[j][2], pla[j][2]);
                split2(sc[2*j+1][2], sc[2*j+1][3], pha[j][3], pla[j][3]);
            }

            // ---- PV (bf16x3) ----
#pragma unroll
            for (int j = 0; j < 2; j++) {
                uint32_t vh2[8][2], vl2[8][2];
#pragma unroll
                for (int np = 0; np < 4; np++) {
                    const uint32_t ad = sb + 4 * KOP +
                        (j * 16 + ((gg & 1) << 3) + l8) * ATS +
                        (np * 16 + ((gg >> 1) << 3)) * 2;
                    uint32_t t0, t1, t2, t3;
                    ldm_x4t(t0, t1, t2, t3, ad);
                    vh2[np*2][0] = t0; vh2[np*2][1] = t1;
                    vh2[np*2+1][0] = t2; vh2[np*2+1][1] = t3;
                    ldm_x4t(t0, t1, t2, t3, ad + KOP);
                    vl2[np*2][0] = t0; vl2[np*2][1] = t1;
                    vl2[np*2+1][0] = t2; vl2[np*2+1][1] = t3;
                }
#pragma unroll
                for (int nt = 0; nt < 8; nt++)
                    mma16816(oacc[nt], pha[j], vh2[nt]);
#pragma unroll
                for (int nt = 0; nt < 8; nt++)
                    mma16816(oacc[nt], pha[j], vl2[nt]);
#pragma unroll
                for (int nt = 0; nt < 8; nt++)
                    mma16816(oacc[nt], pla[j], vh2[nt]);
            }
        }
        __syncthreads();
    }

    const float rr1 = (lsum[0] > 0.f) ? (1.f / lsum[0]) : 0.f;
    const float rr2 = (lsum[1] > 0.f) ? (1.f / lsum[1]) : 0.f;
    const size_t base1 = (size_t)(b * SS + r1) * DD + hc;
    const size_t base2 = (size_t)(b * SS + r2) * DD + hc;
#pragma unroll
    for (int nt = 0; nt < 8; nt++) {
        const int co = nt * 8 + qcb;
        uint32_t hi, lo;
        split2(oacc[nt][0] * rr1, oacc[nt][1] * rr1, hi, lo);
        *(uint32_t*)(Oh + base1 + co) = hi;
        *(uint32_t*)(Ol + base1 + co) = lo;
        split2(oacc[nt][2] * rr2, oacc[nt][3] * rr2, hi, lo);
        *(uint32_t*)(Oh + base2 + co) = hi;
        *(uint32_t*)(Ol + base2 + co) = lo;
    }
}

// ---------------------------------------------------------------------------
// In-place LayerNorm: one warp per row of 512 floats.
// ---------------------------------------------------------------------------
__global__ __launch_bounds__(256) void ln_kernel(
    float* __restrict__ X, const float* __restrict__ gam, const float* __restrict__ bet)
{
    const int warp = threadIdx.x >> 5, lane = threadIdx.x & 31;
    const size_t row = (size_t)blockIdx.x * 8 + warp;
    float* xr = X + row * DD;

    float4 v[4];
    float s = 0.f, s2 = 0.f;
#pragma unroll
    for (int w = 0; w < 4; w++) {
        v[w] = *(const float4*)(xr + w * 128 + lane * 4);
        s  += v[w].x + v[w].y + v[w].z + v[w].w;
        s2 += v[w].x * v[w].x + v[w].y * v[w].y + v[w].z * v[w].z + v[w].w * v[w].w;
    }
#pragma unroll
    for (int o = 16; o > 0; o >>= 1) {
        s  += __shfl_xor_sync(0xffffffffu, s,  o);
        s2 += __shfl_xor_sync(0xffffffffu, s2, o);
    }
    const float mu  = s * (1.f / DD);
    const float var = s2 * (1.f / DD) - mu * mu;
    const float inv = rsqrtf(var + 1e-5f);
#pragma unroll
    for (int w = 0; w < 4; w++) {
        const int c = w * 128 + lane * 4;
        float4 gv = *(const float4*)(gam + c);
        float4 bv = *(const float4*)(bet + c);
        float4 o;
        o.x = (v[w].x - mu) * inv * gv.x + bv.x;
        o.y = (v[w].y - mu) * inv * gv.y + bv.y;
        o.z = (v[w].z - mu) * inv * gv.z + bv.z;
        o.w = (v[w].w - mu) * inv * gv.w + bv.w;
        *(float4*)(xr + c) = o;
    }
}

// ---------------------------------------------------------------------------
extern "C" void kernel_launch(void* const* d_in, const int* in_sizes, int n_in,
                              void* d_out, int out_size)
{
    const float* q_in  = (const float*)d_in[0];
    const float* k_in  = (const float*)d_in[1];
    const float* v_in  = (const float*)d_in[2];
    const int*   smask = (const int*)  d_in[3];
    const float* Wq    = (const float*)d_in[4];
    const float* bq    = (const float*)d_in[5];
    const float* Wv    = (const float*)d_in[6];
    const float* bv    = (const float*)d_in[7];
    const float* Wo    = (const float*)d_in[8];
    const float* bo    = (const float*)d_in[9];
    const float* gam   = (const float*)d_in[10];
    const float* ln_g  = (const float*)d_in[11];
    const float* ln_b  = (const float*)d_in[12];
    float* out = (float*)d_out;

    __nv_bfloat16 *Xqh, *Xql, *Xkh, *Xkl, *Xvh, *Xvl;
    __nv_bfloat16 *Qh, *Ql, *Kh, *Kl, *Vh, *Vl, *Oh, *Ol;
    __nv_bfloat16 *Wqh, *Wql, *Wvh, *Wvl, *Woh, *Wol;
    unsigned long long* mbits;
    cudaGetSymbolAddress((void**)&Xqh, g_Xqh); cudaGetSymbolAddress((void**)&Xql, g_Xql);
    cudaGetSymbolAddress((void**)&Xkh, g_Xkh); cudaGetSymbolAddress((void**)&Xkl, g_Xkl);
    cudaGetSymbolAddress((void**)&Xvh, g_Xvh); cudaGetSymbolAddress((void**)&Xvl, g_Xvl);
    cudaGetSymbolAddress((void**)&Qh, g_Qh);   cudaGetSymbolAddress((void**)&Ql, g_Ql);
    cudaGetSymbolAddress((void**)&Kh, g_Kh);   cudaGetSymbolAddress((void**)&Kl, g_Kl);
    cudaGetSymbolAddress((void**)&Vh, g_Vh);   cudaGetSymbolAddress((void**)&Vl, g_Vl);
    cudaGetSymbolAddress((void**)&Oh, g_Oh);   cudaGetSymbolAddress((void**)&Ol, g_Ol);
    cudaGetSymbolAddress((void**)&Wqh, g_Wqh); cudaGetSymbolAddress((void**)&Wql, g_Wql);
    cudaGetSymbolAddress((void**)&Wvh, g_Wvh); cudaGetSymbolAddress((void**)&Wvl, g_Wvl);
    cudaGetSymbolAddress((void**)&Woh, g_Woh); cudaGetSymbolAddress((void**)&Wol, g_Wol);
    cudaGetSymbolAddress((void**)&mbits, g_mbits);

    cudaFuncSetAttribute(mma_gemm_kernel, cudaFuncAttributeMaxDynamicSharedMemorySize,
                         (int)MMG_SMEM);
    cudaFuncSetAttribute(attn_mma_kernel, cudaFuncAttributeMaxDynamicSharedMemorySize,
                         (int)AT_SMEM);

    const dim3 gb(256);

    // fused prepasses: input splits + weight transpose/split + mask bit-pack
    prep_kernel<<<PREP_TOTAL_B, gb>>>(
        q_in, k_in, v_in, Xqh, Xql, Xkh, Xkl, Xvh, Xvl,
        Wq, Wv, Wo, Wqh, Wql, Wvh, Wvl, Woh, Wol,
        smask, mbits);

    // Q + K + V projections fused in one launch (grid.z = 3)
    const dim3 ggrid3(DD / 128, MM / 128, 3);
    mma_gemm_kernel<<<ggrid3, gb, MMG_SMEM>>>(
        Xqh, Xql, Xkh, Xkl, Xvh, Xvl,
        Wqh, Wql, Wvh, Wvl,
        bq, bv, nullptr, nullptr,
        Qh, Ql, Kh, Kl, Vh, Vl);

    // tensor-core attention: 1024 CTAs, heavy-first, 3 CTAs/SM
    attn_mma_kernel<<<1024, 128, AT_SMEM>>>(Qh, Ql, Kh, Kl, Vh, Vl,
                                            Xqh, Xql, Xkh, Xkl, mbits, gam, Oh, Ol);

    // output projection + bias + residual -> fp32 out
    const dim3 ggrid(DD / 128, MM / 128, 1);
    mma_gemm_kernel<<<ggrid, gb, MMG_SMEM>>>(
        Oh, Ol, Oh, Ol, Oh, Ol,
        Woh, Wol, Woh, Wol,
        bo, bo, q_in, out,
        nullptr, nullptr, nullptr, nullptr, nullptr, nullptr);

    // in-place LayerNorm
    ln_kernel<<<MM / 8, gb>>>(out, ln_g, ln_b);
}

// round 13
// speedup vs baseline: 1.0515x; 1.0287x over previous
#include <cuda_runtime.h>
#include <cuda_bf16.h>
#include <math.h>
#include <cstdint>

// Problem constants
#define BB 8
#define SS 1024
#define DD 512
#define HH 8
#define DKK 64
#define MM (BB*SS)   // 8192 rows
#define NELEM ((size_t)MM * DD)

// ---------------- scratch (static __device__: allocation-guard safe) --------
__device__ __nv_bfloat16 g_Xqh[NELEM], g_Xql[NELEM];
__device__ __nv_bfloat16 g_Xkh[NELEM], g_Xkl[NELEM];
__device__ __nv_bfloat16 g_Xvh[NELEM], g_Xvl[NELEM];
__device__ __nv_bfloat16 g_Qh[NELEM], g_Ql[NELEM];
__device__ __nv_bfloat16 g_Kh[NELEM], g_Kl[NELEM];
__device__ __nv_bfloat16 g_Vh[NELEM], g_Vl[NELEM];
__device__ __nv_bfloat16 g_Oh[NELEM], g_Ol[NELEM];
__device__ __nv_bfloat16 g_Wqh[DD * DD], g_Wql[DD * DD];
__device__ __nv_bfloat16 g_Wvh[DD * DD], g_Wvl[DD * DD];
__device__ __nv_bfloat16 g_Woh[DD * DD], g_Wol[DD * DD];
__device__ unsigned long long g_mbits[(size_t)MM * 16];

// ---------------- PTX helpers (base sm_103-safe) -----------------------------
__device__ __forceinline__ uint32_t smem_u32(const void* p) {
    uint32_t a;
    asm("{ .reg .u64 t; cvta.to.shared.u64 t, %1; cvt.u32.u64 %0, t; }" : "=r"(a) : "l"(p));
    return a;
}
#define CP_ASYNC16(dst, src) \
    asm volatile("cp.async.cg.shared.global [%0], [%1], 16;" :: "r"(dst), "l"(src) : "memory")
#define CP_COMMIT() asm volatile("cp.async.commit_group;" ::: "memory")
#define CP_WAIT1()  asm volatile("cp.async.wait_group 1;" ::: "memory")
#define CP_WAIT0()  asm volatile("cp.async.wait_group 0;" ::: "memory")

__device__ __forceinline__ void ldm_x4(uint32_t& r0, uint32_t& r1, uint32_t& r2,
                                       uint32_t& r3, uint32_t addr) {
    asm volatile("ldmatrix.sync.aligned.m8n8.x4.shared.b16 {%0,%1,%2,%3}, [%4];"
                 : "=r"(r0), "=r"(r1), "=r"(r2), "=r"(r3) : "r"(addr));
}
__device__ __forceinline__ void ldm_x4t(uint32_t& r0, uint32_t& r1, uint32_t& r2,
                                        uint32_t& r3, uint32_t addr) {
    asm volatile("ldmatrix.sync.aligned.m8n8.x4.trans.shared.b16 {%0,%1,%2,%3}, [%4];"
                 : "=r"(r0), "=r"(r1), "=r"(r2), "=r"(r3) : "r"(addr));
}
__device__ __forceinline__ void mma16816(float* d, const uint32_t* a, const uint32_t* b) {
    asm volatile("mma.sync.aligned.m16n8k16.row.col.f32.bf16.bf16.f32 "
                 "{%0,%1,%2,%3}, {%4,%5,%6,%7}, {%8,%9}, {%0,%1,%2,%3};"
                 : "+f"(d[0]), "+f"(d[1]), "+f"(d[2]), "+f"(d[3])
                 : "r"(a[0]), "r"(a[1]), "r"(a[2]), "r"(a[3]), "r"(b[0]), "r"(b[1]));
}
__device__ __forceinline__ uint32_t pack_bf2(float a, float b) {
    __nv_bfloat162 t = __floats2bfloat162_rn(a, b);
    return *(uint32_t*)&t;
}
__device__ __forceinline__ void split2(float a, float b, uint32_t& hi, uint32_t& lo) {
    const __nv_bfloat16 ha = __float2bfloat16(a), hb = __float2bfloat16(b);
    const float ra = a - __bfloat162float(ha), rb = b - __bfloat162float(hb);
    __nv_bfloat162 th; th.x = ha; th.y = hb;
    hi = *(uint32_t*)&th;
    lo = pack_bf2(ra, rb);
}

// ---------------------------------------------------------------------------
// Fused prepass kernel: split3 + wsplit3 + pack_mask.
// ---------------------------------------------------------------------------
#define PREP_SPLIT_B 12288
#define PREP_WSPL_B  768
#define PREP_MASK_B  16384
#define PREP_TOTAL_B (PREP_SPLIT_B + PREP_WSPL_B + PREP_MASK_B)

__global__ __launch_bounds__(256) void prep_kernel(
    const float* __restrict__ Xq, const float* __restrict__ Xk,
    const float* __restrict__ Xv,
    __nv_bfloat16* __restrict__ Xqh, __nv_bfloat16* __restrict__ Xql,
    __nv_bfloat16* __restrict__ Xkh, __nv_bfloat16* __restrict__ Xkl,
    __nv_bfloat16* __restrict__ Xvh, __nv_bfloat16* __restrict__ Xvl,
    const float* __restrict__ Wq, const float* __restrict__ Wv,
    const float* __restrict__ Wo,
    __nv_bfloat16* __restrict__ Wqh, __nv_bfloat16* __restrict__ Wql,
    __nv_bfloat16* __restrict__ Wvh, __nv_bfloat16* __restrict__ Wvl,
    __nv_bfloat16* __restrict__ Woh, __nv_bfloat16* __restrict__ Wol,
    const int* __restrict__ smask, unsigned long long* __restrict__ bits)
{
    __shared__ float tile[32][33];
    const int bid = blockIdx.x;
    const int tid = threadIdx.x;

    if (bid < PREP_SPLIT_B) {
        const int s = bid / 4096;
        const int blk = bid - s * 4096;
        const float* X = (s == 0) ? Xq : (s == 1) ? Xk : Xv;
        __nv_bfloat16* H = (s == 0) ? Xqh : (s == 1) ? Xkh : Xvh;
        __nv_bfloat16* L = (s == 0) ? Xql : (s == 1) ? Xkl : Xvl;
        const size_t i = ((size_t)blk * 256 + tid) * 4;
        float4 v = *(const float4*)(X + i);
        __nv_bfloat16 h[4], l[4];
        float x[4] = {v.x, v.y, v.z, v.w};
#pragma unroll
        for (int j = 0; j < 4; j++) {
            h[j] = __float2bfloat16(x[j]);
            l[j] = __float2bfloat16(x[j] - __bfloat162float(h[j]));
        }
        *(uint2*)(H + i) = *(uint2*)h;
        *(uint2*)(L + i) = *(uint2*)l;
    } else if (bid < PREP_SPLIT_B + PREP_WSPL_B) {
        const int w = bid - PREP_SPLIT_B;
        const int s = w / 256;
        const int rem = w - s * 256;
        const int bx = rem & 15, by = rem >> 4;
        const float* W = (s == 0) ? Wq : (s == 1) ? Wv : Wo;
        __nv_bfloat16* Ht = (s == 0) ? Wqh : (s == 1) ? Wvh : Woh;
        __nv_bfloat16* Lt = (s == 0) ? Wql : (s == 1) ? Wvl : Wol;
        const int tx = tid & 31, ty = tid >> 5;
        const int k0 = by * 32, n0 = bx * 32;
#pragma unroll
        for (int r = 0; r < 4; r++)
            tile[ty * 4 + r][tx] = W[(size_t)(k0 + ty * 4 + r) * DD + n0 + tx];
        __syncthreads();
#pragma unroll
        for (int r = 0; r < 4; r++) {
            const int n = n0 + ty * 4 + r;
            const float x = tile[tx][ty * 4 + r];
            const __nv_bfloat16 h = __float2bfloat16(x);
            Ht[(size_t)n * DD + k0 + tx] = h;
            Lt[(size_t)n * DD + k0 + tx] = __float2bfloat16(x - __bfloat162float(h));
        }
    } else {
        const int pb = bid - PREP_SPLIT_B - PREP_WSPL_B;
        const int gw = pb * 8 + (tid >> 5);
        const int lane = tid & 31;
        const int word = gw & 15;
        const int row  = gw >> 4;
        const int* p = smask + (size_t)row * SS + word * 64;
        const unsigned lo = __ballot_sync(0xffffffffu, p[lane] != 0);
        const unsigned hi = __ballot_sync(0xffffffffu, p[lane + 32] != 0);
        if (lane == 0)
            bits[(size_t)row * 16 + word] = ((unsigned long long)hi << 32) | lo;
    }
}

// ---------------------------------------------------------------------------
// mma.sync bf16x3 GEMM (256 threads, CTA 128x128, warp tile 32x64), K-chunk 32,
// cp.async double buffer. grid.z selects operand set (fused QKV projections).
// ---------------------------------------------------------------------------
#define LDSP 40
#define OPB  (128 * LDSP * 2)
#define STAGE_B (4 * OPB)
#define MMG_SMEM (2 * STAGE_B)

extern __shared__ char mm_sm[];

__global__ __launch_bounds__(256) void mma_gemm_kernel(
    const __nv_bfloat16* __restrict__ Ah0, const __nv_bfloat16* __restrict__ Al0,
    const __nv_bfloat16* __restrict__ Ah1, const __nv_bfloat16* __restrict__ Al1,
    const __nv_bfloat16* __restrict__ Ah2, const __nv_bfloat16* __restrict__ Al2,
    const __nv_bfloat16* __restrict__ Bh0, const __nv_bfloat16* __restrict__ Bl0,
    const __nv_bfloat16* __restrict__ Bh1, const __nv_bfloat16* __restrict__ Bl1,
    const float* __restrict__ bias0, const float* __restrict__ bias1,
    __nv_bfloat16* __restrict__ Ch0, __nv_bfloat16* __restrict__ Cl0,
    __nv_bfloat16* __restrict__ Ch1, __nv_bfloat16* __restrict__ Cl1,
    __nv_bfloat16* __restrict__ Ch2, __nv_bfloat16* __restrict__ Cl2)
{
    const uint32_t smb = smem_u32(mm_sm);
    const int tid  = threadIdx.x;
    const int wid  = tid >> 5;
    const int lane = tid & 31;
    const int wm   = wid & 3;
    const int wn   = wid >> 2;
    const int m0 = blockIdx.y * 128, n0 = blockIdx.x * 128;
    const int z = blockIdx.z;
    const __nv_bfloat16* Ah = (z == 0) ? Ah0 : (z == 1) ? Ah1 : Ah2;
    const __nv_bfloat16* Al = (z == 0) ? Al0 : (z == 1) ? Al1 : Al2;
    const __nv_bfloat16* Bh = (z == 2) ? Bh1 : Bh0;
    const __nv_bfloat16* Bl = (z == 2) ? Bl1 : Bl0;
    const float* bias = (z == 2) ? bias1 : bias0;
    __nv_bfloat16* Ch = (z == 0) ? Ch0 : (z == 1) ? Ch1 : Ch2;
    __nv_bfloat16* Cl = (z == 0) ? Cl0 : (z == 1) ? Cl1 : Cl2;

    const char* srcs[4] = {
        (const char*)(Ah + (size_t)m0 * DD),
        (const char*)(Al + (size_t)m0 * DD),
        (const char*)(Bh + (size_t)n0 * DD),
        (const char*)(Bl + (size_t)n0 * DD)
    };

    int l_op[8], l_row[8], l_seg[8];
#pragma unroll
    for (int i = 0; i < 8; i++) {
        const int idx = tid + i * 256;
        l_op[i]  = idx >> 9;
        l_row[i] = (idx & 511) >> 2;
        l_seg[i] = idx & 3;
    }

    float acc[2][8][4];
#pragma unroll
    for (int mt = 0; mt < 2; mt++)
#pragma unroll
        for (int nt = 0; nt < 8; nt++)
#pragma unroll
            for (int r = 0; r < 4; r++) acc[mt][nt][r] = 0.f;

    const int lrow = lane & 15;
    const int lkof = (lane >> 4) * 8;

#pragma unroll
    for (int i = 0; i < 8; i++) {
        CP_ASYNC16(smb + l_op[i] * OPB + l_row[i] * 80 + l_seg[i] * 16,
                   srcs[l_op[i]] + (size_t)l_row[i] * 1024 + l_seg[i] * 16);
    }
    CP_COMMIT();

    for (int c = 0; c < 16; c++) {
        if (c + 1 < 16) {
            const uint32_t sb = smb + ((c + 1) & 1) * STAGE_B;
            const int koff = (c + 1) * 64;
#pragma unroll
            for (int i = 0; i < 8; i++) {
                CP_ASYNC16(sb + l_op[i] * OPB + l_row[i] * 80 + l_seg[i] * 16,
                           srcs[l_op[i]] + (size_t)l_row[i] * 1024 + koff + l_seg[i] * 16);
            }
            CP_COMMIT();
            CP_WAIT1();
        } else {
            CP_WAIT0();
        }
        __syncthreads();

        const uint32_t sb = smb + (c & 1) * STAGE_B;
#pragma unroll
        for (int ks = 0; ks < 32; ks += 16) {
            uint32_t ah[2][4], al[2][4];
#pragma unroll
            for (int mt = 0; mt < 2; mt++) {
                const int r = wm * 32 + mt * 16 + lrow;
                const uint32_t ad = sb + r * 80 + (ks + lkof) * 2;
                ldm_x4(ah[mt][0], ah[mt][1], ah[mt][2], ah[mt][3], ad);
                ldm_x4(al[mt][0], al[mt][1], al[mt][2], al[mt][3], ad + OPB);
            }
            uint32_t bh[8][2], bl[8][2];
#pragma unroll
            for (int np = 0; np < 4; np++) {
                const int r = wn * 64 + np * 16 + lrow;
                const uint32_t bd = sb + 2 * OPB + r * 80 + (ks + lkof) * 2;
                uint32_t t0, t1, t2, t3;
                ldm_x4(t0, t1, t2, t3, bd);
                bh[np * 2][0] = t0; bh[np * 2][1] = t2;
                bh[np * 2 + 1][0] = t1; bh[np * 2 + 1][1] = t3;
                ldm_x4(t0, t1, t2, t3, bd + OPB);
                bl[np * 2][0] = t0; bl[np * 2][1] = t2;
                bl[np * 2 + 1][0] = t1; bl[np * 2 + 1][1] = t3;
            }
#pragma unroll
            for (int mt = 0; mt < 2; mt++)
#pragma unroll
                for (int nt = 0; nt < 8; nt++)
                    mma16816(acc[mt][nt], ah[mt], bh[nt]);
#pragma unroll
            for (int mt = 0; mt < 2; mt++)
#pragma unroll
                for (int nt = 0; nt < 8; nt++)
                    mma16816(acc[mt][nt], ah[mt], bl[nt]);
#pragma unroll
            for (int mt = 0; mt < 2; mt++)
#pragma unroll
                for (int nt = 0; nt < 8; nt++)
                    mma16816(acc[mt][nt], al[mt], bh[nt]);
        }
        __syncthreads();
    }

    const int qr = lane >> 2;
    const int qc = (lane & 3) * 2;
#pragma unroll
    for (int mt = 0; mt < 2; mt++) {
#pragma unroll
        for (int nt = 0; nt < 8; nt++) {
            const int col = n0 + wn * 64 + nt * 8 + qc;
            const float2 bv = *(const float2*)(bias + col);
#pragma unroll
            for (int half = 0; half < 2; half++) {
                const int row = m0 + wm * 32 + mt * 16 + qr + half * 8;
                float ox = acc[mt][nt][half * 2 + 0] + bv.x;
                float oy = acc[mt][nt][half * 2 + 1] + bv.y;
                uint32_t hi, lo;
                split2(ox, oy, hi, lo);
                *(uint32_t*)(Ch + (size_t)row * DD + col) = hi;
                *(uint32_t*)(Cl + (size_t)row * DD + col) = lo;
            }
        }
    }
}

// ---------------------------------------------------------------------------
// Output projection: CTA 64x128, 128 threads (4 warps, warp tile 32x64),
// K-chunk 32, double buffer. smem 61440B -> 3 CTAs/SM, 512 CTAs (balanced).
// fp32 output + bias + residual. Per-element accumulation order identical to
// mma_gemm_kernel (same K chunking, same hh/hl/lh pass order).
// ---------------------------------------------------------------------------
#define OPA64 (64 * LDSP * 2)            // 5120
#define STAGE64 (2 * OPA64 + 2 * OPB)    // 30720
#define MMG64_SMEM (2 * STAGE64)         // 61440

__global__ __launch_bounds__(128, 3) void mma_gemm64_kernel(
    const __nv_bfloat16* __restrict__ Ah, const __nv_bfloat16* __restrict__ Al,
    const __nv_bfloat16* __restrict__ Bh, const __nv_bfloat16* __restrict__ Bl,
    const float* __restrict__ bias, const float* __restrict__ resid,
    float* __restrict__ C)
{
    const uint32_t smb = smem_u32(mm_sm);
    const int tid  = threadIdx.x;
    const int wid  = tid >> 5;
    const int lane = tid & 31;
    const int wm   = wid & 1;           // 2 warp rows of 32
    const int wn   = wid >> 1;          // 2 warp cols of 64
    const int m0 = blockIdx.y * 64, n0 = blockIdx.x * 128;

    const char* srcA[2] = {(const char*)(Ah + (size_t)m0 * DD),
                           (const char*)(Al + (size_t)m0 * DD)};
    const char* srcB[2] = {(const char*)(Bh + (size_t)n0 * DD),
                           (const char*)(Bl + (size_t)n0 * DD)};

    // 1536 16B transfers per stage, 12 per thread.
    // idx < 512: A (2 ops x 64 rows x 4 segs); else B (2 ops x 128 x 4).
    int l_isA[12], l_op[12], l_row[12], l_seg[12];
#pragma unroll
    for (int i = 0; i < 12; i++) {
        const int idx = tid + i * 128;
        if (idx < 512) {
            l_isA[i] = 1;
            l_op[i]  = idx >> 8;
            l_row[i] = (idx >> 2) & 63;
            l_seg[i] = idx & 3;
        } else {
            const int j = idx - 512;
            l_isA[i] = 0;
            l_op[i]  = j >> 9;
            l_row[i] = (j >> 2) & 127;
            l_seg[i] = j & 3;
        }
    }

    float acc[2][8][4];
#pragma unroll
    for (int mt = 0; mt < 2; mt++)
#pragma unroll
        for (int nt = 0; nt < 8; nt++)
#pragma unroll
            for (int r = 0; r < 4; r++) acc[mt][nt][r] = 0.f;

    const int lrow = lane & 15;
    const int lkof = (lane >> 4) * 8;

#pragma unroll
    for (int i = 0; i < 12; i++) {
        const uint32_t dst = smb +
            (l_isA[i] ? (l_op[i] * OPA64) : (2 * OPA64 + l_op[i] * OPB)) +
            l_row[i] * 80 + l_seg[i] * 16;
        const char* src = (l_isA[i] ? srcA[l_op[i]] : srcB[l_op[i]]) +
                          (size_t)l_row[i] * 1024 + l_seg[i] * 16;
        CP_ASYNC16(dst, src);
    }
    CP_COMMIT();

    for (int c = 0; c < 16; c++) {
        if (c + 1 < 16) {
            const uint32_t sb = smb + ((c + 1) & 1) * STAGE64;
            const int koff = (c + 1) * 64;
#pragma unroll
            for (int i = 0; i < 12; i++) {
                const uint32_t dst = sb +
                    (l_isA[i] ? (l_op[i] * OPA64) : (2 * OPA64 + l_op[i] * OPB)) +
                    l_row[i] * 80 + l_seg[i] * 16;
                const char* src = (l_isA[i] ? srcA[l_op[i]] : srcB[l_op[i]]) +
                                  (size_t)l_row[i] * 1024 + koff + l_seg[i] * 16;
                CP_ASYNC16(dst, src);
            }
            CP_COMMIT();
            CP_WAIT1();
        } else {
            CP_WAIT0();
        }
        __syncthreads();

        const uint32_t sb = smb + (c & 1) * STAGE64;
#pragma unroll
        for (int ks = 0; ks < 32; ks += 16) {
            uint32_t ah[2][4], al[2][4];
#pragma unroll
            for (int mt = 0; mt < 2; mt++) {
                const int r = wm * 32 + mt * 16 + lrow;
                const uint32_t ad = sb + r * 80 + (ks + lkof) * 2;
                ldm_x4(ah[mt][0], ah[mt][1], ah[mt][2], ah[mt][3], ad);
                ldm_x4(al[mt][0], al[mt][1], al[mt][2], al[mt][3], ad + OPA64);
            }
            uint32_t bh[8][2], bl[8][2];
#pragma unroll
            for (int np = 0; np < 4; np++) {
                const int r = wn * 64 + np * 16 + lrow;
                const uint32_t bd = sb + 2 * OPA64 + r * 80 + (ks + lkof) * 2;
                uint32_t t0, t1, t2, t3;
                ldm_x4(t0, t1, t2, t3, bd);
                bh[np * 2][0] = t0; bh[np * 2][1] = t2;
                bh[np * 2 + 1][0] = t1; bh[np * 2 + 1][1] = t3;
                ldm_x4(t0, t1, t2, t3, bd + OPB);
                bl[np * 2][0] = t0; bl[np * 2][1] = t2;
                bl[np * 2 + 1][0] = t1; bl[np * 2 + 1][1] = t3;
            }
#pragma unroll
            for (int mt = 0; mt < 2; mt++)
#pragma unroll
                for (int nt = 0; nt < 8; nt++)
                    mma16816(acc[mt][nt], ah[mt], bh[nt]);
#pragma unroll
            for (int mt = 0; mt < 2; mt++)
#pragma unroll
                for (int nt = 0; nt < 8; nt++)
                    mma16816(acc[mt][nt], ah[mt], bl[nt]);
#pragma unroll
            for (int mt = 0; mt < 2; mt++)
#pragma unroll
                for (int nt = 0; nt < 8; nt++)
                    mma16816(acc[mt][nt], al[mt], bh[nt]);
        }
        __syncthreads();
    }

    const int qr = lane >> 2;
    const int qc = (lane & 3) * 2;
#pragma unroll
    for (int mt = 0; mt < 2; mt++) {
#pragma unroll
        for (int nt = 0; nt < 8; nt++) {
            const int col = n0 + wn * 64 + nt * 8 + qc;
            const float2 bv = *(const float2*)(bias + col);
#pragma unroll
            for (int half = 0; half < 2; half++) {
                const int row = m0 + wm * 32 + mt * 16 + qr + half * 8;
                const float2 rv = *(const float2*)(resid + (size_t)row * DD + col);
                float2 o;
                o.x = acc[mt][nt][half * 2 + 0] + bv.x + rv.x;
                o.y = acc[mt][nt][half * 2 + 1] + bv.y + rv.y;
                *(float2*)(C + (size_t)row * DD + col) = o;
            }
        }
    }
}

// ---------------------------------------------------------------------------
// Tensor-core dual-score causal flash attention (R10 config: K-tile 32,
// 3 CTAs/SM, heavy-first, no per-warp guard).
// ---------------------------------------------------------------------------
#define ATS   144
#define QOP   9216
#define KOP   4608
#define STG   (6 * KOP)
#define AT_SMEM (2 * QOP + 2 * STG)

extern __shared__ char at_sm[];

__device__ __forceinline__ void at_load_tile32(
    uint32_t smb, int buf, int tid, int b, int kt0, int hc,
    const __nv_bfloat16* Kh, const __nv_bfloat16* Kl,
    const __nv_bfloat16* Rkh, const __nv_bfloat16* Rkl,
    const __nv_bfloat16* Vh, const __nv_bfloat16* Vl)
{
    const char* srcs[6] = {(const char*)Kh, (const char*)Kl, (const char*)Rkh,
                           (const char*)Rkl, (const char*)Vh, (const char*)Vl};
    const uint32_t base = smb + 2 * QOP + buf * STG;
#pragma unroll
    for (int i = 0; i < 12; i++) {
        const int idx = tid + i * 128;
        const int op = idx >> 8, r = (idx >> 3) & 31, seg = idx & 7;
        CP_ASYNC16(base + op * KOP + r * ATS + seg * 16,
                   srcs[op] + ((size_t)(b * SS + kt0 + r) * DD + hc) * 2 + seg * 16);
    }
}

__global__ __launch_bounds__(128, 3) void attn_mma_kernel(
    const __nv_bfloat16* __restrict__ Qh, const __nv_bfloat16* __restrict__ Ql,
    const __nv_bfloat16* __restrict__ Kh, const __nv_bfloat16* __restrict__ Kl,
    const __nv_bfloat16* __restrict__ Vh, const __nv_bfloat16* __restrict__ Vl,
    const __nv_bfloat16* __restrict__ Rqh, const __nv_bfloat16* __restrict__ Rql,
    const __nv_bfloat16* __restrict__ Rkh, const __nv_bfloat16* __restrict__ Rkl,
    const unsigned long long* __restrict__ mbits, const float* __restrict__ gammas,
    __nv_bfloat16* __restrict__ Oh, __nv_bfloat16* __restrict__ Ol)
{
    const uint32_t smb = smem_u32(at_sm);
    const int tid = threadIdx.x, lane = tid & 31, w = tid >> 5;
    const int bh = blockIdx.x & 63;
    const int q0 = (15 - (blockIdx.x >> 6)) * 64;
    const int b  = bh >> 3, h = bh & 7;
    const int hc = h * DKK;

    float g  = gammas[h];
    float sp = (g > 20.f) ? g : log1pf(__expf(g));
    float te = __expf(-sp);
    te = fminf(fmaxf(te, 1e-5f), 1e5f);
    const float f1 = 0.125f;
    const float f2 = te * rsqrtf((float)DD);
    const float f2f1 = f2 * 8.0f;

    const int qcb = (lane & 3) * 2;
    const int gg = lane >> 3, l8 = lane & 7;
    const int mrw = w * 16 + ((gg & 1) << 3) + l8;
    const int r1 = q0 + w * 16 + (lane >> 2);
    const int r2 = r1 + 8;

    {
        const char* qsrc[4] = {(const char*)Qh, (const char*)Ql,
                               (const char*)Rqh, (const char*)Rql};
#pragma unroll
        for (int i = 0; i < 16; i++) {
            const int idx = tid + i * 128;
            const int op = idx >> 9, r = (idx >> 3) & 63, seg = idx & 7;
            const uint32_t base = (op < 2) ? (smb + 2 * QOP + op * QOP)
                                           : (smb + (op - 2) * QOP);
            CP_ASYNC16(base + r * ATS + seg * 16,
                       qsrc[op] + ((size_t)(b * SS + q0 + r) * DD + hc) * 2 + seg * 16);
        }
        CP_COMMIT(); CP_WAIT0();
        __syncthreads();
    }
    uint32_t qph[4][4], qpl[4][4];
#pragma unroll
    for (int ks = 0; ks < 4; ks++) {
        const uint32_t qa = smb + 2 * QOP + mrw * ATS +
                            (ks * 16 + ((gg >> 1) << 3)) * 2;
        ldm_x4(qph[ks][0], qph[ks][1], qph[ks][2], qph[ks][3], qa);
        ldm_x4(qpl[ks][0], qpl[ks][1], qpl[ks][2], qpl[ks][3], qa + QOP);
    }
    __syncthreads();

    float oacc[8][4];
#pragma unroll
    for (int nt = 0; nt < 8; nt++)
#pragma unroll
        for (int e = 0; e < 4; e++) oacc[nt][e] = 0.f;
    float mrow[2] = {-1e30f, -1e30f};
    float lsum[2] = {0.f, 0.f};

    const int T = q0 / 32 + 2;

    at_load_tile32(smb, 0, tid, b, 0, hc, Kh, Kl, Rkh, Rkl, Vh, Vl);
    CP_COMMIT();

    for (int t = 0; t < T; t++) {
        const int kt0 = t * 32;
        if (t + 1 < T) {
            at_load_tile32(smb, (t + 1) & 1, tid, b, kt0 + 32, hc, Kh, Kl, Rkh, Rkl, Vh, Vl);
            CP_COMMIT(); CP_WAIT1();
        } else {
            CP_WAIT0();
        }
        __syncthreads();

        const uint32_t sb = smb + 2 * QOP + (t & 1) * STG;

        float sc[4][4];
#pragma unroll
        for (int nt = 0; nt < 4; nt++)
#pragma unroll
            for (int e = 0; e < 4; e++) sc[nt][e] = 0.f;

        // ---- s2: raw scores ----
#pragma unroll
        for (int ks = 0; ks < 4; ks++) {
            uint32_t qh4[4], ql4[4];
            const uint32_t qa = smb + mrw * ATS + (ks * 16 + ((gg >> 1) << 3)) * 2;
            ldm_x4(qh4[0], qh4[1], qh4[2], qh4[3], qa);
            ldm_x4(ql4[0], ql4[1], ql4[2], ql4[3], qa + QOP);
            uint32_t bh2[4][2], bl2[4][2];
#pragma unroll
            for (int np = 0; np < 2; np++) {
                const uint32_t ad = sb + 2 * KOP +
                    (np * 16 + ((gg >> 1) << 3) + l8) * ATS +
                    (ks * 16 + ((gg & 1) << 3)) * 2;
                uint32_t t0, t1, t2, t3;
                ldm_x4(t0, t1, t2, t3, ad);
                bh2[np*2][0] = t0; bh2[np*2][1] = t1;
                bh2[np*2+1][0] = t2; bh2[np*2+1][1] = t3;
                ldm_x4(t0, t1, t2, t3, ad + KOP);
                bl2[np*2][0] = t0; bl2[np*2][1] = t1;
                bl2[np*2+1][0] = t2; bl2[np*2+1][1] = t3;
            }
#pragma unroll
            for (int nt = 0; nt < 4; nt++)
                mma16816(sc[nt], qh4, bh2[nt]);
#pragma unroll
            for (int nt = 0; nt < 4; nt++)
                mma16816(sc[nt], qh4, bl2[nt]);
#pragma unroll
            for (int nt = 0; nt < 4; nt++)
                mma16816(sc[nt], ql4, bh2[nt]);
        }

        // ---- gate s2 by packed mask ----
        const unsigned long long mw1 =
            mbits[(size_t)(b * SS + r1) * 16 + (kt0 >> 6)];
        const unsigned long long mw2 =
            mbits[(size_t)(b * SS + r2) * 16 + (kt0 >> 6)];
        const int msh = kt0 & 32;
#pragma unroll
        for (int nt = 0; nt < 4; nt++) {
            const int j0 = msh + nt * 8 + qcb;
            sc[nt][0] = ((mw1 >> j0) & 1)       ? sc[nt][0] * f2f1 : 0.f;
            sc[nt][1] = ((mw1 >> (j0 + 1)) & 1) ? sc[nt][1] * f2f1 : 0.f;
            sc[nt][2] = ((mw2 >> j0) & 1)       ? sc[nt][2] * f2f1 : 0.f;
            sc[nt][3] = ((mw2 >> (j0 + 1)) & 1) ? sc[nt][3] * f2f1 : 0.f;
        }

        // ---- s1: projected scores ----
#pragma unroll
        for (int ks = 0; ks < 4; ks++) {
            uint32_t bh2[4][2], bl2[4][2];
#pragma unroll
            for (int np = 0; np < 2; np++) {
                const uint32_t ad = sb +
                    (np * 16 + ((gg >> 1) << 3) + l8) * ATS +
                    (ks * 16 + ((gg & 1) << 3)) * 2;
                uint32_t t0, t1, t2, t3;
                ldm_x4(t0, t1, t2, t3, ad);
                bh2[np*2][0] = t0; bh2[np*2][1] = t1;
                bh2[np*2+1][0] = t2; bh2[np*2+1][1] = t3;
                ldm_x4(t0, t1, t2, t3, ad + KOP);
                bl2[np*2][0] = t0; bl2[np*2][1] = t1;
                bl2[np*2+1][0] = t2; bl2[np*2+1][1] = t3;
            }
#pragma unroll
            for (int nt = 0; nt < 4; nt++)
                mma16816(sc[nt], qph[ks], bh2[nt]);
#pragma unroll
            for (int nt = 0; nt < 4; nt++)
                mma16816(sc[nt], qph[ks], bl2[nt]);
#pragma unroll
            for (int nt = 0; nt < 4; nt++)
                mma16816(sc[nt], qpl[ks], bh2[nt]);
        }

        // ---- causal mask + final scale ----
#pragma unroll
        for (int nt = 0; nt < 4; nt++) {
            const int gj0 = kt0 + nt * 8 + qcb;
            sc[nt][0] = (gj0     < r1) ? sc[nt][0] * f1 : -INFINITY;
            sc[nt][1] = (gj0 + 1 < r1) ? sc[nt][1] * f1 : -INFINITY;
            sc[nt][2] = (gj0     < r2) ? sc[nt][2] * f1 : -INFINITY;
            sc[nt][3] = (gj0 + 1 < r2) ? sc[nt][3] * f1 : -INFINITY;
        }

        // ---- online softmax ----
        float rm1 = -INFINITY, rm2 = -INFINITY;
#pragma unroll
        for (int nt = 0; nt < 4; nt++) {
            rm1 = fmaxf(rm1, fmaxf(sc[nt][0], sc[nt][1]));
            rm2 = fmaxf(rm2, fmaxf(sc[nt][2], sc[nt][3]));
        }
        rm1 = fmaxf(rm1, __shfl_xor_sync(0xffffffffu, rm1, 1));
        rm1 = fmaxf(rm1, __shfl_xor_sync(0xffffffffu, rm1, 2));
        rm2 = fmaxf(rm2, __shfl_xor_sync(0xffffffffu, rm2, 1));
        rm2 = fmaxf(rm2, __shfl_xor_sync(0xffffffffu, rm2, 2));
        const float mn1 = fmaxf(mrow[0], rm1);
        const float mn2 = fmaxf(mrow[1], rm2);
        const float scl1 = __expf(mrow[0] - mn1);
        const float scl2 = __expf(mrow[1] - mn2);
        mrow[0] = mn1; mrow[1] = mn2;

        float ps1 = 0.f, ps2 = 0.f;
#pragma unroll
        for (int nt = 0; nt < 4; nt++) {
            sc[nt][0] = __expf(sc[nt][0] - mn1);
            sc[nt][1] = __expf(sc[nt][1] - mn1);
            sc[nt][2] = __expf(sc[nt][2] - mn2);
            sc[nt][3] = __expf(sc[nt][3] - mn2);
            ps1 += sc[nt][0] + sc[nt][1];
            ps2 += sc[nt][2] + sc[nt][3];
        }
        ps1 += __shfl_xor_sync(0xffffffffu, ps1, 1);
        ps1 += __shfl_xor_sync(0xffffffffu, ps1, 2);
        ps2 += __shfl_xor_sync(0xffffffffu, ps2, 1);
        ps2 += __shfl_xor_sync(0xffffffffu, ps2, 2);
        lsum[0] = lsum[0] * scl1 + ps1;
        lsum[1] = lsum[1] * scl2 + ps2;

#pragma unroll
        for (int nt = 0; nt < 8; nt++) {
            oacc[nt][0] *= scl1; oacc[nt][1] *= scl1;
            oacc[nt][2] *= scl2; oacc[nt][3] *= scl2;
        }

        uint32_t pha[2][4], pla[2][4];
#pragma unroll
        for (int j = 0; j < 2; j++) {
            split2(sc[2*j][0],   sc[2*j][1],   pha[j][0], pla[j][0]);
            split2(sc[2*j][2],   sc[2*j][3],   pha[j][1], pla[j][1]);
            split2(sc[2*j+1][0], sc[2*j+1][1], pha[j][2], pla[j][2]);
            split2(sc[2*j+1][2], sc[2*j+1][3], pha[j][3], pla[j][3]);
        }

        // ---- PV (bf16x3) ----
#pragma unroll
        for (int j = 0; j < 2; j++) {
            uint32_t vh2[8][2], vl2[8][2];
#pragma unroll
            for (int np = 0; np < 4; np++) {
                const uint32_t ad = sb + 4 * KOP +
                    (j * 16 + ((gg & 1) << 3) + l8) * ATS +
                    (np * 16 + ((gg >> 1) << 3)) * 2;
                uint32_t t0, t1, t2, t3;
                ldm_x4t(t0, t1, t2, t3, ad);
                vh2[np*2][0] = t0; vh2[np*2][1] = t1;
                vh2[np*2+1][0] = t2; vh2[np*2+1][1] = t3;
                ldm_x4t(t0, t1, t2, t3, ad + KOP);
                vl2[np*2][0] = t0; vl2[np*2][1] = t1;
                vl2[np*2+1][0] = t2; vl2[np*2+1][1] = t3;
            }
#pragma unroll
            for (int nt = 0; nt < 8; nt++)
                mma16816(oacc[nt], pha[j], vh2[nt]);
#pragma unroll
            for (int nt = 0; nt < 8; nt++)
                mma16816(oacc[nt], pha[j], vl2[nt]);
#pragma unroll
            for (int nt = 0; nt < 8; nt++)
                mma16816(oacc[nt], pla[j], vh2[nt]);
        }
        __syncthreads();
    }

    const float rr1 = (lsum[0] > 0.f) ? (1.f / lsum[0]) : 0.f;
    const float rr2 = (lsum[1] > 0.f) ? (1.f / lsum[1]) : 0.f;
    const size_t base1 = (size_t)(b * SS + r1) * DD + hc;
    const size_t base2 = (size_t)(b * SS + r2) * DD + hc;
#pragma unroll
    for (int nt = 0; nt < 8; nt++) {
        const int co = nt * 8 + qcb;
        uint32_t hi, lo;
        split2(oacc[nt][0] * rr1, oacc[nt][1] * rr1, hi, lo);
        *(uint32_t*)(Oh + base1 + co) = hi;
        *(uint32_t*)(Ol + base1 + co) = lo;
        split2(oacc[nt][2] * rr2, oacc[nt][3] * rr2, hi, lo);
        *(uint32_t*)(Oh + base2 + co) = hi;
        *(uint32_t*)(Ol + base2 + co) = lo;
    }
}

// ---------------------------------------------------------------------------
// In-place LayerNorm: one warp per row of 512 floats.
// ---------------------------------------------------------------------------
__global__ __launch_bounds__(256) void ln_kernel(
    float* __restrict__ X, const float* __restrict__ gam, const float* __restrict__ bet)
{
    const int warp = threadIdx.x >> 5, lane = threadIdx.x & 31;
    const size_t row = (size_t)blockIdx.x * 8 + warp;
    float* xr = X + row * DD;

    float4 v[4];
    float s = 0.f, s2 = 0.f;
#pragma unroll
    for (int w = 0; w < 4; w++) {
        v[w] = *(const float4*)(xr + w * 128 + lane * 4);
        s  += v[w].x + v[w].y + v[w].z + v[w].w;
        s2 += v[w].x * v[w].x + v[w].y * v[w].y + v[w].z * v[w].z + v[w].w * v[w].w;
    }
#pragma unroll
    for (int o = 16; o > 0; o >>= 1) {
        s  += __shfl_xor_sync(0xffffffffu, s,  o);
        s2 += __shfl_xor_sync(0xffffffffu, s2, o);
    }
    const float mu  = s * (1.f / DD);
    const float var = s2 * (1.f / DD) - mu * mu;
    const float inv = rsqrtf(var + 1e-5f);
#pragma unroll
    for (int w = 0; w < 4; w++) {
        const int c = w * 128 + lane * 4;
        float4 gv = *(const float4*)(gam + c);
        float4 bv = *(const float4*)(bet + c);
        float4 o;
        o.x = (v[w].x - mu) * inv * gv.x + bv.x;
        o.y = (v[w].y - mu) * inv * gv.y + bv.y;
        o.z = (v[w].z - mu) * inv * gv.z + bv.z;
        o.w = (v[w].w - mu) * inv * gv.w + bv.w;
        *(float4*)(xr + c) = o;
    }
}

// ---------------------------------------------------------------------------
extern "C" void kernel_launch(void* const* d_in, const int* in_sizes, int n_in,
                              void* d_out, int out_size)
{
    const float* q_in  = (const float*)d_in[0];
    const float* k_in  = (const float*)d_in[1];
    const float* v_in  = (const float*)d_in[2];
    const int*   smask = (const int*)  d_in[3];
    const float* Wq    = (const float*)d_in[4];
    const float* bq    = (const float*)d_in[5];
    const float* Wv    = (const float*)d_in[6];
    const float* bv    = (const float*)d_in[7];
    const float* Wo    = (const float*)d_in[8];
    const float* bo    = (const float*)d_in[9];
    const float* gam   = (const float*)d_in[10];
    const float* ln_g  = (const float*)d_in[11];
    const float* ln_b  = (const float*)d_in[12];
    float* out = (float*)d_out;

    __nv_bfloat16 *Xqh, *Xql, *Xkh, *Xkl, *Xvh, *Xvl;
    __nv_bfloat16 *Qh, *Ql, *Kh, *Kl, *Vh, *Vl, *Oh, *Ol;
    __nv_bfloat16 *Wqh, *Wql, *Wvh, *Wvl, *Woh, *Wol;
    unsigned long long* mbits;
    cudaGetSymbolAddress((void**)&Xqh, g_Xqh); cudaGetSymbolAddress((void**)&Xql, g_Xql);
    cudaGetSymbolAddress((void**)&Xkh, g_Xkh); cudaGetSymbolAddress((void**)&Xkl, g_Xkl);
    cudaGetSymbolAddress((void**)&Xvh, g_Xvh); cudaGetSymbolAddress((void**)&Xvl, g_Xvl);
    cudaGetSymbolAddress((void**)&Qh, g_Qh);   cudaGetSymbolAddress((void**)&Ql, g_Ql);
    cudaGetSymbolAddress((void**)&Kh, g_Kh);   cudaGetSymbolAddress((void**)&Kl, g_Kl);
    cudaGetSymbolAddress((void**)&Vh, g_Vh);   cudaGetSymbolAddress((void**)&Vl, g_Vl);
    cudaGetSymbolAddress((void**)&Oh, g_Oh);   cudaGetSymbolAddress((void**)&Ol, g_Ol);
    cudaGetSymbolAddress((void**)&Wqh, g_Wqh); cudaGetSymbolAddress((void**)&Wql, g_Wql);
    cudaGetSymbolAddress((void**)&Wvh, g_Wvh); cudaGetSymbolAddress((void**)&Wvl, g_Wvl);
    cudaGetSymbolAddress((void**)&Woh, g_Woh); cudaGetSymbolAddress((void**)&Wol, g_Wol);
    cudaGetSymbolAddress((void**)&mbits, g_mbits);

    cudaFuncSetAttribute(mma_gemm_kernel, cudaFuncAttributeMaxDynamicSharedMemorySize,
                         (int)MMG_SMEM);
    cudaFuncSetAttribute(mma_gemm64_kernel, cudaFuncAttributeMaxDynamicSharedMemorySize,
                         (int)MMG64_SMEM);
    cudaFuncSetAttribute(attn_mma_kernel, cudaFuncAttributeMaxDynamicSharedMemorySize,
                         (int)AT_SMEM);

    const dim3 gb(256);

    // fused prepasses: input splits + weight transpose/split + mask bit-pack
    prep_kernel<<<PREP_TOTAL_B, gb>>>(
        q_in, k_in, v_in, Xqh, Xql, Xkh, Xkl, Xvh, Xvl,
        Wq, Wv, Wo, Wqh, Wql, Wvh, Wvl, Woh, Wol,
        smask, mbits);

    // Q + K + V projections fused in one launch (grid.z = 3)
    const dim3 ggrid3(DD / 128, MM / 128, 3);
    mma_gemm_kernel<<<ggrid3, gb, MMG_SMEM>>>(
        Xqh, Xql, Xkh, Xkl, Xvh, Xvl,
        Wqh, Wql, Wvh, Wvl,
        bq, bv,
        Qh, Ql, Kh, Kl, Vh, Vl);

    // tensor-core attention: 1024 CTAs, heavy-first, 3 CTAs/SM
    attn_mma_kernel<<<1024, 128, AT_SMEM>>>(Qh, Ql, Kh, Kl, Vh, Vl,
                                            Xqh, Xql, Xkh, Xkl, mbits, gam, Oh, Ol);

    // output projection + bias + residual -> fp32 out (64-row tiles, balanced)
    const dim3 ggrid64(DD / 128, MM / 64);   // (4, 128) = 512 CTAs
    mma_gemm64_kernel<<<ggrid64, 128, MMG64_SMEM>>>(
        Oh, Ol, Woh, Wol, bo, q_in, out);

    // in-place LayerNorm
    ln_kernel<<<MM / 8, gb>>>(out, ln_g, ln_b);
}

// round 14
// speedup vs baseline: 1.0640x; 1.0119x over previous
#include <cuda_runtime.h>
#include <cuda_bf16.h>
#include <math.h>
#include <cstdint>

// Problem constants
#define BB 8
#define SS 1024
#define DD 512
#define HH 8
#define DKK 64
#define MM (BB*SS)   // 8192 rows
#define NELEM ((size_t)MM * DD)

// ---------------- scratch (static __device__: allocation-guard safe) --------
__device__ __nv_bfloat16 g_Xqh[NELEM], g_Xql[NELEM];
__device__ __nv_bfloat16 g_Xkh[NELEM], g_Xkl[NELEM];
__device__ __nv_bfloat16 g_Xvh[NELEM], g_Xvl[NELEM];
__device__ __nv_bfloat16 g_Qh[NELEM], g_Ql[NELEM];
__device__ __nv_bfloat16 g_Kh[NELEM], g_Kl[NELEM];
__device__ __nv_bfloat16 g_Vh[NELEM], g_Vl[NELEM];
__device__ __nv_bfloat16 g_Oh[NELEM], g_Ol[NELEM];
__device__ __nv_bfloat16 g_Wqh[DD * DD], g_Wql[DD * DD];
__device__ __nv_bfloat16 g_Wvh[DD * DD], g_Wvl[DD * DD];
__device__ __nv_bfloat16 g_Woh[DD * DD], g_Wol[DD * DD];
__device__ unsigned long long g_mbits[(size_t)MM * 16];

// ---------------- PTX helpers (base sm_103-safe) -----------------------------
__device__ __forceinline__ uint32_t smem_u32(const void* p) {
    uint32_t a;
    asm("{ .reg .u64 t; cvta.to.shared.u64 t, %1; cvt.u32.u64 %0, t; }" : "=r"(a) : "l"(p));
    return a;
}
#define CP_ASYNC16(dst, src) \
    asm volatile("cp.async.cg.shared.global [%0], [%1], 16;" :: "r"(dst), "l"(src) : "memory")
#define CP_COMMIT() asm volatile("cp.async.commit_group;" ::: "memory")
#define CP_WAIT1()  asm volatile("cp.async.wait_group 1;" ::: "memory")
#define CP_WAIT0()  asm volatile("cp.async.wait_group 0;" ::: "memory")

__device__ __forceinline__ void ldm_x4(uint32_t& r0, uint32_t& r1, uint32_t& r2,
                                       uint32_t& r3, uint32_t addr) {
    asm volatile("ldmatrix.sync.aligned.m8n8.x4.shared.b16 {%0,%1,%2,%3}, [%4];"
                 : "=r"(r0), "=r"(r1), "=r"(r2), "=r"(r3) : "r"(addr));
}
__device__ __forceinline__ void ldm_x4t(uint32_t& r0, uint32_t& r1, uint32_t& r2,
                                        uint32_t& r3, uint32_t addr) {
    asm volatile("ldmatrix.sync.aligned.m8n8.x4.trans.shared.b16 {%0,%1,%2,%3}, [%4];"
                 : "=r"(r0), "=r"(r1), "=r"(r2), "=r"(r3) : "r"(addr));
}
__device__ __forceinline__ void mma16816(float* d, const uint32_t* a, const uint32_t* b) {
    asm volatile("mma.sync.aligned.m16n8k16.row.col.f32.bf16.bf16.f32 "
                 "{%0,%1,%2,%3}, {%4,%5,%6,%7}, {%8,%9}, {%0,%1,%2,%3};"
                 : "+f"(d[0]), "+f"(d[1]), "+f"(d[2]), "+f"(d[3])
                 : "r"(a[0]), "r"(a[1]), "r"(a[2]), "r"(a[3]), "r"(b[0]), "r"(b[1]));
}
__device__ __forceinline__ uint32_t pack_bf2(float a, float b) {
    __nv_bfloat162 t = __floats2bfloat162_rn(a, b);
    return *(uint32_t*)&t;
}
__device__ __forceinline__ void split2(float a, float b, uint32_t& hi, uint32_t& lo) {
    const __nv_bfloat16 ha = __float2bfloat16(a), hb = __float2bfloat16(b);
    const float ra = a - __bfloat162float(ha), rb = b - __bfloat162float(hb);
    __nv_bfloat162 th; th.x = ha; th.y = hb;
    hi = *(uint32_t*)&th;
    lo = pack_bf2(ra, rb);
}

// ---------------------------------------------------------------------------
// Fused prepass kernel: split3 + wsplit3 + triangle-only pack_mask.
// mbits[row][word] is only consumed when word*64 < row (reads at the causal
// boundary are gated to don't-care lanes), so upper-triangle words are skipped.
// ---------------------------------------------------------------------------
#define PREP_SPLIT_B 12288
#define PREP_WSPL_B  768
#define PREP_MASK_B  16384
#define PREP_TOTAL_B (PREP_SPLIT_B + PREP_WSPL_B + PREP_MASK_B)

__global__ __launch_bounds__(256) void prep_kernel(
    const float* __restrict__ Xq, const float* __restrict__ Xk,
    const float* __restrict__ Xv,
    __nv_bfloat16* __restrict__ Xqh, __nv_bfloat16* __restrict__ Xql,
    __nv_bfloat16* __restrict__ Xkh, __nv_bfloat16* __restrict__ Xkl,
    __nv_bfloat16* __restrict__ Xvh, __nv_bfloat16* __restrict__ Xvl,
    const float* __restrict__ Wq, const float* __restrict__ Wv,
    const float* __restrict__ Wo,
    __nv_bfloat16* __restrict__ Wqh, __nv_bfloat16* __restrict__ Wql,
    __nv_bfloat16* __restrict__ Wvh, __nv_bfloat16* __restrict__ Wvl,
    __nv_bfloat16* __restrict__ Woh, __nv_bfloat16* __restrict__ Wol,
    const int* __restrict__ smask, unsigned long long* __restrict__ bits)
{
    __shared__ float tile[32][33];
    const int bid = blockIdx.x;
    const int tid = threadIdx.x;

    if (bid < PREP_SPLIT_B) {
        const int s = bid / 4096;
        const int blk = bid - s * 4096;
        const float* X = (s == 0) ? Xq : (s == 1) ? Xk : Xv;
        __nv_bfloat16* H = (s == 0) ? Xqh : (s == 1) ? Xkh : Xvh;
        __nv_bfloat16* L = (s == 0) ? Xql : (s == 1) ? Xkl : Xvl;
        const size_t i = ((size_t)blk * 256 + tid) * 4;
        float4 v = *(const float4*)(X + i);
        __nv_bfloat16 h[4], l[4];
        float x[4] = {v.x, v.y, v.z, v.w};
#pragma unroll
        for (int j = 0; j < 4; j++) {
            h[j] = __float2bfloat16(x[j]);
            l[j] = __float2bfloat16(x[j] - __bfloat162float(h[j]));
        }
        *(uint2*)(H + i) = *(uint2*)h;
        *(uint2*)(L + i) = *(uint2*)l;
    } else if (bid < PREP_SPLIT_B + PREP_WSPL_B) {
        const int w = bid - PREP_SPLIT_B;
        const int s = w / 256;
        const int rem = w - s * 256;
        const int bx = rem & 15, by = rem >> 4;
        const float* W = (s == 0) ? Wq : (s == 1) ? Wv : Wo;
        __nv_bfloat16* Ht = (s == 0) ? Wqh : (s == 1) ? Wvh : Woh;
        __nv_bfloat16* Lt = (s == 0) ? Wql : (s == 1) ? Wvl : Wol;
        const int tx = tid & 31, ty = tid >> 5;
        const int k0 = by * 32, n0 = bx * 32;
#pragma unroll
        for (int r = 0; r < 4; r++)
            tile[ty * 4 + r][tx] = W[(size_t)(k0 + ty * 4 + r) * DD + n0 + tx];
        __syncthreads();
#pragma unroll
        for (int r = 0; r < 4; r++) {
            const int n = n0 + ty * 4 + r;
            const float x = tile[tx][ty * 4 + r];
            const __nv_bfloat16 h = __float2bfloat16(x);
            Ht[(size_t)n * DD + k0 + tx] = h;
            Lt[(size_t)n * DD + k0 + tx] = __float2bfloat16(x - __bfloat162float(h));
        }
    } else {
        const int pb = bid - PREP_SPLIT_B - PREP_WSPL_B;
        const int gw = pb * 8 + (tid >> 5);
        const int lane = tid & 31;
        const int word = gw & 15;
        const int row  = gw >> 4;
        const int srow = row & (SS - 1);           // row within sequence
        if (word * 64 < srow) {                    // triangle-only
            const int* p = smask + (size_t)row * SS + word * 64;
            const unsigned lo = __ballot_sync(0xffffffffu, p[lane] != 0);
            const unsigned hi = __ballot_sync(0xffffffffu, p[lane + 32] != 0);
            if (lane == 0)
                bits[(size_t)row * 16 + word] = ((unsigned long long)hi << 32) | lo;
        }
    }
}

// ---------------------------------------------------------------------------
// mma.sync bf16x3 GEMM (256 threads, CTA 128x128, warp tile 32x64), K-chunk 32,
// cp.async double buffer. grid.z selects operand set (fused QKV projections).
// ---------------------------------------------------------------------------
#define LDSP 40
#define OPB  (128 * LDSP * 2)
#define STAGE_B (4 * OPB)
#define MMG_SMEM (2 * STAGE_B)

extern __shared__ char mm_sm[];

__global__ __launch_bounds__(256) void mma_gemm_kernel(
    const __nv_bfloat16* __restrict__ Ah0, const __nv_bfloat16* __restrict__ Al0,
    const __nv_bfloat16* __restrict__ Ah1, const __nv_bfloat16* __restrict__ Al1,
    const __nv_bfloat16* __restrict__ Ah2, const __nv_bfloat16* __restrict__ Al2,
    const __nv_bfloat16* __restrict__ Bh0, const __nv_bfloat16* __restrict__ Bl0,
    const __nv_bfloat16* __restrict__ Bh1, const __nv_bfloat16* __restrict__ Bl1,
    const float* __restrict__ bias0, const float* __restrict__ bias1,
    __nv_bfloat16* __restrict__ Ch0, __nv_bfloat16* __restrict__ Cl0,
    __nv_bfloat16* __restrict__ Ch1, __nv_bfloat16* __restrict__ Cl1,
    __nv_bfloat16* __restrict__ Ch2, __nv_bfloat16* __restrict__ Cl2)
{
    const uint32_t smb = smem_u32(mm_sm);
    const int tid  = threadIdx.x;
    const int wid  = tid >> 5;
    const int lane = tid & 31;
    const int wm   = wid & 3;
    const int wn   = wid >> 2;
    const int m0 = blockIdx.y * 128, n0 = blockIdx.x * 128;
    const int z = blockIdx.z;
    const __nv_bfloat16* Ah = (z == 0) ? Ah0 : (z == 1) ? Ah1 : Ah2;
    const __nv_bfloat16* Al = (z == 0) ? Al0 : (z == 1) ? Al1 : Al2;
    const __nv_bfloat16* Bh = (z == 2) ? Bh1 : Bh0;
    const __nv_bfloat16* Bl = (z == 2) ? Bl1 : Bl0;
    const float* bias = (z == 2) ? bias1 : bias0;
    __nv_bfloat16* Ch = (z == 0) ? Ch0 : (z == 1) ? Ch1 : Ch2;
    __nv_bfloat16* Cl = (z == 0) ? Cl0 : (z == 1) ? Cl1 : Cl2;

    const char* srcs[4] = {
        (const char*)(Ah + (size_t)m0 * DD),
        (const char*)(Al + (size_t)m0 * DD),
        (const char*)(Bh + (size_t)n0 * DD),
        (const char*)(Bl + (size_t)n0 * DD)
    };

    int l_op[8], l_row[8], l_seg[8];
#pragma unroll
    for (int i = 0; i < 8; i++) {
        const int idx = tid + i * 256;
        l_op[i]  = idx >> 9;
        l_row[i] = (idx & 511) >> 2;
        l_seg[i] = idx & 3;
    }

    float acc[2][8][4];
#pragma unroll
    for (int mt = 0; mt < 2; mt++)
#pragma unroll
        for (int nt = 0; nt < 8; nt++)
#pragma unroll
            for (int r = 0; r < 4; r++) acc[mt][nt][r] = 0.f;

    const int lrow = lane & 15;
    const int lkof = (lane >> 4) * 8;

#pragma unroll
    for (int i = 0; i < 8; i++) {
        CP_ASYNC16(smb + l_op[i] * OPB + l_row[i] * 80 + l_seg[i] * 16,
                   srcs[l_op[i]] + (size_t)l_row[i] * 1024 + l_seg[i] * 16);
    }
    CP_COMMIT();

    for (int c = 0; c < 16; c++) {
        if (c + 1 < 16) {
            const uint32_t sb = smb + ((c + 1) & 1) * STAGE_B;
            const int koff = (c + 1) * 64;
#pragma unroll
            for (int i = 0; i < 8; i++) {
                CP_ASYNC16(sb + l_op[i] * OPB + l_row[i] * 80 + l_seg[i] * 16,
                           srcs[l_op[i]] + (size_t)l_row[i] * 1024 + koff + l_seg[i] * 16);
            }
            CP_COMMIT();
            CP_WAIT1();
        } else {
            CP_WAIT0();
        }
        __syncthreads();

        const uint32_t sb = smb + (c & 1) * STAGE_B;
#pragma unroll
        for (int ks = 0; ks < 32; ks += 16) {
            uint32_t ah[2][4], al[2][4];
#pragma unroll
            for (int mt = 0; mt < 2; mt++) {
                const int r = wm * 32 + mt * 16 + lrow;
                const uint32_t ad = sb + r * 80 + (ks + lkof) * 2;
                ldm_x4(ah[mt][0], ah[mt][1], ah[mt][2], ah[mt][3], ad);
                ldm_x4(al[mt][0], al[mt][1], al[mt][2], al[mt][3], ad + OPB);
            }
            uint32_t bh[8][2], bl[8][2];
#pragma unroll
            for (int np = 0; np < 4; np++) {
                const int r = wn * 64 + np * 16 + lrow;
                const uint32_t bd = sb + 2 * OPB + r * 80 + (ks + lkof) * 2;
                uint32_t t0, t1, t2, t3;
                ldm_x4(t0, t1, t2, t3, bd);
                bh[np * 2][0] = t0; bh[np * 2][1] = t2;
                bh[np * 2 + 1][0] = t1; bh[np * 2 + 1][1] = t3;
                ldm_x4(t0, t1, t2, t3, bd + OPB);
                bl[np * 2][0] = t0; bl[np * 2][1] = t2;
                bl[np * 2 + 1][0] = t1; bl[np * 2 + 1][1] = t3;
            }
#pragma unroll
            for (int mt = 0; mt < 2; mt++)
#pragma unroll
                for (int nt = 0; nt < 8; nt++)
                    mma16816(acc[mt][nt], ah[mt], bh[nt]);
#pragma unroll
            for (int mt = 0; mt < 2; mt++)
#pragma unroll
                for (int nt = 0; nt < 8; nt++)
                    mma16816(acc[mt][nt], ah[mt], bl[nt]);
#pragma unroll
            for (int mt = 0; mt < 2; mt++)
#pragma unroll
                for (int nt = 0; nt < 8; nt++)
                    mma16816(acc[mt][nt], al[mt], bh[nt]);
        }
        __syncthreads();
    }

    const int qr = lane >> 2;
    const int qc = (lane & 3) * 2;
#pragma unroll
    for (int mt = 0; mt < 2; mt++) {
#pragma unroll
        for (int nt = 0; nt < 8; nt++) {
            const int col = n0 + wn * 64 + nt * 8 + qc;
            const float2 bv = *(const float2*)(bias + col);
#pragma unroll
            for (int half = 0; half < 2; half++) {
                const int row = m0 + wm * 32 + mt * 16 + qr + half * 8;
                float ox = acc[mt][nt][half * 2 + 0] + bv.x;
                float oy = acc[mt][nt][half * 2 + 1] + bv.y;
                uint32_t hi, lo;
                split2(ox, oy, hi, lo);
                *(uint32_t*)(Ch + (size_t)row * DD + col) = hi;
                *(uint32_t*)(Cl + (size_t)row * DD + col) = lo;
            }
        }
    }
}

// ---------------------------------------------------------------------------
// Output projection: CTA 64x128, 128 threads, 3 CTAs/SM (R13 config).
// ---------------------------------------------------------------------------
#define OPA64 (64 * LDSP * 2)
#define STAGE64 (2 * OPA64 + 2 * OPB)
#define MMG64_SMEM (2 * STAGE64)

__global__ __launch_bounds__(128, 3) void mma_gemm64_kernel(
    const __nv_bfloat16* __restrict__ Ah, const __nv_bfloat16* __restrict__ Al,
    const __nv_bfloat16* __restrict__ Bh, const __nv_bfloat16* __restrict__ Bl,
    const float* __restrict__ bias, const float* __restrict__ resid,
    float* __restrict__ C)
{
    const uint32_t smb = smem_u32(mm_sm);
    const int tid  = threadIdx.x;
    const int wid  = tid >> 5;
    const int lane = tid & 31;
    const int wm   = wid & 1;
    const int wn   = wid >> 1;
    const int m0 = blockIdx.y * 64, n0 = blockIdx.x * 128;

    const char* srcA[2] = {(const char*)(Ah + (size_t)m0 * DD),
                           (const char*)(Al + (size_t)m0 * DD)};
    const char* srcB[2] = {(const char*)(Bh + (size_t)n0 * DD),
                           (const char*)(Bl + (size_t)n0 * DD)};

    int l_isA[12], l_op[12], l_row[12], l_seg[12];
#pragma unroll
    for (int i = 0; i < 12; i++) {
        const int idx = tid + i * 128;
        if (idx < 512) {
            l_isA[i] = 1;
            l_op[i]  = idx >> 8;
            l_row[i] = (idx >> 2) & 63;
            l_seg[i] = idx & 3;
        } else {
            const int j = idx - 512;
            l_isA[i] = 0;
            l_op[i]  = j >> 9;
            l_row[i] = (j >> 2) & 127;
            l_seg[i] = j & 3;
        }
    }

    float acc[2][8][4];
#pragma unroll
    for (int mt = 0; mt < 2; mt++)
#pragma unroll
        for (int nt = 0; nt < 8; nt++)
#pragma unroll
            for (int r = 0; r < 4; r++) acc[mt][nt][r] = 0.f;

    const int lrow = lane & 15;
    const int lkof = (lane >> 4) * 8;

#pragma unroll
    for (int i = 0; i < 12; i++) {
        const uint32_t dst = smb +
            (l_isA[i] ? (l_op[i] * OPA64) : (2 * OPA64 + l_op[i] * OPB)) +
            l_row[i] * 80 + l_seg[i] * 16;
        const char* src = (l_isA[i] ? srcA[l_op[i]] : srcB[l_op[i]]) +
                          (size_t)l_row[i] * 1024 + l_seg[i] * 16;
        CP_ASYNC16(dst, src);
    }
    CP_COMMIT();

    for (int c = 0; c < 16; c++) {
        if (c + 1 < 16) {
            const uint32_t sb = smb + ((c + 1) & 1) * STAGE64;
            const int koff = (c + 1) * 64;
#pragma unroll
            for (int i = 0; i < 12; i++) {
                const uint32_t dst = sb +
                    (l_isA[i] ? (l_op[i] * OPA64) : (2 * OPA64 + l_op[i] * OPB)) +
                    l_row[i] * 80 + l_seg[i] * 16;
                const char* src = (l_isA[i] ? srcA[l_op[i]] : srcB[l_op[i]]) +
                                  (size_t)l_row[i] * 1024 + koff + l_seg[i] * 16;
                CP_ASYNC16(dst, src);
            }
            CP_COMMIT();
            CP_WAIT1();
        } else {
            CP_WAIT0();
        }
        __syncthreads();

        const uint32_t sb = smb + (c & 1) * STAGE64;
#pragma unroll
        for (int ks = 0; ks < 32; ks += 16) {
            uint32_t ah[2][4], al[2][4];
#pragma unroll
            for (int mt = 0; mt < 2; mt++) {
                const int r = wm * 32 + mt * 16 + lrow;
                const uint32_t ad = sb + r * 80 + (ks + lkof) * 2;
                ldm_x4(ah[mt][0], ah[mt][1], ah[mt][2], ah[mt][3], ad);
                ldm_x4(al[mt][0], al[mt][1], al[mt][2], al[mt][3], ad + OPA64);
            }
            uint32_t bh[8][2], bl[8][2];
#pragma unroll
            for (int np = 0; np < 4; np++) {
                const int r = wn * 64 + np * 16 + lrow;
                const uint32_t bd = sb + 2 * OPA64 + r * 80 + (ks + lkof) * 2;
                uint32_t t0, t1, t2, t3;
                ldm_x4(t0, t1, t2, t3, bd);
                bh[np * 2][0] = t0; bh[np * 2][1] = t2;
                bh[np * 2 + 1][0] = t1; bh[np * 2 + 1][1] = t3;
                ldm_x4(t0, t1, t2, t3, bd + OPB);
                bl[np * 2][0] = t0; bl[np * 2][1] = t2;
                bl[np * 2 + 1][0] = t1; bl[np * 2 + 1][1] = t3;
            }
#pragma unroll
            for (int mt = 0; mt < 2; mt++)
#pragma unroll
                for (int nt = 0; nt < 8; nt++)
                    mma16816(acc[mt][nt], ah[mt], bh[nt]);
#pragma unroll
            for (int mt = 0; mt < 2; mt++)
#pragma unroll
                for (int nt = 0; nt < 8; nt++)
                    mma16816(acc[mt][nt], ah[mt], bl[nt]);
#pragma unroll
            for (int mt = 0; mt < 2; mt++)
#pragma unroll
                for (int nt = 0; nt < 8; nt++)
                    mma16816(acc[mt][nt], al[mt], bh[nt]);
        }
        __syncthreads();
    }

    const int qr = lane >> 2;
    const int qc = (lane & 3) * 2;
#pragma unroll
    for (int mt = 0; mt < 2; mt++) {
#pragma unroll
        for (int nt = 0; nt < 8; nt++) {
            const int col = n0 + wn * 64 + nt * 8 + qc;
            const float2 bv = *(const float2*)(bias + col);
#pragma unroll
            for (int half = 0; half < 2; half++) {
                const int row = m0 + wm * 32 + mt * 16 + qr + half * 8;
                const float2 rv = *(const float2*)(resid + (size_t)row * DD + col);
                float2 o;
                o.x = acc[mt][nt][half * 2 + 0] + bv.x + rv.x;
                o.y = acc[mt][nt][half * 2 + 1] + bv.y + rv.y;
                *(float2*)(C + (size_t)row * DD + col) = o;
            }
        }
    }
}

// ---------------------------------------------------------------------------
// Tensor-core dual-score causal flash attention (R10 config; mbits prefetched
// ahead of the s2 MMA block).
// ---------------------------------------------------------------------------
#define ATS   144
#define QOP   9216
#define KOP   4608
#define STG   (6 * KOP)
#define AT_SMEM (2 * QOP + 2 * STG)

extern __shared__ char at_sm[];

__device__ __forceinline__ void at_load_tile32(
    uint32_t smb, int buf, int tid, int b, int kt0, int hc,
    const __nv_bfloat16* Kh, const __nv_bfloat16* Kl,
    const __nv_bfloat16* Rkh, const __nv_bfloat16* Rkl,
    const __nv_bfloat16* Vh, const __nv_bfloat16* Vl)
{
    const char* srcs[6] = {(const char*)Kh, (const char*)Kl, (const char*)Rkh,
                           (const char*)Rkl, (const char*)Vh, (const char*)Vl};
    const uint32_t base = smb + 2 * QOP + buf * STG;
#pragma unroll
    for (int i = 0; i < 12; i++) {
        const int idx = tid + i * 128;
        const int op = idx >> 8, r = (idx >> 3) & 31, seg = idx & 7;
        CP_ASYNC16(base + op * KOP + r * ATS + seg * 16,
                   srcs[op] + ((size_t)(b * SS + kt0 + r) * DD + hc) * 2 + seg * 16);
    }
}

__global__ __launch_bounds__(128, 3) void attn_mma_kernel(
    const __nv_bfloat16* __restrict__ Qh, const __nv_bfloat16* __restrict__ Ql,
    const __nv_bfloat16* __restrict__ Kh, const __nv_bfloat16* __restrict__ Kl,
    const __nv_bfloat16* __restrict__ Vh, const __nv_bfloat16* __restrict__ Vl,
    const __nv_bfloat16* __restrict__ Rqh, const __nv_bfloat16* __restrict__ Rql,
    const __nv_bfloat16* __restrict__ Rkh, const __nv_bfloat16* __restrict__ Rkl,
    const unsigned long long* __restrict__ mbits, const float* __restrict__ gammas,
    __nv_bfloat16* __restrict__ Oh, __nv_bfloat16* __restrict__ Ol)
{
    const uint32_t smb = smem_u32(at_sm);
    const int tid = threadIdx.x, lane = tid & 31, w = tid >> 5;
    const int bh = blockIdx.x & 63;
    const int q0 = (15 - (blockIdx.x >> 6)) * 64;
    const int b  = bh >> 3, h = bh & 7;
    const int hc = h * DKK;

    float g  = gammas[h];
    float sp = (g > 20.f) ? g : log1pf(__expf(g));
    float te = __expf(-sp);
    te = fminf(fmaxf(te, 1e-5f), 1e5f);
    const float f1 = 0.125f;
    const float f2 = te * rsqrtf((float)DD);
    const float f2f1 = f2 * 8.0f;

    const int qcb = (lane & 3) * 2;
    const int gg = lane >> 3, l8 = lane & 7;
    const int mrw = w * 16 + ((gg & 1) << 3) + l8;
    const int r1 = q0 + w * 16 + (lane >> 2);
    const int r2 = r1 + 8;

    {
        const char* qsrc[4] = {(const char*)Qh, (const char*)Ql,
                               (const char*)Rqh, (const char*)Rql};
#pragma unroll
        for (int i = 0; i < 16; i++) {
            const int idx = tid + i * 128;
            const int op = idx >> 9, r = (idx >> 3) & 63, seg = idx & 7;
            const uint32_t base = (op < 2) ? (smb + 2 * QOP + op * QOP)
                                           : (smb + (op - 2) * QOP);
            CP_ASYNC16(base + r * ATS + seg * 16,
                       qsrc[op] + ((size_t)(b * SS + q0 + r) * DD + hc) * 2 + seg * 16);
        }
        CP_COMMIT(); CP_WAIT0();
        __syncthreads();
    }
    uint32_t qph[4][4], qpl[4][4];
#pragma unroll
    for (int ks = 0; ks < 4; ks++) {
        const uint32_t qa = smb + 2 * QOP + mrw * ATS +
                            (ks * 16 + ((gg >> 1) << 3)) * 2;
        ldm_x4(qph[ks][0], qph[ks][1], qph[ks][2], qph[ks][3], qa);
        ldm_x4(qpl[ks][0], qpl[ks][1], qpl[ks][2], qpl[ks][3], qa + QOP);
    }
    __syncthreads();

    float oacc[8][4];
#pragma unroll
    for (int nt = 0; nt < 8; nt++)
#pragma unroll
        for (int e = 0; e < 4; e++) oacc[nt][e] = 0.f;
    float mrow[2] = {-1e30f, -1e30f};
    float lsum[2] = {0.f, 0.f};

    const int T = q0 / 32 + 2;

    at_load_tile32(smb, 0, tid, b, 0, hc, Kh, Kl, Rkh, Rkl, Vh, Vl);
    CP_COMMIT();

    for (int t = 0; t < T; t++) {
        const int kt0 = t * 32;
        // prefetch mask words early (hidden behind s2 MMAs)
        const unsigned long long mw1 =
            mbits[(size_t)(b * SS + r1) * 16 + (kt0 >> 6)];
        const unsigned long long mw2 =
            mbits[(size_t)(b * SS + r2) * 16 + (kt0 >> 6)];
        if (t + 1 < T) {
            at_load_tile32(smb, (t + 1) & 1, tid, b, kt0 + 32, hc, Kh, Kl, Rkh, Rkl, Vh, Vl);
            CP_COMMIT(); CP_WAIT1();
        } else {
            CP_WAIT0();
        }
        __syncthreads();

        const uint32_t sb = smb + 2 * QOP + (t & 1) * STG;

        float sc[4][4];
#pragma unroll
        for (int nt = 0; nt < 4; nt++)
#pragma unroll
            for (int e = 0; e < 4; e++) sc[nt][e] = 0.f;

        // ---- s2: raw scores ----
#pragma unroll
        for (int ks = 0; ks < 4; ks++) {
            uint32_t qh4[4], ql4[4];
            const uint32_t qa = smb + mrw * ATS + (ks * 16 + ((gg >> 1) << 3)) * 2;
            ldm_x4(qh4[0], qh4[1], qh4[2], qh4[3], qa);
            ldm_x4(ql4[0], ql4[1], ql4[2], ql4[3], qa + QOP);
            uint32_t bh2[4][2], bl2[4][2];
#pragma unroll
            for (int np = 0; np < 2; np++) {
                const uint32_t ad = sb + 2 * KOP +
                    (np * 16 + ((gg >> 1) << 3) + l8) * ATS +
                    (ks * 16 + ((gg & 1) << 3)) * 2;
                uint32_t t0, t1, t2, t3;
                ldm_x4(t0, t1, t2, t3, ad);
                bh2[np*2][0] = t0; bh2[np*2][1] = t1;
                bh2[np*2+1][0] = t2; bh2[np*2+1][1] = t3;
                ldm_x4(t0, t1, t2, t3, ad + KOP);
                bl2[np*2][0] = t0; bl2[np*2][1] = t1;
                bl2[np*2+1][0] = t2; bl2[np*2+1][1] = t3;
            }
#pragma unroll
            for (int nt = 0; nt < 4; nt++)
                mma16816(sc[nt], qh4, bh2[nt]);
#pragma unroll
            for (int nt = 0; nt < 4; nt++)
                mma16816(sc[nt], qh4, bl2[nt]);
#pragma unroll
            for (int nt = 0; nt < 4; nt++)
                mma16816(sc[nt], ql4, bh2[nt]);
        }

        // ---- gate s2 by packed mask ----
        const int msh = kt0 & 32;
#pragma unroll
        for (int nt = 0; nt < 4; nt++) {
            const int j0 = msh + nt * 8 + qcb;
            sc[nt][0] = ((mw1 >> j0) & 1)       ? sc[nt][0] * f2f1 : 0.f;
            sc[nt][1] = ((mw1 >> (j0 + 1)) & 1) ? sc[nt][1] * f2f1 : 0.f;
            sc[nt][2] = ((mw2 >> j0) & 1)       ? sc[nt][2] * f2f1 : 0.f;
            sc[nt][3] = ((mw2 >> (j0 + 1)) & 1) ? sc[nt][3] * f2f1 : 0.f;
        }

        // ---- s1: projected scores ----
#pragma unroll
        for (int ks = 0; ks < 4; ks++) {
            uint32_t bh2[4][2], bl2[4][2];
#pragma unroll
            for (int np = 0; np < 2; np++) {
                const uint32_t ad = sb +
                    (np * 16 + ((gg >> 1) << 3) + l8) * ATS +
                    (ks * 16 + ((gg & 1) << 3)) * 2;
                uint32_t t0, t1, t2, t3;
                ldm_x4(t0, t1, t2, t3, ad);
                bh2[np*2][0] = t0; bh2[np*2][1] = t1;
                bh2[np*2+1][0] = t2; bh2[np*2+1][1] = t3;
                ldm_x4(t0, t1, t2, t3, ad + KOP);
                bl2[np*2][0] = t0; bl2[np*2][1] = t1;
                bl2[np*2+1][0] = t2; bl2[np*2+1][1] = t3;
            }
#pragma unroll
            for (int nt = 0; nt < 4; nt++)
                mma16816(sc[nt], qph[ks], bh2[nt]);
#pragma unroll
            for (int nt = 0; nt < 4; nt++)
                mma16816(sc[nt], qph[ks], bl2[nt]);
#pragma unroll
            for (int nt = 0; nt < 4; nt++)
                mma16816(sc[nt], qpl[ks], bh2[nt]);
        }

        // ---- causal mask + final scale ----
#pragma unroll
        for (int nt = 0; nt < 4; nt++) {
            const int gj0 = kt0 + nt * 8 + qcb;
            sc[nt][0] = (gj0     < r1) ? sc[nt][0] * f1 : -INFINITY;
            sc[nt][1] = (gj0 + 1 < r1) ? sc[nt][1] * f1 : -INFINITY;
            sc[nt][2] = (gj0     < r2) ? sc[nt][2] * f1 : -INFINITY;
            sc[nt][3] = (gj0 + 1 < r2) ? sc[nt][3] * f1 : -INFINITY;
        }

        // ---- online softmax ----
        float rm1 = -INFINITY, rm2 = -INFINITY;
#pragma unroll
        for (int nt = 0; nt < 4; nt++) {
            rm1 = fmaxf(rm1, fmaxf(sc[nt][0], sc[nt][1]));
            rm2 = fmaxf(rm2, fmaxf(sc[nt][2], sc[nt][3]));
        }
        rm1 = fmaxf(rm1, __shfl_xor_sync(0xffffffffu, rm1, 1));
        rm1 = fmaxf(rm1, __shfl_xor_sync(0xffffffffu, rm1, 2));
        rm2 = fmaxf(rm2, __shfl_xor_sync(0xffffffffu, rm2, 1));
        rm2 = fmaxf(rm2, __shfl_xor_sync(0xffffffffu, rm2, 2));
        const float mn1 = fmaxf(mrow[0], rm1);
        const float mn2 = fmaxf(mrow[1], rm2);
        const float scl1 = __expf(mrow[0] - mn1);
        const float scl2 = __expf(mrow[1] - mn2);
        mrow[0] = mn1; mrow[1] = mn2;

        float ps1 = 0.f, ps2 = 0.f;
#pragma unroll
        for (int nt = 0; nt < 4; nt++) {
            sc[nt][0] = __expf(sc[nt][0] - mn1);
            sc[nt][1] = __expf(sc[nt][1] - mn1);
            sc[nt][2] = __expf(sc[nt][2] - mn2);
            sc[nt][3] = __expf(sc[nt][3] - mn2);
            ps1 += sc[nt][0] + sc[nt][1];
            ps2 += sc[nt][2] + sc[nt][3];
        }
        ps1 += __shfl_xor_sync(0xffffffffu, ps1, 1);
        ps1 += __shfl_xor_sync(0xffffffffu, ps1, 2);
        ps2 += __shfl_xor_sync(0xffffffffu, ps2, 1);
        ps2 += __shfl_xor_sync(0xffffffffu, ps2, 2);
        lsum[0] = lsum[0] * scl1 + ps1;
        lsum[1] = lsum[1] * scl2 + ps2;

#pragma unroll
        for (int nt = 0; nt < 8; nt++) {
            oacc[nt][0] *= scl1; oacc[nt][1] *= scl1;
            oacc[nt][2] *= scl2; oacc[nt][3] *= scl2;
        }

        uint32_t pha[2][4], pla[2][4];
#pragma unroll
        for (int j = 0; j < 2; j++) {
            split2(sc[2*j][0],   sc[2*j][1],   pha[j][0], pla[j][0]);
            split2(sc[2*j][2],   sc[2*j][3],   pha[j][1], pla[j][1]);
            split2(sc[2*j+1][0], sc[2*j+1][1], pha[j][2], pla[j][2]);
            split2(sc[2*j+1][2], sc[2*j+1][3], pha[j][3], pla[j][3]);
        }

        // ---- PV (bf16x3) ----
#pragma unroll
        for (int j = 0; j < 2; j++) {
            uint32_t vh2[8][2], vl2[8][2];
#pragma unroll
            for (int np = 0; np < 4; np++) {
                const uint32_t ad = sb + 4 * KOP +
                    (j * 16 + ((gg & 1) << 3) + l8) * ATS +
                    (np * 16 + ((gg >> 1) << 3)) * 2;
                uint32_t t0, t1, t2, t3;
                ldm_x4t(t0, t1, t2, t3, ad);
                vh2[np*2][0] = t0; vh2[np*2][1] = t1;
                vh2[np*2+1][0] = t2; vh2[np*2+1][1] = t3;
                ldm_x4t(t0, t1, t2, t3, ad + KOP);
                vl2[np*2][0] = t0; vl2[np*2][1] = t1;
                vl2[np*2+1][0] = t2; vl2[np*2+1][1] = t3;
            }
#pragma unroll
            for (int nt = 0; nt < 8; nt++)
                mma16816(oacc[nt], pha[j], vh2[nt]);
#pragma unroll
            for (int nt = 0; nt < 8; nt++)
                mma16816(oacc[nt], pha[j], vl2[nt]);
#pragma unroll
            for (int nt = 0; nt < 8; nt++)
                mma16816(oacc[nt], pla[j], vh2[nt]);
        }
        __syncthreads();
    }

    const float rr1 = (lsum[0] > 0.f) ? (1.f / lsum[0]) : 0.f;
    const float rr2 = (lsum[1] > 0.f) ? (1.f / lsum[1]) : 0.f;
    const size_t base1 = (size_t)(b * SS + r1) * DD + hc;
    const size_t base2 = (size_t)(b * SS + r2) * DD + hc;
#pragma unroll
    for (int nt = 0; nt < 8; nt++) {
        const int co = nt * 8 + qcb;
        uint32_t hi, lo;
        split2(oacc[nt][0] * rr1, oacc[nt][1] * rr1, hi, lo);
        *(uint32_t*)(Oh + base1 + co) = hi;
        *(uint32_t*)(Ol + base1 + co) = lo;
        split2(oacc[nt][2] * rr2, oacc[nt][3] * rr2, hi, lo);
        *(uint32_t*)(Oh + base2 + co) = hi;
        *(uint32_t*)(Ol + base2 + co) = lo;
    }
}

// ---------------------------------------------------------------------------
// In-place LayerNorm: one warp per row of 512 floats.
// ---------------------------------------------------------------------------
__global__ __launch_bounds__(256) void ln_kernel(
    float* __restrict__ X, const float* __restrict__ gam, const float* __restrict__ bet)
{
    const int warp = threadIdx.x >> 5, lane = threadIdx.x & 31;
    const size_t row = (size_t)blockIdx.x * 8 + warp;
    float* xr = X + row * DD;

    float4 v[4];
    float s = 0.f, s2 = 0.f;
#pragma unroll
    for (int w = 0; w < 4; w++) {
        v[w] = *(const float4*)(xr + w * 128 + lane * 4);
        s  += v[w].x + v[w].y + v[w].z + v[w].w;
        s2 += v[w].x * v[w].x + v[w].y * v[w].y + v[w].z * v[w].z + v[w].w * v[w].w;
    }
#pragma unroll
    for (int o = 16; o > 0; o >>= 1) {
        s  += __shfl_xor_sync(0xffffffffu, s,  o);
        s2 += __shfl_xor_sync(0xffffffffu, s2, o);
    }
    const float mu  = s * (1.f / DD);
    const float var = s2 * (1.f / DD) - mu * mu;
    const float inv = rsqrtf(var + 1e-5f);
#pragma unroll
    for (int w = 0; w < 4; w++) {
        const int c = w * 128 + lane * 4;
        float4 gv = *(const float4*)(gam + c);
        float4 bv = *(const float4*)(bet + c);
        float4 o;
        o.x = (v[w].x - mu) * inv * gv.x + bv.x;
        o.y = (v[w].y - mu) * inv * gv.y + bv.y;
        o.z = (v[w].z - mu) * inv * gv.z + bv.z;
        o.w = (v[w].w - mu) * inv * gv.w + bv.w;
        *(float4*)(xr + c) = o;
    }
}

// ---------------------------------------------------------------------------
extern "C" void kernel_launch(void* const* d_in, const int* in_sizes, int n_in,
                              void* d_out, int out_size)
{
    const float* q_in  = (const float*)d_in[0];
    const float* k_in  = (const float*)d_in[1];
    const float* v_in  = (const float*)d_in[2];
    const int*   smask = (const int*)  d_in[3];
    const float* Wq    = (const float*)d_in[4];
    const float* bq    = (const float*)d_in[5];
    const float* Wv    = (const float*)d_in[6];
    const float* bv    = (const float*)d_in[7];
    const float* Wo    = (const float*)d_in[8];
    const float* bo    = (const float*)d_in[9];
    const float* gam   = (const float*)d_in[10];
    const float* ln_g  = (const float*)d_in[11];
    const float* ln_b  = (const float*)d_in[12];
    float* out = (float*)d_out;

    __nv_bfloat16 *Xqh, *Xql, *Xkh, *Xkl, *Xvh, *Xvl;
    __nv_bfloat16 *Qh, *Ql, *Kh, *Kl, *Vh, *Vl, *Oh, *Ol;
    __nv_bfloat16 *Wqh, *Wql, *Wvh, *Wvl, *Woh, *Wol;
    unsigned long long* mbits;
    cudaGetSymbolAddress((void**)&Xqh, g_Xqh); cudaGetSymbolAddress((void**)&Xql, g_Xql);
    cudaGetSymbolAddress((void**)&Xkh, g_Xkh); cudaGetSymbolAddress((void**)&Xkl, g_Xkl);
    cudaGetSymbolAddress((void**)&Xvh, g_Xvh); cudaGetSymbolAddress((void**)&Xvl, g_Xvl);
    cudaGetSymbolAddress((void**)&Qh, g_Qh);   cudaGetSymbolAddress((void**)&Ql, g_Ql);
    cudaGetSymbolAddress((void**)&Kh, g_Kh);   cudaGetSymbolAddress((void**)&Kl, g_Kl);
    cudaGetSymbolAddress((void**)&Vh, g_Vh);   cudaGetSymbolAddress((void**)&Vl, g_Vl);
    cudaGetSymbolAddress((void**)&Oh, g_Oh);   cudaGetSymbolAddress((void**)&Ol, g_Ol);
    cudaGetSymbolAddress((void**)&Wqh, g_Wqh); cudaGetSymbolAddress((void**)&Wql, g_Wql);
    cudaGetSymbolAddress((void**)&Wvh, g_Wvh); cudaGetSymbolAddress((void**)&Wvl, g_Wvl);
    cudaGetSymbolAddress((void**)&Woh, g_Woh); cudaGetSymbolAddress((void**)&Wol, g_Wol);
    cudaGetSymbolAddress((void**)&mbits, g_mbits);

    cudaFuncSetAttribute(mma_gemm_kernel, cudaFuncAttributeMaxDynamicSharedMemorySize,
                         (int)MMG_SMEM);
    cudaFuncSetAttribute(mma_gemm64_kernel, cudaFuncAttributeMaxDynamicSharedMemorySize,
                         (int)MMG64_SMEM);
    cudaFuncSetAttribute(attn_mma_kernel, cudaFuncAttributeMaxDynamicSharedMemorySize,
                         (int)AT_SMEM);

    const dim3 gb(256);

    // fused prepasses: input splits + weight transpose/split + triangle mask pack
    prep_kernel<<<PREP_TOTAL_B, gb>>>(
        q_in, k_in, v_in, Xqh, Xql, Xkh, Xkl, Xvh, Xvl,
        Wq, Wv, Wo, Wqh, Wql, Wvh, Wvl, Woh, Wol,
        smask, mbits);

    // Q + K + V projections fused in one launch (grid.z = 3)
    const dim3 ggrid3(DD / 128, MM / 128, 3);
    mma_gemm_kernel<<<ggrid3, gb, MMG_SMEM>>>(
        Xqh, Xql, Xkh, Xkl, Xvh, Xvl,
        Wqh, Wql, Wvh, Wvl,
        bq, bv,
        Qh, Ql, Kh, Kl, Vh, Vl);

    // tensor-core attention: 1024 CTAs, heavy-first, 3 CTAs/SM
    attn_mma_kernel<<<1024, 128, AT_SMEM>>>(Qh, Ql, Kh, Kl, Vh, Vl,
                                            Xqh, Xql, Xkh, Xkl, mbits, gam, Oh, Ol);

    // output projection + bias + residual -> fp32 out (64-row tiles, balanced)
    const dim3 ggrid64(DD / 128, MM / 64);   // (4, 128) = 512 CTAs
    mma_gemm64_kernel<<<ggrid64, 128, MMG64_SMEM>>>(
        Oh, Ol, Woh, Wol, bo, q_in, out);

    // in-place LayerNorm
    ln_kernel<<<MM / 8, gb>>>(out, ln_g, ln_b);
}

// round 15
// speedup vs baseline: 1.1023x; 1.0360x over previous
#include <cuda_runtime.h>
#include <cuda_bf16.h>
#include <math.h>
#include <cstdint>

// Problem constants
#define BB 8
#define SS 1024
#define DD 512
#define HH 8
#define DKK 64
#define MM (BB*SS)   // 8192 rows
#define NELEM ((size_t)MM * DD)

// ---------------- scratch (static __device__: allocation-guard safe) --------
__device__ __nv_bfloat16 g_Xqh[NELEM], g_Xql[NELEM];
__device__ __nv_bfloat16 g_Xkh[NELEM], g_Xkl[NELEM];
__device__ __nv_bfloat16 g_Xvh[NELEM], g_Xvl[NELEM];
__device__ __nv_bfloat16 g_Qh[NELEM], g_Ql[NELEM];
__device__ __nv_bfloat16 g_Kh[NELEM], g_Kl[NELEM];
__device__ __nv_bfloat16 g_Vh[NELEM], g_Vl[NELEM];
__device__ __nv_bfloat16 g_Oh[NELEM], g_Ol[NELEM];
__device__ __nv_bfloat16 g_Wqh[DD * DD], g_Wql[DD * DD];
__device__ __nv_bfloat16 g_Wvh[DD * DD], g_Wvl[DD * DD];
__device__ __nv_bfloat16 g_Woh[DD * DD], g_Wol[DD * DD];
__device__ unsigned long long g_mbits[(size_t)MM * 16];

// ---------------- PTX helpers (base sm_103-safe) -----------------------------
__device__ __forceinline__ uint32_t smem_u32(const void* p) {
    uint32_t a;
    asm("{ .reg .u64 t; cvta.to.shared.u64 t, %1; cvt.u32.u64 %0, t; }" : "=r"(a) : "l"(p));
    return a;
}
#define CP_ASYNC16(dst, src) \
    asm volatile("cp.async.cg.shared.global [%0], [%1], 16;" :: "r"(dst), "l"(src) : "memory")
#define CP_COMMIT() asm volatile("cp.async.commit_group;" ::: "memory")
#define CP_WAIT1()  asm volatile("cp.async.wait_group 1;" ::: "memory")
#define CP_WAIT0()  asm volatile("cp.async.wait_group 0;" ::: "memory")

__device__ __forceinline__ void ldm_x4(uint32_t& r0, uint32_t& r1, uint32_t& r2,
                                       uint32_t& r3, uint32_t addr) {
    asm volatile("ldmatrix.sync.aligned.m8n8.x4.shared.b16 {%0,%1,%2,%3}, [%4];"
                 : "=r"(r0), "=r"(r1), "=r"(r2), "=r"(r3) : "r"(addr));
}
__device__ __forceinline__ void ldm_x4t(uint32_t& r0, uint32_t& r1, uint32_t& r2,
                                        uint32_t& r3, uint32_t addr) {
    asm volatile("ldmatrix.sync.aligned.m8n8.x4.trans.shared.b16 {%0,%1,%2,%3}, [%4];"
                 : "=r"(r0), "=r"(r1), "=r"(r2), "=r"(r3) : "r"(addr));
}
__device__ __forceinline__ void mma16816(float* d, const uint32_t* a, const uint32_t* b) {
    asm volatile("mma.sync.aligned.m16n8k16.row.col.f32.bf16.bf16.f32 "
                 "{%0,%1,%2,%3}, {%4,%5,%6,%7}, {%8,%9}, {%0,%1,%2,%3};"
                 : "+f"(d[0]), "+f"(d[1]), "+f"(d[2]), "+f"(d[3])
                 : "r"(a[0]), "r"(a[1]), "r"(a[2]), "r"(a[3]), "r"(b[0]), "r"(b[1]));
}
__device__ __forceinline__ uint32_t pack_bf2(float a, float b) {
    __nv_bfloat162 t = __floats2bfloat162_rn(a, b);
    return *(uint32_t*)&t;
}
__device__ __forceinline__ void split2(float a, float b, uint32_t& hi, uint32_t& lo) {
    const __nv_bfloat16 ha = __float2bfloat16(a), hb = __float2bfloat16(b);
    const float ra = a - __bfloat162float(ha), rb = b - __bfloat162float(hb);
    __nv_bfloat162 th; th.x = ha; th.y = hb;
    hi = *(uint32_t*)&th;
    lo = pack_bf2(ra, rb);
}

// ---------------------------------------------------------------------------
// Fused prepass kernel: split3 + wsplit3 + triangle-only pack_mask.
// ---------------------------------------------------------------------------
#define PREP_SPLIT_B 12288
#define PREP_WSPL_B  768
#define PREP_MASK_B  16384
#define PREP_TOTAL_B (PREP_SPLIT_B + PREP_WSPL_B + PREP_MASK_B)

__global__ __launch_bounds__(256) void prep_kernel(
    const float* __restrict__ Xq, const float* __restrict__ Xk,
    const float* __restrict__ Xv,
    __nv_bfloat16* __restrict__ Xqh, __nv_bfloat16* __restrict__ Xql,
    __nv_bfloat16* __restrict__ Xkh, __nv_bfloat16* __restrict__ Xkl,
    __nv_bfloat16* __restrict__ Xvh, __nv_bfloat16* __restrict__ Xvl,
    const float* __restrict__ Wq, const float* __restrict__ Wv,
    const float* __restrict__ Wo,
    __nv_bfloat16* __restrict__ Wqh, __nv_bfloat16* __restrict__ Wql,
    __nv_bfloat16* __restrict__ Wvh, __nv_bfloat16* __restrict__ Wvl,
    __nv_bfloat16* __restrict__ Woh, __nv_bfloat16* __restrict__ Wol,
    const int* __restrict__ smask, unsigned long long* __restrict__ bits)
{
    __shared__ float tile[32][33];
    const int bid = blockIdx.x;
    const int tid = threadIdx.x;

    if (bid < PREP_SPLIT_B) {
        const int s = bid / 4096;
        const int blk = bid - s * 4096;
        const float* X = (s == 0) ? Xq : (s == 1) ? Xk : Xv;
        __nv_bfloat16* H = (s == 0) ? Xqh : (s == 1) ? Xkh : Xvh;
        __nv_bfloat16* L = (s == 0) ? Xql : (s == 1) ? Xkl : Xvl;
        const size_t i = ((size_t)blk * 256 + tid) * 4;
        float4 v = *(const float4*)(X + i);
        __nv_bfloat16 h[4], l[4];
        float x[4] = {v.x, v.y, v.z, v.w};
#pragma unroll
        for (int j = 0; j < 4; j++) {
            h[j] = __float2bfloat16(x[j]);
            l[j] = __float2bfloat16(x[j] - __bfloat162float(h[j]));
        }
        *(uint2*)(H + i) = *(uint2*)h;
        *(uint2*)(L + i) = *(uint2*)l;
    } else if (bid < PREP_SPLIT_B + PREP_WSPL_B) {
        const int w = bid - PREP_SPLIT_B;
        const int s = w / 256;
        const int rem = w - s * 256;
        const int bx = rem & 15, by = rem >> 4;
        const float* W = (s == 0) ? Wq : (s == 1) ? Wv : Wo;
        __nv_bfloat16* Ht = (s == 0) ? Wqh : (s == 1) ? Wvh : Woh;
        __nv_bfloat16* Lt = (s == 0) ? Wql : (s == 1) ? Wvl : Wol;
        const int tx = tid & 31, ty = tid >> 5;
        const int k0 = by * 32, n0 = bx * 32;
#pragma unroll
        for (int r = 0; r < 4; r++)
            tile[ty * 4 + r][tx] = W[(size_t)(k0 + ty * 4 + r) * DD + n0 + tx];
        __syncthreads();
#pragma unroll
        for (int r = 0; r < 4; r++) {
            const int n = n0 + ty * 4 + r;
            const float x = tile[tx][ty * 4 + r];
            const __nv_bfloat16 h = __float2bfloat16(x);
            Ht[(size_t)n * DD + k0 + tx] = h;
            Lt[(size_t)n * DD + k0 + tx] = __float2bfloat16(x - __bfloat162float(h));
        }
    } else {
        const int pb = bid - PREP_SPLIT_B - PREP_WSPL_B;
        const int gw = pb * 8 + (tid >> 5);
        const int lane = tid & 31;
        const int word = gw & 15;
        const int row  = gw >> 4;
        const int srow = row & (SS - 1);
        if (word * 64 < srow) {
            const int* p = smask + (size_t)row * SS + word * 64;
            const unsigned lo = __ballot_sync(0xffffffffu, p[lane] != 0);
            const unsigned hi = __ballot_sync(0xffffffffu, p[lane + 32] != 0);
            if (lane == 0)
                bits[(size_t)row * 16 + word] = ((unsigned long long)hi << 32) | lo;
        }
    }
}

// ---------------------------------------------------------------------------
// mma.sync bf16x3 GEMM (256 threads, CTA 128x128, warp tile 32x64), K-chunk 32,
// cp.async double buffer. grid.z selects operand set (fused QKV projections).
// ---------------------------------------------------------------------------
#define LDSP 40
#define OPB  (128 * LDSP * 2)
#define STAGE_B (4 * OPB)
#define MMG_SMEM (2 * STAGE_B)

extern __shared__ char mm_sm[];

__global__ __launch_bounds__(256) void mma_gemm_kernel(
    const __nv_bfloat16* __restrict__ Ah0, const __nv_bfloat16* __restrict__ Al0,
    const __nv_bfloat16* __restrict__ Ah1, const __nv_bfloat16* __restrict__ Al1,
    const __nv_bfloat16* __restrict__ Ah2, const __nv_bfloat16* __restrict__ Al2,
    const __nv_bfloat16* __restrict__ Bh0, const __nv_bfloat16* __restrict__ Bl0,
    const __nv_bfloat16* __restrict__ Bh1, const __nv_bfloat16* __restrict__ Bl1,
    const float* __restrict__ bias0, const float* __restrict__ bias1,
    __nv_bfloat16* __restrict__ Ch0, __nv_bfloat16* __restrict__ Cl0,
    __nv_bfloat16* __restrict__ Ch1, __nv_bfloat16* __restrict__ Cl1,
    __nv_bfloat16* __restrict__ Ch2, __nv_bfloat16* __restrict__ Cl2)
{
    const uint32_t smb = smem_u32(mm_sm);
    const int tid  = threadIdx.x;
    const int wid  = tid >> 5;
    const int lane = tid & 31;
    const int wm   = wid & 3;
    const int wn   = wid >> 2;
    const int m0 = blockIdx.y * 128, n0 = blockIdx.x * 128;
    const int z = blockIdx.z;
    const __nv_bfloat16* Ah = (z == 0) ? Ah0 : (z == 1) ? Ah1 : Ah2;
    const __nv_bfloat16* Al = (z == 0) ? Al0 : (z == 1) ? Al1 : Al2;
    const __nv_bfloat16* Bh = (z == 2) ? Bh1 : Bh0;
    const __nv_bfloat16* Bl = (z == 2) ? Bl1 : Bl0;
    const float* bias = (z == 2) ? bias1 : bias0;
    __nv_bfloat16* Ch = (z == 0) ? Ch0 : (z == 1) ? Ch1 : Ch2;
    __nv_bfloat16* Cl = (z == 0) ? Cl0 : (z == 1) ? Cl1 : Cl2;

    const char* srcs[4] = {
        (const char*)(Ah + (size_t)m0 * DD),
        (const char*)(Al + (size_t)m0 * DD),
        (const char*)(Bh + (size_t)n0 * DD),
        (const char*)(Bl + (size_t)n0 * DD)
    };

    int l_op[8], l_row[8], l_seg[8];
#pragma unroll
    for (int i = 0; i < 8; i++) {
        const int idx = tid + i * 256;
        l_op[i]  = idx >> 9;
        l_row[i] = (idx & 511) >> 2;
        l_seg[i] = idx & 3;
    }

    float acc[2][8][4];
#pragma unroll
    for (int mt = 0; mt < 2; mt++)
#pragma unroll
        for (int nt = 0; nt < 8; nt++)
#pragma unroll
            for (int r = 0; r < 4; r++) acc[mt][nt][r] = 0.f;

    const int lrow = lane & 15;
    const int lkof = (lane >> 4) * 8;

#pragma unroll
    for (int i = 0; i < 8; i++) {
        CP_ASYNC16(smb + l_op[i] * OPB + l_row[i] * 80 + l_seg[i] * 16,
                   srcs[l_op[i]] + (size_t)l_row[i] * 1024 + l_seg[i] * 16);
    }
    CP_COMMIT();

    for (int c = 0; c < 16; c++) {
        if (c + 1 < 16) {
            const uint32_t sb = smb + ((c + 1) & 1) * STAGE_B;
            const int koff = (c + 1) * 64;
#pragma unroll
            for (int i = 0; i < 8; i++) {
                CP_ASYNC16(sb + l_op[i] * OPB + l_row[i] * 80 + l_seg[i] * 16,
                           srcs[l_op[i]] + (size_t)l_row[i] * 1024 + koff + l_seg[i] * 16);
            }
            CP_COMMIT();
            CP_WAIT1();
        } else {
            CP_WAIT0();
        }
        __syncthreads();

        const uint32_t sb = smb + (c & 1) * STAGE_B;
#pragma unroll
        for (int ks = 0; ks < 32; ks += 16) {
            uint32_t ah[2][4], al[2][4];
#pragma unroll
            for (int mt = 0; mt < 2; mt++) {
                const int r = wm * 32 + mt * 16 + lrow;
                const uint32_t ad = sb + r * 80 + (ks + lkof) * 2;
                ldm_x4(ah[mt][0], ah[mt][1], ah[mt][2], ah[mt][3], ad);
                ldm_x4(al[mt][0], al[mt][1], al[mt][2], al[mt][3], ad + OPB);
            }
            uint32_t bh[8][2], bl[8][2];
#pragma unroll
            for (int np = 0; np < 4; np++) {
                const int r = wn * 64 + np * 16 + lrow;
                const uint32_t bd = sb + 2 * OPB + r * 80 + (ks + lkof) * 2;
                uint32_t t0, t1, t2, t3;
                ldm_x4(t0, t1, t2, t3, bd);
                bh[np * 2][0] = t0; bh[np * 2][1] = t2;
                bh[np * 2 + 1][0] = t1; bh[np * 2 + 1][1] = t3;
                ldm_x4(t0, t1, t2, t3, bd + OPB);
                bl[np * 2][0] = t0; bl[np * 2][1] = t2;
                bl[np * 2 + 1][0] = t1; bl[np * 2 + 1][1] = t3;
            }
#pragma unroll
            for (int mt = 0; mt < 2; mt++)
#pragma unroll
                for (int nt = 0; nt < 8; nt++)
                    mma16816(acc[mt][nt], ah[mt], bh[nt]);
#pragma unroll
            for (int mt = 0; mt < 2; mt++)
#pragma unroll
                for (int nt = 0; nt < 8; nt++)
                    mma16816(acc[mt][nt], ah[mt], bl[nt]);
#pragma unroll
            for (int mt = 0; mt < 2; mt++)
#pragma unroll
                for (int nt = 0; nt < 8; nt++)
                    mma16816(acc[mt][nt], al[mt], bh[nt]);
        }
        __syncthreads();
    }

    const int qr = lane >> 2;
    const int qc = (lane & 3) * 2;
#pragma unroll
    for (int mt = 0; mt < 2; mt++) {
#pragma unroll
        for (int nt = 0; nt < 8; nt++) {
            const int col = n0 + wn * 64 + nt * 8 + qc;
            const float2 bv = *(const float2*)(bias + col);
#pragma unroll
            for (int half = 0; half < 2; half++) {
                const int row = m0 + wm * 32 + mt * 16 + qr + half * 8;
                float ox = acc[mt][nt][half * 2 + 0] + bv.x;
                float oy = acc[mt][nt][half * 2 + 1] + bv.y;
                uint32_t hi, lo;
                split2(ox, oy, hi, lo);
                *(uint32_t*)(Ch + (size_t)row * DD + col) = hi;
                *(uint32_t*)(Cl + (size_t)row * DD + col) = lo;
            }
        }
    }
}

// ---------------------------------------------------------------------------
// Output projection: CTA 64x128, 128 threads, 3 CTAs/SM (R13 config).
// ---------------------------------------------------------------------------
#define OPA64 (64 * LDSP * 2)
#define STAGE64 (2 * OPA64 + 2 * OPB)
#define MMG64_SMEM (2 * STAGE64)

__global__ __launch_bounds__(128, 3) void mma_gemm64_kernel(
    const __nv_bfloat16* __restrict__ Ah, const __nv_bfloat16* __restrict__ Al,
    const __nv_bfloat16* __restrict__ Bh, const __nv_bfloat16* __restrict__ Bl,
    const float* __restrict__ bias, const float* __restrict__ resid,
    float* __restrict__ C)
{
    const uint32_t smb = smem_u32(mm_sm);
    const int tid  = threadIdx.x;
    const int wid  = tid >> 5;
    const int lane = tid & 31;
    const int wm   = wid & 1;
    const int wn   = wid >> 1;
    const int m0 = blockIdx.y * 64, n0 = blockIdx.x * 128;

    const char* srcA[2] = {(const char*)(Ah + (size_t)m0 * DD),
                           (const char*)(Al + (size_t)m0 * DD)};
    const char* srcB[2] = {(const char*)(Bh + (size_t)n0 * DD),
                           (const char*)(Bl + (size_t)n0 * DD)};

    int l_isA[12], l_op[12], l_row[12], l_seg[12];
#pragma unroll
    for (int i = 0; i < 12; i++) {
        const int idx = tid + i * 128;
        if (idx < 512) {
            l_isA[i] = 1;
            l_op[i]  = idx >> 8;
            l_row[i] = (idx >> 2) & 63;
            l_seg[i] = idx & 3;
        } else {
            const int j = idx - 512;
            l_isA[i] = 0;
            l_op[i]  = j >> 9;
            l_row[i] = (j >> 2) & 127;
            l_seg[i] = j & 3;
        }
    }

    float acc[2][8][4];
#pragma unroll
    for (int mt = 0; mt < 2; mt++)
#pragma unroll
        for (int nt = 0; nt < 8; nt++)
#pragma unroll
            for (int r = 0; r < 4; r++) acc[mt][nt][r] = 0.f;

    const int lrow = lane & 15;
    const int lkof = (lane >> 4) * 8;

#pragma unroll
    for (int i = 0; i < 12; i++) {
        const uint32_t dst = smb +
            (l_isA[i] ? (l_op[i] * OPA64) : (2 * OPA64 + l_op[i] * OPB)) +
            l_row[i] * 80 + l_seg[i] * 16;
        const char* src = (l_isA[i] ? srcA[l_op[i]] : srcB[l_op[i]]) +
                          (size_t)l_row[i] * 1024 + l_seg[i] * 16;
        CP_ASYNC16(dst, src);
    }
    CP_COMMIT();

    for (int c = 0; c < 16; c++) {
        if (c + 1 < 16) {
            const uint32_t sb = smb + ((c + 1) & 1) * STAGE64;
            const int koff = (c + 1) * 64;
#pragma unroll
            for (int i = 0; i < 12; i++) {
                const uint32_t dst = sb +
                    (l_isA[i] ? (l_op[i] * OPA64) : (2 * OPA64 + l_op[i] * OPB)) +
                    l_row[i] * 80 + l_seg[i] * 16;
                const char* src = (l_isA[i] ? srcA[l_op[i]] : srcB[l_op[i]]) +
                                  (size_t)l_row[i] * 1024 + koff + l_seg[i] * 16;
                CP_ASYNC16(dst, src);
            }
            CP_COMMIT();
            CP_WAIT1();
        } else {
            CP_WAIT0();
        }
        __syncthreads();

        const uint32_t sb = smb + (c & 1) * STAGE64;
#pragma unroll
        for (int ks = 0; ks < 32; ks += 16) {
            uint32_t ah[2][4], al[2][4];
#pragma unroll
            for (int mt = 0; mt < 2; mt++) {
                const int r = wm * 32 + mt * 16 + lrow;
                const uint32_t ad = sb + r * 80 + (ks + lkof) * 2;
                ldm_x4(ah[mt][0], ah[mt][1], ah[mt][2], ah[mt][3], ad);
                ldm_x4(al[mt][0], al[mt][1], al[mt][2], al[mt][3], ad + OPA64);
            }
            uint32_t bh[8][2], bl[8][2];
#pragma unroll
            for (int np = 0; np < 4; np++) {
                const int r = wn * 64 + np * 16 + lrow;
                const uint32_t bd = sb + 2 * OPA64 + r * 80 + (ks + lkof) * 2;
                uint32_t t0, t1, t2, t3;
                ldm_x4(t0, t1, t2, t3, bd);
                bh[np * 2][0] = t0; bh[np * 2][1] = t2;
                bh[np * 2 + 1][0] = t1; bh[np * 2 + 1][1] = t3;
                ldm_x4(t0, t1, t2, t3, bd + OPB);
                bl[np * 2][0] = t0; bl[np * 2][1] = t2;
                bl[np * 2 + 1][0] = t1; bl[np * 2 + 1][1] = t3;
            }
#pragma unroll
            for (int mt = 0; mt < 2; mt++)
#pragma unroll
                for (int nt = 0; nt < 8; nt++)
                    mma16816(acc[mt][nt], ah[mt], bh[nt]);
#pragma unroll
            for (int mt = 0; mt < 2; mt++)
#pragma unroll
                for (int nt = 0; nt < 8; nt++)
                    mma16816(acc[mt][nt], ah[mt], bl[nt]);
#pragma unroll
            for (int mt = 0; mt < 2; mt++)
#pragma unroll
                for (int nt = 0; nt < 8; nt++)
                    mma16816(acc[mt][nt], al[mt], bh[nt]);
        }
        __syncthreads();
    }

    const int qr = lane >> 2;
    const int qc = (lane & 3) * 2;
#pragma unroll
    for (int mt = 0; mt < 2; mt++) {
#pragma unroll
        for (int nt = 0; nt < 8; nt++) {
            const int col = n0 + wn * 64 + nt * 8 + qc;
            const float2 bv = *(const float2*)(bias + col);
#pragma unroll
            for (int half = 0; half < 2; half++) {
                const int row = m0 + wm * 32 + mt * 16 + qr + half * 8;
                const float2 rv = *(const float2*)(resid + (size_t)row * DD + col);
                float2 o;
                o.x = acc[mt][nt][half * 2 + 0] + bv.x + rv.x;
                o.y = acc[mt][nt][half * 2 + 1] + bv.y + rv.y;
                *(float2*)(C + (size_t)row * DD + col) = o;
            }
        }
    }
}

// ---------------------------------------------------------------------------
// Tensor-core dual-score causal flash attention.
// s2 uses bf16x2 via full-Rq x Rk_hi (Rkl dropped from smem: 5-op stages).
// Stage ops: 0=Kph 1=Kpl 2=Krh 3=Vh 4=Vl.
// ---------------------------------------------------------------------------
#define ATS   144
#define QOP   9216
#define KOP   4608
#define STG   (5 * KOP)                 // 23040
#define AT_SMEM (2 * QOP + 2 * STG)     // 64512

extern __shared__ char at_sm[];

__device__ __forceinline__ void at_load_tile32(
    uint32_t smb, int buf, int tid, int b, int kt0, int hc,
    const __nv_bfloat16* Kh, const __nv_bfloat16* Kl,
    const __nv_bfloat16* Rkh,
    const __nv_bfloat16* Vh, const __nv_bfloat16* Vl)
{
    const char* srcs[5] = {(const char*)Kh, (const char*)Kl, (const char*)Rkh,
                           (const char*)Vh, (const char*)Vl};
    const uint32_t base = smb + 2 * QOP + buf * STG;
#pragma unroll
    for (int i = 0; i < 10; i++) {
        const int idx = tid + i * 128;
        const int op = idx >> 8, r = (idx >> 3) & 31, seg = idx & 7;
        CP_ASYNC16(base + op * KOP + r * ATS + seg * 16,
                   srcs[op] + ((size_t)(b * SS + kt0 + r) * DD + hc) * 2 + seg * 16);
    }
}

__global__ __launch_bounds__(128, 3) void attn_mma_kernel(
    const __nv_bfloat16* __restrict__ Qh, const __nv_bfloat16* __restrict__ Ql,
    const __nv_bfloat16* __restrict__ Kh, const __nv_bfloat16* __restrict__ Kl,
    const __nv_bfloat16* __restrict__ Vh, const __nv_bfloat16* __restrict__ Vl,
    const __nv_bfloat16* __restrict__ Rqh, const __nv_bfloat16* __restrict__ Rql,
    const __nv_bfloat16* __restrict__ Rkh,
    const unsigned long long* __restrict__ mbits, const float* __restrict__ gammas,
    __nv_bfloat16* __restrict__ Oh, __nv_bfloat16* __restrict__ Ol)
{
    const uint32_t smb = smem_u32(at_sm);
    const int tid = threadIdx.x, lane = tid & 31, w = tid >> 5;
    const int bh = blockIdx.x & 63;
    const int q0 = (15 - (blockIdx.x >> 6)) * 64;
    const int b  = bh >> 3, h = bh & 7;
    const int hc = h * DKK;

    float g  = gammas[h];
    float sp = (g > 20.f) ? g : log1pf(__expf(g));
    float te = __expf(-sp);
    te = fminf(fmaxf(te, 1e-5f), 1e5f);
    const float f1 = 0.125f;
    const float f2 = te * rsqrtf((float)DD);
    const float f2f1 = f2 * 8.0f;

    const int qcb = (lane & 3) * 2;
    const int gg = lane >> 3, l8 = lane & 7;
    const int mrw = w * 16 + ((gg & 1) << 3) + l8;
    const int r1 = q0 + w * 16 + (lane >> 2);
    const int r2 = r1 + 8;

    // stage 4 Q ops: raw (Rqh,Rql) -> persistent [0, 2*QOP); proj -> temp
    {
        const char* qsrc[4] = {(const char*)Qh, (const char*)Ql,
                               (const char*)Rqh, (const char*)Rql};
#pragma unroll
        for (int i = 0; i < 16; i++) {
            const int idx = tid + i * 128;
            const int op = idx >> 9, r = (idx >> 3) & 63, seg = idx & 7;
            const uint32_t base = (op < 2) ? (smb + 2 * QOP + op * QOP)
                                           : (smb + (op - 2) * QOP);
            CP_ASYNC16(base + r * ATS + seg * 16,
                       qsrc[op] + ((size_t)(b * SS + q0 + r) * DD + hc) * 2 + seg * 16);
        }
        CP_COMMIT(); CP_WAIT0();
        __syncthreads();
    }
    uint32_t qph[4][4], qpl[4][4];
#pragma unroll
    for (int ks = 0; ks < 4; ks++) {
        const uint32_t qa = smb + 2 * QOP + mrw * ATS +
                            (ks * 16 + ((gg >> 1) << 3)) * 2;
        ldm_x4(qph[ks][0], qph[ks][1], qph[ks][2], qph[ks][3], qa);
        ldm_x4(qpl[ks][0], qpl[ks][1], qpl[ks][2], qpl[ks][3], qa + QOP);
    }
    __syncthreads();

    float oacc[8][4];
#pragma unroll
    for (int nt = 0; nt < 8; nt++)
#pragma unroll
        for (int e = 0; e < 4; e++) oacc[nt][e] = 0.f;
    float mrow[2] = {-1e30f, -1e30f};
    float lsum[2] = {0.f, 0.f};

    const int T = q0 / 32 + 2;

    at_load_tile32(smb, 0, tid, b, 0, hc, Kh, Kl, Rkh, Vh, Vl);
    CP_COMMIT();

    for (int t = 0; t < T; t++) {
        const int kt0 = t * 32;
        const unsigned long long mw1 =
            mbits[(size_t)(b * SS + r1) * 16 + (kt0 >> 6)];
        const unsigned long long mw2 =
            mbits[(size_t)(b * SS + r2) * 16 + (kt0 >> 6)];
        if (t + 1 < T) {
            at_load_tile32(smb, (t + 1) & 1, tid, b, kt0 + 32, hc, Kh, Kl, Rkh, Vh, Vl);
            CP_COMMIT(); CP_WAIT1();
        } else {
            CP_WAIT0();
        }
        __syncthreads();

        const uint32_t sb = smb + 2 * QOP + (t & 1) * STG;

        float sc[4][4];
#pragma unroll
        for (int nt = 0; nt < 4; nt++)
#pragma unroll
            for (int e = 0; e < 4; e++) sc[nt][e] = 0.f;

        // ---- s2: raw scores (bf16x2: (Rqh+Rql) x Rkh) ----
#pragma unroll
        for (int ks = 0; ks < 4; ks++) {
            uint32_t qh4[4], ql4[4];
            const uint32_t qa = smb + mrw * ATS + (ks * 16 + ((gg >> 1) << 3)) * 2;
            ldm_x4(qh4[0], qh4[1], qh4[2], qh4[3], qa);
            ldm_x4(ql4[0], ql4[1], ql4[2], ql4[3], qa + QOP);
            uint32_t bh2[4][2];
#pragma unroll
            for (int np = 0; np < 2; np++) {
                const uint32_t ad = sb + 2 * KOP +
                    (np * 16 + ((gg >> 1) << 3) + l8) * ATS +
                    (ks * 16 + ((gg & 1) << 3)) * 2;
                uint32_t t0, t1, t2, t3;
                ldm_x4(t0, t1, t2, t3, ad);
                bh2[np*2][0] = t0; bh2[np*2][1] = t1;
                bh2[np*2+1][0] = t2; bh2[np*2+1][1] = t3;
            }
#pragma unroll
            for (int nt = 0; nt < 4; nt++)
                mma16816(sc[nt], qh4, bh2[nt]);
#pragma unroll
            for (int nt = 0; nt < 4; nt++)
                mma16816(sc[nt], ql4, bh2[nt]);
        }

        // ---- gate s2 by packed mask ----
        const int msh = kt0 & 32;
#pragma unroll
        for (int nt = 0; nt < 4; nt++) {
            const int j0 = msh + nt * 8 + qcb;
            sc[nt][0] = ((mw1 >> j0) & 1)       ? sc[nt][0] * f2f1 : 0.f;
            sc[nt][1] = ((mw1 >> (j0 + 1)) & 1) ? sc[nt][1] * f2f1 : 0.f;
            sc[nt][2] = ((mw2 >> j0) & 1)       ? sc[nt][2] * f2f1 : 0.f;
            sc[nt][3] = ((mw2 >> (j0 + 1)) & 1) ? sc[nt][3] * f2f1 : 0.f;
        }

        // ---- s1: projected scores (bf16x3) ----
#pragma unroll
        for (int ks = 0; ks < 4; ks++) {
            uint32_t bh2[4][2], bl2[4][2];
#pragma unroll
            for (int np = 0; np < 2; np++) {
                const uint32_t ad = sb +
                    (np * 16 + ((gg >> 1) << 3) + l8) * ATS +
                    (ks * 16 + ((gg & 1) << 3)) * 2;
                uint32_t t0, t1, t2, t3;
                ldm_x4(t0, t1, t2, t3, ad);
                bh2[np*2][0] = t0; bh2[np*2][1] = t1;
                bh2[np*2+1][0] = t2; bh2[np*2+1][1] = t3;
                ldm_x4(t0, t1, t2, t3, ad + KOP);
                bl2[np*2][0] = t0; bl2[np*2][1] = t1;
                bl2[np*2+1][0] = t2; bl2[np*2+1][1] = t3;
            }
#pragma unroll
            for (int nt = 0; nt < 4; nt++)
                mma16816(sc[nt], qph[ks], bh2[nt]);
#pragma unroll
            for (int nt = 0; nt < 4; nt++)
                mma16816(sc[nt], qph[ks], bl2[nt]);
#pragma unroll
            for (int nt = 0; nt < 4; nt++)
                mma16816(sc[nt], qpl[ks], bh2[nt]);
        }

        // ---- causal mask + final scale ----
#pragma unroll
        for (int nt = 0; nt < 4; nt++) {
            const int gj0 = kt0 + nt * 8 + qcb;
            sc[nt][0] = (gj0     < r1) ? sc[nt][0] * f1 : -INFINITY;
            sc[nt][1] = (gj0 + 1 < r1) ? sc[nt][1] * f1 : -INFINITY;
            sc[nt][2] = (gj0     < r2) ? sc[nt][2] * f1 : -INFINITY;
            sc[nt][3] = (gj0 + 1 < r2) ? sc[nt][3] * f1 : -INFINITY;
        }

        // ---- online softmax ----
        float rm1 = -INFINITY, rm2 = -INFINITY;
#pragma unroll
        for (int nt = 0; nt < 4; nt++) {
            rm1 = fmaxf(rm1, fmaxf(sc[nt][0], sc[nt][1]));
            rm2 = fmaxf(rm2, fmaxf(sc[nt][2], sc[nt][3]));
        }
        rm1 = fmaxf(rm1, __shfl_xor_sync(0xffffffffu, rm1, 1));
        rm1 = fmaxf(rm1, __shfl_xor_sync(0xffffffffu, rm1, 2));
        rm2 = fmaxf(rm2, __shfl_xor_sync(0xffffffffu, rm2, 1));
        rm2 = fmaxf(rm2, __shfl_xor_sync(0xffffffffu, rm2, 2));
        const float mn1 = fmaxf(mrow[0], rm1);
        const float mn2 = fmaxf(mrow[1], rm2);
        const float scl1 = __expf(mrow[0] - mn1);
        const float scl2 = __expf(mrow[1] - mn2);
        mrow[0] = mn1; mrow[1] = mn2;

        float ps1 = 0.f, ps2 = 0.f;
#pragma unroll
        for (int nt = 0; nt < 4; nt++) {
            sc[nt][0] = __expf(sc[nt][0] - mn1);
            sc[nt][1] = __expf(sc[nt][1] - mn1);
            sc[nt][2] = __expf(sc[nt][2] - mn2);
            sc[nt][3] = __expf(sc[nt][3] - mn2);
            ps1 += sc[nt][0] + sc[nt][1];
            ps2 += sc[nt][2] + sc[nt][3];
        }
        ps1 += __shfl_xor_sync(0xffffffffu, ps1, 1);
        ps1 += __shfl_xor_sync(0xffffffffu, ps1, 2);
        ps2 += __shfl_xor_sync(0xffffffffu, ps2, 1);
        ps2 += __shfl_xor_sync(0xffffffffu, ps2, 2);
        lsum[0] = lsum[0] * scl1 + ps1;
        lsum[1] = lsum[1] * scl2 + ps2;

#pragma unroll
        for (int nt = 0; nt < 8; nt++) {
            oacc[nt][0] *= scl1; oacc[nt][1] *= scl1;
            oacc[nt][2] *= scl2; oacc[nt][3] *= scl2;
        }

        uint32_t pha[2][4], pla[2][4];
#pragma unroll
        for (int j = 0; j < 2; j++) {
            split2(sc[2*j][0],   sc[2*j][1],   pha[j][0], pla[j][0]);
            split2(sc[2*j][2],   sc[2*j][3],   pha[j][1], pla[j][1]);
            split2(sc[2*j+1][0], sc[2*j+1][1], pha[j][2], pla[j][2]);
            split2(sc[2*j+1][2], sc[2*j+1][3], pha[j][3], pla[j][3]);
        }

        // ---- PV (bf16x3); V hi at op3, lo at op4 ----
#pragma unroll
        for (int j = 0; j < 2; j++) {
            uint32_t vh2[8][2], vl2[8][2];
#pragma unroll
            for (int np = 0; np < 4; np++) {
                const uint32_t ad = sb + 3 * KOP +
                    (j * 16 + ((gg & 1) << 3) + l8) * ATS +
                    (np * 16 + ((gg >> 1) << 3)) * 2;
                uint32_t t0, t1, t2, t3;
                ldm_x4t(t0, t1, t2, t3, ad);
                vh2[np*2][0] = t0; vh2[np*2][1] = t1;
                vh2[np*2+1][0] = t2; vh2[np*2+1][1] = t3;
                ldm_x4t(t0, t1, t2, t3, ad + KOP);
                vl2[np*2][0] = t0; vl2[np*2][1] = t1;
                vl2[np*2+1][0] = t2; vl2[np*2+1][1] = t3;
            }
#pragma unroll
            for (int nt = 0; nt < 8; nt++)
                mma16816(oacc[nt], pha[j], vh2[nt]);
#pragma unroll
            for (int nt = 0; nt < 8; nt++)
                mma16816(oacc[nt], pha[j], vl2[nt]);
#pragma unroll
            for (int nt = 0; nt < 8; nt++)
                mma16816(oacc[nt], pla[j], vh2[nt]);
        }
        __syncthreads();
    }

    const float rr1 = (lsum[0] > 0.f) ? (1.f / lsum[0]) : 0.f;
    const float rr2 = (lsum[1] > 0.f) ? (1.f / lsum[1]) : 0.f;
    const size_t base1 = (size_t)(b * SS + r1) * DD + hc;
    const size_t base2 = (size_t)(b * SS + r2) * DD + hc;
#pragma unroll
    for (int nt = 0; nt < 8; nt++) {
        const int co = nt * 8 + qcb;
        uint32_t hi, lo;
        split2(oacc[nt][0] * rr1, oacc[nt][1] * rr1, hi, lo);
        *(uint32_t*)(Oh + base1 + co) = hi;
        *(uint32_t*)(Ol + base1 + co) = lo;
        split2(oacc[nt][2] * rr2, oacc[nt][3] * rr2, hi, lo);
        *(uint32_t*)(Oh + base2 + co) = hi;
        *(uint32_t*)(Ol + base2 + co) = lo;
    }
}

// ---------------------------------------------------------------------------
// In-place LayerNorm: one warp per row of 512 floats.
// ---------------------------------------------------------------------------
__global__ __launch_bounds__(256) void ln_kernel(
    float* __restrict__ X, const float* __restrict__ gam, const float* __restrict__ bet)
{
    const int warp = threadIdx.x >> 5, lane = threadIdx.x & 31;
    const size_t row = (size_t)blockIdx.x * 8 + warp;
    float* xr = X + row * DD;

    float4 v[4];
    float s = 0.f, s2 = 0.f;
#pragma unroll
    for (int w = 0; w < 4; w++) {
        v[w] = *(const float4*)(xr + w * 128 + lane * 4);
        s  += v[w].x + v[w].y + v[w].z + v[w].w;
        s2 += v[w].x * v[w].x + v[w].y * v[w].y + v[w].z * v[w].z + v[w].w * v[w].w;
    }
#pragma unroll
    for (int o = 16; o > 0; o >>= 1) {
        s  += __shfl_xor_sync(0xffffffffu, s,  o);
        s2 += __shfl_xor_sync(0xffffffffu, s2, o);
    }
    const float mu  = s * (1.f / DD);
    const float var = s2 * (1.f / DD) - mu * mu;
    const float inv = rsqrtf(var + 1e-5f);
#pragma unroll
    for (int w = 0; w < 4; w++) {
        const int c = w * 128 + lane * 4;
        float4 gv = *(const float4*)(gam + c);
        float4 bv = *(const float4*)(bet + c);
        float4 o;
        o.x = (v[w].x - mu) * inv * gv.x + bv.x;
        o.y = (v[w].y - mu) * inv * gv.y + bv.y;
        o.z = (v[w].z - mu) * inv * gv.z + bv.z;
        o.w = (v[w].w - mu) * inv * gv.w + bv.w;
        *(float4*)(xr + c) = o;
    }
}

// ---------------------------------------------------------------------------
extern "C" void kernel_launch(void* const* d_in, const int* in_sizes, int n_in,
                              void* d_out, int out_size)
{
    const float* q_in  = (const float*)d_in[0];
    const float* k_in  = (const float*)d_in[1];
    const float* v_in  = (const float*)d_in[2];
    const int*   smask = (const int*)  d_in[3];
    const float* Wq    = (const float*)d_in[4];
    const float* bq    = (const float*)d_in[5];
    const float* Wv    = (const float*)d_in[6];
    const float* bv    = (const float*)d_in[7];
    const float* Wo    = (const float*)d_in[8];
    const float* bo    = (const float*)d_in[9];
    const float* gam   = (const float*)d_in[10];
    const float* ln_g  = (const float*)d_in[11];
    const float* ln_b  = (const float*)d_in[12];
    float* out = (float*)d_out;

    __nv_bfloat16 *Xqh, *Xql, *Xkh, *Xkl, *Xvh, *Xvl;
    __nv_bfloat16 *Qh, *Ql, *Kh, *Kl, *Vh, *Vl, *Oh, *Ol;
    __nv_bfloat16 *Wqh, *Wql, *Wvh, *Wvl, *Woh, *Wol;
    unsigned long long* mbits;
    cudaGetSymbolAddress((void**)&Xqh, g_Xqh); cudaGetSymbolAddress((void**)&Xql, g_Xql);
    cudaGetSymbolAddress((void**)&Xkh, g_Xkh); cudaGetSymbolAddress((void**)&Xkl, g_Xkl);
    cudaGetSymbolAddress((void**)&Xvh, g_Xvh); cudaGetSymbolAddress((void**)&Xvl, g_Xvl);
    cudaGetSymbolAddress((void**)&Qh, g_Qh);   cudaGetSymbolAddress((void**)&Ql, g_Ql);
    cudaGetSymbolAddress((void**)&Kh, g_Kh);   cudaGetSymbolAddress((void**)&Kl, g_Kl);
    cudaGetSymbolAddress((void**)&Vh, g_Vh);   cudaGetSymbolAddress((void**)&Vl, g_Vl);
    cudaGetSymbolAddress((void**)&Oh, g_Oh);   cudaGetSymbolAddress((void**)&Ol, g_Ol);
    cudaGetSymbolAddress((void**)&Wqh, g_Wqh); cudaGetSymbolAddress((void**)&Wql, g_Wql);
    cudaGetSymbolAddress((void**)&Wvh, g_Wvh); cudaGetSymbolAddress((void**)&Wvl, g_Wvl);
    cudaGetSymbolAddress((void**)&Woh, g_Woh); cudaGetSymbolAddress((void**)&Wol, g_Wol);
    cudaGetSymbolAddress((void**)&mbits, g_mbits);

    cudaFuncSetAttribute(mma_gemm_kernel, cudaFuncAttributeMaxDynamicSharedMemorySize,
                         (int)MMG_SMEM);
    cudaFuncSetAttribute(mma_gemm64_kernel, cudaFuncAttributeMaxDynamicSharedMemorySize,
                         (int)MMG64_SMEM);
    cudaFuncSetAttribute(attn_mma_kernel, cudaFuncAttributeMaxDynamicSharedMemorySize,
                         (int)AT_SMEM);

    const dim3 gb(256);

    // fused prepasses
    prep_kernel<<<PREP_TOTAL_B, gb>>>(
        q_in, k_in, v_in, Xqh, Xql, Xkh, Xkl, Xvh, Xvl,
        Wq, Wv, Wo, Wqh, Wql, Wvh, Wvl, Woh, Wol,
        smask, mbits);

    // Q + K + V projections fused in one launch (grid.z = 3)
    const dim3 ggrid3(DD / 128, MM / 128, 3);
    mma_gemm_kernel<<<ggrid3, gb, MMG_SMEM>>>(
        Xqh, Xql, Xkh, Xkl, Xvh, Xvl,
        Wqh, Wql, Wvh, Wvl,
        bq, bv,
        Qh, Ql, Kh, Kl, Vh, Vl);

    // tensor-core attention: 1024 CTAs, heavy-first, 3 CTAs/SM
    attn_mma_kernel<<<1024, 128, AT_SMEM>>>(Qh, Ql, Kh, Kl, Vh, Vl,
                                            Xqh, Xql, Xkh, mbits, gam, Oh, Ol);

    // output projection + bias + residual -> fp32 out (64-row tiles, balanced)
    const dim3 ggrid64(DD / 128, MM / 64);
    mma_gemm64_kernel<<<ggrid64, 128, MMG64_SMEM>>>(
        Oh, Ol, Woh, Wol, bo, q_in, out);

    // in-place LayerNorm
    ln_kernel<<<MM / 8, gb>>>(out, ln_g, ln_b);
}

// round 16
// speedup vs baseline: 1.1363x; 1.0308x over previous
#include <cuda_runtime.h>
#include <cuda_bf16.h>
#include <math.h>
#include <cstdint>

// Problem constants
#define BB 8
#define SS 1024
#define DD 512
#define HH 8
#define DKK 64
#define MM (BB*SS)   // 8192 rows
#define NELEM ((size_t)MM * DD)

// ---------------- scratch (static __device__: allocation-guard safe) --------
__device__ __nv_bfloat16 g_Xqh[NELEM], g_Xql[NELEM];
__device__ __nv_bfloat16 g_Xkh[NELEM], g_Xkl[NELEM];
__device__ __nv_bfloat16 g_Xvh[NELEM], g_Xvl[NELEM];
__device__ __nv_bfloat16 g_Qh[NELEM], g_Ql[NELEM];
__device__ __nv_bfloat16 g_Kh[NELEM], g_Kl[NELEM];
__device__ __nv_bfloat16 g_Vh[NELEM], g_Vl[NELEM];
__device__ __nv_bfloat16 g_Oh[NELEM], g_Ol[NELEM];
__device__ __nv_bfloat16 g_Wqh[DD * DD], g_Wql[DD * DD];
__device__ __nv_bfloat16 g_Wvh[DD * DD], g_Wvl[DD * DD];
__device__ __nv_bfloat16 g_Woh[DD * DD], g_Wol[DD * DD];
__device__ unsigned long long g_mbits[(size_t)MM * 16];

// ---------------- PTX helpers (base sm_103-safe) -----------------------------
__device__ __forceinline__ uint32_t smem_u32(const void* p) {
    uint32_t a;
    asm("{ .reg .u64 t; cvta.to.shared.u64 t, %1; cvt.u32.u64 %0, t; }" : "=r"(a) : "l"(p));
    return a;
}
#define CP_ASYNC16(dst, src) \
    asm volatile("cp.async.cg.shared.global [%0], [%1], 16;" :: "r"(dst), "l"(src) : "memory")
#define CP_COMMIT() asm volatile("cp.async.commit_group;" ::: "memory")
#define CP_WAIT1()  asm volatile("cp.async.wait_group 1;" ::: "memory")
#define CP_WAIT0()  asm volatile("cp.async.wait_group 0;" ::: "memory")

__device__ __forceinline__ void ldm_x4(uint32_t& r0, uint32_t& r1, uint32_t& r2,
                                       uint32_t& r3, uint32_t addr) {
    asm volatile("ldmatrix.sync.aligned.m8n8.x4.shared.b16 {%0,%1,%2,%3}, [%4];"
                 : "=r"(r0), "=r"(r1), "=r"(r2), "=r"(r3) : "r"(addr));
}
__device__ __forceinline__ void ldm_x4t(uint32_t& r0, uint32_t& r1, uint32_t& r2,
                                        uint32_t& r3, uint32_t addr) {
    asm volatile("ldmatrix.sync.aligned.m8n8.x4.trans.shared.b16 {%0,%1,%2,%3}, [%4];"
                 : "=r"(r0), "=r"(r1), "=r"(r2), "=r"(r3) : "r"(addr));
}
__device__ __forceinline__ void mma16816(float* d, const uint32_t* a, const uint32_t* b) {
    asm volatile("mma.sync.aligned.m16n8k16.row.col.f32.bf16.bf16.f32 "
                 "{%0,%1,%2,%3}, {%4,%5,%6,%7}, {%8,%9}, {%0,%1,%2,%3};"
                 : "+f"(d[0]), "+f"(d[1]), "+f"(d[2]), "+f"(d[3])
                 : "r"(a[0]), "r"(a[1]), "r"(a[2]), "r"(a[3]), "r"(b[0]), "r"(b[1]));
}
__device__ __forceinline__ uint32_t pack_bf2(float a, float b) {
    __nv_bfloat162 t = __floats2bfloat162_rn(a, b);
    return *(uint32_t*)&t;
}
__device__ __forceinline__ void split2(float a, float b, uint32_t& hi, uint32_t& lo) {
    const __nv_bfloat16 ha = __float2bfloat16(a), hb = __float2bfloat16(b);
    const float ra = a - __bfloat162float(ha), rb = b - __bfloat162float(hb);
    __nv_bfloat162 th; th.x = ha; th.y = hb;
    hi = *(uint32_t*)&th;
    lo = pack_bf2(ra, rb);
}

// ---------------------------------------------------------------------------
// Fused prepass kernel: split3 + wsplit3 + triangle-only pack_mask.
// ---------------------------------------------------------------------------
#define PREP_SPLIT_B 12288
#define PREP_WSPL_B  768
#define PREP_MASK_B  16384
#define PREP_TOTAL_B (PREP_SPLIT_B + PREP_WSPL_B + PREP_MASK_B)

__global__ __launch_bounds__(256) void prep_kernel(
    const float* __restrict__ Xq, const float* __restrict__ Xk,
    const float* __restrict__ Xv,
    __nv_bfloat16* __restrict__ Xqh, __nv_bfloat16* __restrict__ Xql,
    __nv_bfloat16* __restrict__ Xkh, __nv_bfloat16* __restrict__ Xkl,
    __nv_bfloat16* __restrict__ Xvh, __nv_bfloat16* __restrict__ Xvl,
    const float* __restrict__ Wq, const float* __restrict__ Wv,
    const float* __restrict__ Wo,
    __nv_bfloat16* __restrict__ Wqh, __nv_bfloat16* __restrict__ Wql,
    __nv_bfloat16* __restrict__ Wvh, __nv_bfloat16* __restrict__ Wvl,
    __nv_bfloat16* __restrict__ Woh, __nv_bfloat16* __restrict__ Wol,
    const int* __restrict__ smask, unsigned long long* __restrict__ bits)
{
    __shared__ float tile[32][33];
    const int bid = blockIdx.x;
    const int tid = threadIdx.x;

    if (bid < PREP_SPLIT_B) {
        const int s = bid / 4096;
        const int blk = bid - s * 4096;
        const float* X = (s == 0) ? Xq : (s == 1) ? Xk : Xv;
        __nv_bfloat16* H = (s == 0) ? Xqh : (s == 1) ? Xkh : Xvh;
        __nv_bfloat16* L = (s == 0) ? Xql : (s == 1) ? Xkl : Xvl;
        const size_t i = ((size_t)blk * 256 + tid) * 4;
        float4 v = *(const float4*)(X + i);
        __nv_bfloat16 h[4], l[4];
        float x[4] = {v.x, v.y, v.z, v.w};
#pragma unroll
        for (int j = 0; j < 4; j++) {
            h[j] = __float2bfloat16(x[j]);
            l[j] = __float2bfloat16(x[j] - __bfloat162float(h[j]));
        }
        *(uint2*)(H + i) = *(uint2*)h;
        *(uint2*)(L + i) = *(uint2*)l;
    } else if (bid < PREP_SPLIT_B + PREP_WSPL_B) {
        const int w = bid - PREP_SPLIT_B;
        const int s = w / 256;
        const int rem = w - s * 256;
        const int bx = rem & 15, by = rem >> 4;
        const float* W = (s == 0) ? Wq : (s == 1) ? Wv : Wo;
        __nv_bfloat16* Ht = (s == 0) ? Wqh : (s == 1) ? Wvh : Woh;
        __nv_bfloat16* Lt = (s == 0) ? Wql : (s == 1) ? Wvl : Wol;
        const int tx = tid & 31, ty = tid >> 5;
        const int k0 = by * 32, n0 = bx * 32;
#pragma unroll
        for (int r = 0; r < 4; r++)
            tile[ty * 4 + r][tx] = W[(size_t)(k0 + ty * 4 + r) * DD + n0 + tx];
        __syncthreads();
#pragma unroll
        for (int r = 0; r < 4; r++) {
            const int n = n0 + ty * 4 + r;
            const float x = tile[tx][ty * 4 + r];
            const __nv_bfloat16 h = __float2bfloat16(x);
            Ht[(size_t)n * DD + k0 + tx] = h;
            Lt[(size_t)n * DD + k0 + tx] = __float2bfloat16(x - __bfloat162float(h));
        }
    } else {
        const int pb = bid - PREP_SPLIT_B - PREP_WSPL_B;
        const int gw = pb * 8 + (tid >> 5);
        const int lane = tid & 31;
        const int word = gw & 15;
        const int row  = gw >> 4;
        const int srow = row & (SS - 1);
        if (word * 64 < srow) {
            const int* p = smask + (size_t)row * SS + word * 64;
            const unsigned lo = __ballot_sync(0xffffffffu, p[lane] != 0);
            const unsigned hi = __ballot_sync(0xffffffffu, p[lane + 32] != 0);
            if (lane == 0)
                bits[(size_t)row * 16 + word] = ((unsigned long long)hi << 32) | lo;
        }
    }
}

// ---------------------------------------------------------------------------
// mma.sync bf16x3 GEMM (256 threads, CTA 128x128, warp tile 32x64), K-chunk 32,
// cp.async double buffer. grid.z selects operand set (fused QKV projections).
// ---------------------------------------------------------------------------
#define LDSP 40
#define OPB  (128 * LDSP * 2)
#define STAGE_B (4 * OPB)
#define MMG_SMEM (2 * STAGE_B)

extern __shared__ char mm_sm[];

__global__ __launch_bounds__(256) void mma_gemm_kernel(
    const __nv_bfloat16* __restrict__ Ah0, const __nv_bfloat16* __restrict__ Al0,
    const __nv_bfloat16* __restrict__ Ah1, const __nv_bfloat16* __restrict__ Al1,
    const __nv_bfloat16* __restrict__ Ah2, const __nv_bfloat16* __restrict__ Al2,
    const __nv_bfloat16* __restrict__ Bh0, const __nv_bfloat16* __restrict__ Bl0,
    const __nv_bfloat16* __restrict__ Bh1, const __nv_bfloat16* __restrict__ Bl1,
    const float* __restrict__ bias0, const float* __restrict__ bias1,
    __nv_bfloat16* __restrict__ Ch0, __nv_bfloat16* __restrict__ Cl0,
    __nv_bfloat16* __restrict__ Ch1, __nv_bfloat16* __restrict__ Cl1,
    __nv_bfloat16* __restrict__ Ch2, __nv_bfloat16* __restrict__ Cl2)
{
    const uint32_t smb = smem_u32(mm_sm);
    const int tid  = threadIdx.x;
    const int wid  = tid >> 5;
    const int lane = tid & 31;
    const int wm   = wid & 3;
    const int wn   = wid >> 2;
    const int m0 = blockIdx.y * 128, n0 = blockIdx.x * 128;
    const int z = blockIdx.z;
    const __nv_bfloat16* Ah = (z == 0) ? Ah0 : (z == 1) ? Ah1 : Ah2;
    const __nv_bfloat16* Al = (z == 0) ? Al0 : (z == 1) ? Al1 : Al2;
    const __nv_bfloat16* Bh = (z == 2) ? Bh1 : Bh0;
    const __nv_bfloat16* Bl = (z == 2) ? Bl1 : Bl0;
    const float* bias = (z == 2) ? bias1 : bias0;
    __nv_bfloat16* Ch = (z == 0) ? Ch0 : (z == 1) ? Ch1 : Ch2;
    __nv_bfloat16* Cl = (z == 0) ? Cl0 : (z == 1) ? Cl1 : Cl2;

    const char* srcs[4] = {
        (const char*)(Ah + (size_t)m0 * DD),
        (const char*)(Al + (size_t)m0 * DD),
        (const char*)(Bh + (size_t)n0 * DD),
        (const char*)(Bl + (size_t)n0 * DD)
    };

    int l_op[8], l_row[8], l_seg[8];
#pragma unroll
    for (int i = 0; i < 8; i++) {
        const int idx = tid + i * 256;
        l_op[i]  = idx >> 9;
        l_row[i] = (idx & 511) >> 2;
        l_seg[i] = idx & 3;
    }

    float acc[2][8][4];
#pragma unroll
    for (int mt = 0; mt < 2; mt++)
#pragma unroll
        for (int nt = 0; nt < 8; nt++)
#pragma unroll
            for (int r = 0; r < 4; r++) acc[mt][nt][r] = 0.f;

    const int lrow = lane & 15;
    const int lkof = (lane >> 4) * 8;

#pragma unroll
    for (int i = 0; i < 8; i++) {
        CP_ASYNC16(smb + l_op[i] * OPB + l_row[i] * 80 + l_seg[i] * 16,
                   srcs[l_op[i]] + (size_t)l_row[i] * 1024 + l_seg[i] * 16);
    }
    CP_COMMIT();

    for (int c = 0; c < 16; c++) {
        if (c + 1 < 16) {
            const uint32_t sb = smb + ((c + 1) & 1) * STAGE_B;
            const int koff = (c + 1) * 64;
#pragma unroll
            for (int i = 0; i < 8; i++) {
                CP_ASYNC16(sb + l_op[i] * OPB + l_row[i] * 80 + l_seg[i] * 16,
                           srcs[l_op[i]] + (size_t)l_row[i] * 1024 + koff + l_seg[i] * 16);
            }
            CP_COMMIT();
            CP_WAIT1();
        } else {
            CP_WAIT0();
        }
        __syncthreads();

        const uint32_t sb = smb + (c & 1) * STAGE_B;
#pragma unroll
        for (int ks = 0; ks < 32; ks += 16) {
            uint32_t ah[2][4], al[2][4];
#pragma unroll
            for (int mt = 0; mt < 2; mt++) {
                const int r = wm * 32 + mt * 16 + lrow;
                const uint32_t ad = sb + r * 80 + (ks + lkof) * 2;
                ldm_x4(ah[mt][0], ah[mt][1], ah[mt][2], ah[mt][3], ad);
                ldm_x4(al[mt][0], al[mt][1], al[mt][2], al[mt][3], ad + OPB);
            }
            uint32_t bh[8][2], bl[8][2];
#pragma unroll
            for (int np = 0; np < 4; np++) {
                const int r = wn * 64 + np * 16 + lrow;
                const uint32_t bd = sb + 2 * OPB + r * 80 + (ks + lkof) * 2;
                uint32_t t0, t1, t2, t3;
                ldm_x4(t0, t1, t2, t3, bd);
                bh[np * 2][0] = t0; bh[np * 2][1] = t2;
                bh[np * 2 + 1][0] = t1; bh[np * 2 + 1][1] = t3;
                ldm_x4(t0, t1, t2, t3, bd + OPB);
                bl[np * 2][0] = t0; bl[np * 2][1] = t2;
                bl[np * 2 + 1][0] = t1; bl[np * 2 + 1][1] = t3;
            }
#pragma unroll
            for (int mt = 0; mt < 2; mt++)
#pragma unroll
                for (int nt = 0; nt < 8; nt++)
                    mma16816(acc[mt][nt], ah[mt], bh[nt]);
#pragma unroll
            for (int mt = 0; mt < 2; mt++)
#pragma unroll
                for (int nt = 0; nt < 8; nt++)
                    mma16816(acc[mt][nt], ah[mt], bl[nt]);
#pragma unroll
            for (int mt = 0; mt < 2; mt++)
#pragma unroll
                for (int nt = 0; nt < 8; nt++)
                    mma16816(acc[mt][nt], al[mt], bh[nt]);
        }
        __syncthreads();
    }

    const int qr = lane >> 2;
    const int qc = (lane & 3) * 2;
#pragma unroll
    for (int mt = 0; mt < 2; mt++) {
#pragma unroll
        for (int nt = 0; nt < 8; nt++) {
            const int col = n0 + wn * 64 + nt * 8 + qc;
            const float2 bv = *(const float2*)(bias + col);
#pragma unroll
            for (int half = 0; half < 2; half++) {
                const int row = m0 + wm * 32 + mt * 16 + qr + half * 8;
                float ox = acc[mt][nt][half * 2 + 0] + bv.x;
                float oy = acc[mt][nt][half * 2 + 1] + bv.y;
                uint32_t hi, lo;
                split2(ox, oy, hi, lo);
                *(uint32_t*)(Ch + (size_t)row * DD + col) = hi;
                *(uint32_t*)(Cl + (size_t)row * DD + col) = lo;
            }
        }
    }
}

// ---------------------------------------------------------------------------
// Output projection: CTA 64x128, 128 threads, 3 CTAs/SM.
// ---------------------------------------------------------------------------
#define OPA64 (64 * LDSP * 2)
#define STAGE64 (2 * OPA64 + 2 * OPB)
#define MMG64_SMEM (2 * STAGE64)

__global__ __launch_bounds__(128, 3) void mma_gemm64_kernel(
    const __nv_bfloat16* __restrict__ Ah, const __nv_bfloat16* __restrict__ Al,
    const __nv_bfloat16* __restrict__ Bh, const __nv_bfloat16* __restrict__ Bl,
    const float* __restrict__ bias, const float* __restrict__ resid,
    float* __restrict__ C)
{
    const uint32_t smb = smem_u32(mm_sm);
    const int tid  = threadIdx.x;
    const int wid  = tid >> 5;
    const int lane = tid & 31;
    const int wm   = wid & 1;
    const int wn   = wid >> 1;
    const int m0 = blockIdx.y * 64, n0 = blockIdx.x * 128;

    const char* srcA[2] = {(const char*)(Ah + (size_t)m0 * DD),
                           (const char*)(Al + (size_t)m0 * DD)};
    const char* srcB[2] = {(const char*)(Bh + (size_t)n0 * DD),
                           (const char*)(Bl + (size_t)n0 * DD)};

    int l_isA[12], l_op[12], l_row[12], l_seg[12];
#pragma unroll
    for (int i = 0; i < 12; i++) {
        const int idx = tid + i * 128;
        if (idx < 512) {
            l_isA[i] = 1;
            l_op[i]  = idx >> 8;
            l_row[i] = (idx >> 2) & 63;
            l_seg[i] = idx & 3;
        } else {
            const int j = idx - 512;
            l_isA[i] = 0;
            l_op[i]  = j >> 9;
            l_row[i] = (j >> 2) & 127;
            l_seg[i] = j & 3;
        }
    }

    float acc[2][8][4];
#pragma unroll
    for (int mt = 0; mt < 2; mt++)
#pragma unroll
        for (int nt = 0; nt < 8; nt++)
#pragma unroll
            for (int r = 0; r < 4; r++) acc[mt][nt][r] = 0.f;

    const int lrow = lane & 15;
    const int lkof = (lane >> 4) * 8;

#pragma unroll
    for (int i = 0; i < 12; i++) {
        const uint32_t dst = smb +
            (l_isA[i] ? (l_op[i] * OPA64) : (2 * OPA64 + l_op[i] * OPB)) +
            l_row[i] * 80 + l_seg[i] * 16;
        const char* src = (l_isA[i] ? srcA[l_op[i]] : srcB[l_op[i]]) +
                          (size_t)l_row[i] * 1024 + l_seg[i] * 16;
        CP_ASYNC16(dst, src);
    }
    CP_COMMIT();

    for (int c = 0; c < 16; c++) {
        if (c + 1 < 16) {
            const uint32_t sb = smb + ((c + 1) & 1) * STAGE64;
            const int koff = (c + 1) * 64;
#pragma unroll
            for (int i = 0; i < 12; i++) {
                const uint32_t dst = sb +
                    (l_isA[i] ? (l_op[i] * OPA64) : (2 * OPA64 + l_op[i] * OPB)) +
                    l_row[i] * 80 + l_seg[i] * 16;
                const char* src = (l_isA[i] ? srcA[l_op[i]] : srcB[l_op[i]]) +
                                  (size_t)l_row[i] * 1024 + koff + l_seg[i] * 16;
                CP_ASYNC16(dst, src);
            }
            CP_COMMIT();
            CP_WAIT1();
        } else {
            CP_WAIT0();
        }
        __syncthreads();

        const uint32_t sb = smb + (c & 1) * STAGE64;
#pragma unroll
        for (int ks = 0; ks < 32; ks += 16) {
            uint32_t ah[2][4], al[2][4];
#pragma unroll
            for (int mt = 0; mt < 2; mt++) {
                const int r = wm * 32 + mt * 16 + lrow;
                const uint32_t ad = sb + r * 80 + (ks + lkof) * 2;
                ldm_x4(ah[mt][0], ah[mt][1], ah[mt][2], ah[mt][3], ad);
                ldm_x4(al[mt][0], al[mt][1], al[mt][2], al[mt][3], ad + OPA64);
            }
            uint32_t bh[8][2], bl[8][2];
#pragma unroll
            for (int np = 0; np < 4; np++) {
                const int r = wn * 64 + np * 16 + lrow;
                const uint32_t bd = sb + 2 * OPA64 + r * 80 + (ks + lkof) * 2;
                uint32_t t0, t1, t2, t3;
                ldm_x4(t0, t1, t2, t3, bd);
                bh[np * 2][0] = t0; bh[np * 2][1] = t2;
                bh[np * 2 + 1][0] = t1; bh[np * 2 + 1][1] = t3;
                ldm_x4(t0, t1, t2, t3, bd + OPB);
                bl[np * 2][0] = t0; bl[np * 2][1] = t2;
                bl[np * 2 + 1][0] = t1; bl[np * 2 + 1][1] = t3;
            }
#pragma unroll
            for (int mt = 0; mt < 2; mt++)
#pragma unroll
                for (int nt = 0; nt < 8; nt++)
                    mma16816(acc[mt][nt], ah[mt], bh[nt]);
#pragma unroll
            for (int mt = 0; mt < 2; mt++)
#pragma unroll
                for (int nt = 0; nt < 8; nt++)
                    mma16816(acc[mt][nt], ah[mt], bl[nt]);
#pragma unroll
            for (int mt = 0; mt < 2; mt++)
#pragma unroll
                for (int nt = 0; nt < 8; nt++)
                    mma16816(acc[mt][nt], al[mt], bh[nt]);
        }
        __syncthreads();
    }

    const int qr = lane >> 2;
    const int qc = (lane & 3) * 2;
#pragma unroll
    for (int mt = 0; mt < 2; mt++) {
#pragma unroll
        for (int nt = 0; nt < 8; nt++) {
            const int col = n0 + wn * 64 + nt * 8 + qc;
            const float2 bv = *(const float2*)(bias + col);
#pragma unroll
            for (int half = 0; half < 2; half++) {
                const int row = m0 + wm * 32 + mt * 16 + qr + half * 8;
                const float2 rv = *(const float2*)(resid + (size_t)row * DD + col);
                float2 o;
                o.x = acc[mt][nt][half * 2 + 0] + bv.x + rv.x;
                o.y = acc[mt][nt][half * 2 + 1] + bv.y + rv.y;
                *(float2*)(C + (size_t)row * DD + col) = o;
            }
        }
    }
}

// ---------------------------------------------------------------------------
// Tensor-core dual-score causal flash attention.
// s2: bf16x2 ((Rqh+Rql) x Rkh). s1: bf16x3. PV: bf16x2 (P_hi x (Vh+Vl);
// P_lo pass dropped -- P in [0,1], residual bounded by 2^-9 P).
// Stage ops: 0=Kph 1=Kpl 2=Krh 3=Vh 4=Vl.
// ---------------------------------------------------------------------------
#define ATS   144
#define QOP   9216
#define KOP   4608
#define STG   (5 * KOP)
#define AT_SMEM (2 * QOP + 2 * STG)

extern __shared__ char at_sm[];

__device__ __forceinline__ void at_load_tile32(
    uint32_t smb, int buf, int tid, int b, int kt0, int hc,
    const __nv_bfloat16* Kh, const __nv_bfloat16* Kl,
    const __nv_bfloat16* Rkh,
    const __nv_bfloat16* Vh, const __nv_bfloat16* Vl)
{
    const char* srcs[5] = {(const char*)Kh, (const char*)Kl, (const char*)Rkh,
                           (const char*)Vh, (const char*)Vl};
    const uint32_t base = smb + 2 * QOP + buf * STG;
#pragma unroll
    for (int i = 0; i < 10; i++) {
        const int idx = tid + i * 128;
        const int op = idx >> 8, r = (idx >> 3) & 31, seg = idx & 7;
        CP_ASYNC16(base + op * KOP + r * ATS + seg * 16,
                   srcs[op] + ((size_t)(b * SS + kt0 + r) * DD + hc) * 2 + seg * 16);
    }
}

__global__ __launch_bounds__(128, 3) void attn_mma_kernel(
    const __nv_bfloat16* __restrict__ Qh, const __nv_bfloat16* __restrict__ Ql,
    const __nv_bfloat16* __restrict__ Kh, const __nv_bfloat16* __restrict__ Kl,
    const __nv_bfloat16* __restrict__ Vh, const __nv_bfloat16* __restrict__ Vl,
    const __nv_bfloat16* __restrict__ Rqh, const __nv_bfloat16* __restrict__ Rql,
    const __nv_bfloat16* __restrict__ Rkh,
    const unsigned long long* __restrict__ mbits, const float* __restrict__ gammas,
    __nv_bfloat16* __restrict__ Oh, __nv_bfloat16* __restrict__ Ol)
{
    const uint32_t smb = smem_u32(at_sm);
    const int tid = threadIdx.x, lane = tid & 31, w = tid >> 5;
    const int bh = blockIdx.x & 63;
    const int q0 = (15 - (blockIdx.x >> 6)) * 64;
    const int b  = bh >> 3, h = bh & 7;
    const int hc = h * DKK;

    float g  = gammas[h];
    float sp = (g > 20.f) ? g : log1pf(__expf(g));
    float te = __expf(-sp);
    te = fminf(fmaxf(te, 1e-5f), 1e5f);
    const float f1 = 0.125f;
    const float f2 = te * rsqrtf((float)DD);
    const float f2f1 = f2 * 8.0f;

    const int qcb = (lane & 3) * 2;
    const int gg = lane >> 3, l8 = lane & 7;
    const int mrw = w * 16 + ((gg & 1) << 3) + l8;
    const int r1 = q0 + w * 16 + (lane >> 2);
    const int r2 = r1 + 8;

    {
        const char* qsrc[4] = {(const char*)Qh, (const char*)Ql,
                               (const char*)Rqh, (const char*)Rql};
#pragma unroll
        for (int i = 0; i < 16; i++) {
            const int idx = tid + i * 128;
            const int op = idx >> 9, r = (idx >> 3) & 63, seg = idx & 7;
            const uint32_t base = (op < 2) ? (smb + 2 * QOP + op * QOP)
                                           : (smb + (op - 2) * QOP);
            CP_ASYNC16(base + r * ATS + seg * 16,
                       qsrc[op] + ((size_t)(b * SS + q0 + r) * DD + hc) * 2 + seg * 16);
        }
        CP_COMMIT(); CP_WAIT0();
        __syncthreads();
    }
    uint32_t qph[4][4], qpl[4][4];
#pragma unroll
    for (int ks = 0; ks < 4; ks++) {
        const uint32_t qa = smb + 2 * QOP + mrw * ATS +
                            (ks * 16 + ((gg >> 1) << 3)) * 2;
        ldm_x4(qph[ks][0], qph[ks][1], qph[ks][2], qph[ks][3], qa);
        ldm_x4(qpl[ks][0], qpl[ks][1], qpl[ks][2], qpl[ks][3], qa + QOP);
    }
    __syncthreads();

    float oacc[8][4];
#pragma unroll
    for (int nt = 0; nt < 8; nt++)
#pragma unroll
        for (int e = 0; e < 4; e++) oacc[nt][e] = 0.f;
    float mrow[2] = {-1e30f, -1e30f};
    float lsum[2] = {0.f, 0.f};

    const int T = q0 / 32 + 2;

    at_load_tile32(smb, 0, tid, b, 0, hc, Kh, Kl, Rkh, Vh, Vl);
    CP_COMMIT();

    for (int t = 0; t < T; t++) {
        const int kt0 = t * 32;
        const unsigned long long mw1 =
            mbits[(size_t)(b * SS + r1) * 16 + (kt0 >> 6)];
        const unsigned long long mw2 =
            mbits[(size_t)(b * SS + r2) * 16 + (kt0 >> 6)];
        if (t + 1 < T) {
            at_load_tile32(smb, (t + 1) & 1, tid, b, kt0 + 32, hc, Kh, Kl, Rkh, Vh, Vl);
            CP_COMMIT(); CP_WAIT1();
        } else {
            CP_WAIT0();
        }
        __syncthreads();

        const uint32_t sb = smb + 2 * QOP + (t & 1) * STG;

        float sc[4][4];
#pragma unroll
        for (int nt = 0; nt < 4; nt++)
#pragma unroll
            for (int e = 0; e < 4; e++) sc[nt][e] = 0.f;

        // ---- s2: raw scores (bf16x2) ----
#pragma unroll
        for (int ks = 0; ks < 4; ks++) {
            uint32_t qh4[4], ql4[4];
            const uint32_t qa = smb + mrw * ATS + (ks * 16 + ((gg >> 1) << 3)) * 2;
            ldm_x4(qh4[0], qh4[1], qh4[2], qh4[3], qa);
            ldm_x4(ql4[0], ql4[1], ql4[2], ql4[3], qa + QOP);
            uint32_t bh2[4][2];
#pragma unroll
            for (int np = 0; np < 2; np++) {
                const uint32_t ad = sb + 2 * KOP +
                    (np * 16 + ((gg >> 1) << 3) + l8) * ATS +
                    (ks * 16 + ((gg & 1) << 3)) * 2;
                uint32_t t0, t1, t2, t3;
                ldm_x4(t0, t1, t2, t3, ad);
                bh2[np*2][0] = t0; bh2[np*2][1] = t1;
                bh2[np*2+1][0] = t2; bh2[np*2+1][1] = t3;
            }
#pragma unroll
            for (int nt = 0; nt < 4; nt++)
                mma16816(sc[nt], qh4, bh2[nt]);
#pragma unroll
            for (int nt = 0; nt < 4; nt++)
                mma16816(sc[nt], ql4, bh2[nt]);
        }

        // ---- gate s2 by packed mask ----
        const int msh = kt0 & 32;
#pragma unroll
        for (int nt = 0; nt < 4; nt++) {
            const int j0 = msh + nt * 8 + qcb;
            sc[nt][0] = ((mw1 >> j0) & 1)       ? sc[nt][0] * f2f1 : 0.f;
            sc[nt][1] = ((mw1 >> (j0 + 1)) & 1) ? sc[nt][1] * f2f1 : 0.f;
            sc[nt][2] = ((mw2 >> j0) & 1)       ? sc[nt][2] * f2f1 : 0.f;
            sc[nt][3] = ((mw2 >> (j0 + 1)) & 1) ? sc[nt][3] * f2f1 : 0.f;
        }

        // ---- s1: projected scores (bf16x3) ----
#pragma unroll
        for (int ks = 0; ks < 4; ks++) {
            uint32_t bh2[4][2], bl2[4][2];
#pragma unroll
            for (int np = 0; np < 2; np++) {
                const uint32_t ad = sb +
                    (np * 16 + ((gg >> 1) << 3) + l8) * ATS +
                    (ks * 16 + ((gg & 1) << 3)) * 2;
                uint32_t t0, t1, t2, t3;
                ldm_x4(t0, t1, t2, t3, ad);
                bh2[np*2][0] = t0; bh2[np*2][1] = t1;
                bh2[np*2+1][0] = t2; bh2[np*2+1][1] = t3;
                ldm_x4(t0, t1, t2, t3, ad + KOP);
                bl2[np*2][0] = t0; bl2[np*2][1] = t1;
                bl2[np*2+1][0] = t2; bl2[np*2+1][1] = t3;
            }
#pragma unroll
            for (int nt = 0; nt < 4; nt++)
                mma16816(sc[nt], qph[ks], bh2[nt]);
#pragma unroll
            for (int nt = 0; nt < 4; nt++)
                mma16816(sc[nt], qph[ks], bl2[nt]);
#pragma unroll
            for (int nt = 0; nt < 4; nt++)
                mma16816(sc[nt], qpl[ks], bh2[nt]);
        }

        // ---- causal mask + final scale ----
#pragma unroll
        for (int nt = 0; nt < 4; nt++) {
            const int gj0 = kt0 + nt * 8 + qcb;
            sc[nt][0] = (gj0     < r1) ? sc[nt][0] * f1 : -INFINITY;
            sc[nt][1] = (gj0 + 1 < r1) ? sc[nt][1] * f1 : -INFINITY;
            sc[nt][2] = (gj0     < r2) ? sc[nt][2] * f1 : -INFINITY;
            sc[nt][3] = (gj0 + 1 < r2) ? sc[nt][3] * f1 : -INFINITY;
        }

        // ---- online softmax ----
        float rm1 = -INFINITY, rm2 = -INFINITY;
#pragma unroll
        for (int nt = 0; nt < 4; nt++) {
            rm1 = fmaxf(rm1, fmaxf(sc[nt][0], sc[nt][1]));
            rm2 = fmaxf(rm2, fmaxf(sc[nt][2], sc[nt][3]));
        }
        rm1 = fmaxf(rm1, __shfl_xor_sync(0xffffffffu, rm1, 1));
        rm1 = fmaxf(rm1, __shfl_xor_sync(0xffffffffu, rm1, 2));
        rm2 = fmaxf(rm2, __shfl_xor_sync(0xffffffffu, rm2, 1));
        rm2 = fmaxf(rm2, __shfl_xor_sync(0xffffffffu, rm2, 2));
        const float mn1 = fmaxf(mrow[0], rm1);
        const float mn2 = fmaxf(mrow[1], rm2);
        const float scl1 = __expf(mrow[0] - mn1);
        const float scl2 = __expf(mrow[1] - mn2);
        mrow[0] = mn1; mrow[1] = mn2;

        float ps1 = 0.f, ps2 = 0.f;
#pragma unroll
        for (int nt = 0; nt < 4; nt++) {
            sc[nt][0] = __expf(sc[nt][0] - mn1);
            sc[nt][1] = __expf(sc[nt][1] - mn1);
            sc[nt][2] = __expf(sc[nt][2] - mn2);
            sc[nt][3] = __expf(sc[nt][3] - mn2);
            ps1 += sc[nt][0] + sc[nt][1];
            ps2 += sc[nt][2] + sc[nt][3];
        }
        ps1 += __shfl_xor_sync(0xffffffffu, ps1, 1);
        ps1 += __shfl_xor_sync(0xffffffffu, ps1, 2);
        ps2 += __shfl_xor_sync(0xffffffffu, ps2, 1);
        ps2 += __shfl_xor_sync(0xffffffffu, ps2, 2);
        lsum[0] = lsum[0] * scl1 + ps1;
        lsum[1] = lsum[1] * scl2 + ps2;

#pragma unroll
        for (int nt = 0; nt < 8; nt++) {
            oacc[nt][0] *= scl1; oacc[nt][1] *= scl1;
            oacc[nt][2] *= scl2; oacc[nt][3] *= scl2;
        }

        // ---- pack P (hi only; residual < 2^-9 P dropped) ----
        uint32_t pha[2][4];
#pragma unroll
        for (int j = 0; j < 2; j++) {
            pha[j][0] = pack_bf2(sc[2*j][0],   sc[2*j][1]);
            pha[j][1] = pack_bf2(sc[2*j][2],   sc[2*j][3]);
            pha[j][2] = pack_bf2(sc[2*j+1][0], sc[2*j+1][1]);
            pha[j][3] = pack_bf2(sc[2*j+1][2], sc[2*j+1][3]);
        }

        // ---- PV (bf16x2: P_hi x V_hi + P_hi x V_lo) ----
#pragma unroll
        for (int j = 0; j < 2; j++) {
            uint32_t vh2[8][2], vl2[8][2];
#pragma unroll
            for (int np = 0; np < 4; np++) {
                const uint32_t ad = sb + 3 * KOP +
                    (j * 16 + ((gg & 1) << 3) + l8) * ATS +
                    (np * 16 + ((gg >> 1) << 3)) * 2;
                uint32_t t0, t1, t2, t3;
                ldm_x4t(t0, t1, t2, t3, ad);
                vh2[np*2][0] = t0; vh2[np*2][1] = t1;
                vh2[np*2+1][0] = t2; vh2[np*2+1][1] = t3;
                ldm_x4t(t0, t1, t2, t3, ad + KOP);
                vl2[np*2][0] = t0; vl2[np*2][1] = t1;
                vl2[np*2+1][0] = t2; vl2[np*2+1][1] = t3;
            }
#pragma unroll
            for (int nt = 0; nt < 8; nt++)
                mma16816(oacc[nt], pha[j], vh2[nt]);
#pragma unroll
            for (int nt = 0; nt < 8; nt++)
                mma16816(oacc[nt], pha[j], vl2[nt]);
        }
        __syncthreads();
    }

    const float rr1 = (lsum[0] > 0.f) ? (1.f / lsum[0]) : 0.f;
    const float rr2 = (lsum[1] > 0.f) ? (1.f / lsum[1]) : 0.f;
    const size_t base1 = (size_t)(b * SS + r1) * DD + hc;
    const size_t base2 = (size_t)(b * SS + r2) * DD + hc;
#pragma unroll
    for (int nt = 0; nt < 8; nt++) {
        const int co = nt * 8 + qcb;
        uint32_t hi, lo;
        split2(oacc[nt][0] * rr1, oacc[nt][1] * rr1, hi, lo);
        *(uint32_t*)(Oh + base1 + co) = hi;
        *(uint32_t*)(Ol + base1 + co) = lo;
        split2(oacc[nt][2] * rr2, oacc[nt][3] * rr2, hi, lo);
        *(uint32_t*)(Oh + base2 + co) = hi;
        *(uint32_t*)(Ol + base2 + co) = lo;
    }
}

// ---------------------------------------------------------------------------
// In-place LayerNorm: one warp per row of 512 floats.
// ---------------------------------------------------------------------------
__global__ __launch_bounds__(256) void ln_kernel(
    float* __restrict__ X, const float* __restrict__ gam, const float* __restrict__ bet)
{
    const int warp = threadIdx.x >> 5, lane = threadIdx.x & 31;
    const size_t row = (size_t)blockIdx.x * 8 + warp;
    float* xr = X + row * DD;

    float4 v[4];
    float s = 0.f, s2 = 0.f;
#pragma unroll
    for (int w = 0; w < 4; w++) {
        v[w] = *(const float4*)(xr + w * 128 + lane * 4);
        s  += v[w].x + v[w].y + v[w].z + v[w].w;
        s2 += v[w].x * v[w].x + v[w].y * v[w].y + v[w].z * v[w].z + v[w].w * v[w].w;
    }
#pragma unroll
    for (int o = 16; o > 0; o >>= 1) {
        s  += __shfl_xor_sync(0xffffffffu, s,  o);
        s2 += __shfl_xor_sync(0xffffffffu, s2, o);
    }
    const float mu  = s * (1.f / DD);
    const float var = s2 * (1.f / DD) - mu * mu;
    const float inv = rsqrtf(var + 1e-5f);
#pragma unroll
    for (int w = 0; w < 4; w++) {
        const int c = w * 128 + lane * 4;
        float4 gv = *(const float4*)(gam + c);
        float4 bv = *(const float4*)(bet + c);
        float4 o;
        o.x = (v[w].x - mu) * inv * gv.x + bv.x;
        o.y = (v[w].y - mu) * inv * gv.y + bv.y;
        o.z = (v[w].z - mu) * inv * gv.z + bv.z;
        o.w = (v[w].w - mu) * inv * gv.w + bv.w;
        *(float4*)(xr + c) = o;
    }
}

// ---------------------------------------------------------------------------
extern "C" void kernel_launch(void* const* d_in, const int* in_sizes, int n_in,
                              void* d_out, int out_size)
{
    const float* q_in  = (const float*)d_in[0];
    const float* k_in  = (const float*)d_in[1];
    const float* v_in  = (const float*)d_in[2];
    const int*   smask = (const int*)  d_in[3];
    const float* Wq    = (const float*)d_in[4];
    const float* bq    = (const float*)d_in[5];
    const float* Wv    = (const float*)d_in[6];
    const float* bv    = (const float*)d_in[7];
    const float* Wo    = (const float*)d_in[8];
    const float* bo    = (const float*)d_in[9];
    const float* gam   = (const float*)d_in[10];
    const float* ln_g  = (const float*)d_in[11];
    const float* ln_b  = (const float*)d_in[12];
    float* out = (float*)d_out;

    __nv_bfloat16 *Xqh, *Xql, *Xkh, *Xkl, *Xvh, *Xvl;
    __nv_bfloat16 *Qh, *Ql, *Kh, *Kl, *Vh, *Vl, *Oh, *Ol;
    __nv_bfloat16 *Wqh, *Wql, *Wvh, *Wvl, *Woh, *Wol;
    unsigned long long* mbits;
    cudaGetSymbolAddress((void**)&Xqh, g_Xqh); cudaGetSymbolAddress((void**)&Xql, g_Xql);
    cudaGetSymbolAddress((void**)&Xkh, g_Xkh); cudaGetSymbolAddress((void**)&Xkl, g_Xkl);
    cudaGetSymbolAddress((void**)&Xvh, g_Xvh); cudaGetSymbolAddress((void**)&Xvl, g_Xvl);
    cudaGetSymbolAddress((void**)&Qh, g_Qh);   cudaGetSymbolAddress((void**)&Ql, g_Ql);
    cudaGetSymbolAddress((void**)&Kh, g_Kh);   cudaGetSymbolAddress((void**)&Kl, g_Kl);
    cudaGetSymbolAddress((void**)&Vh, g_Vh);   cudaGetSymbolAddress((void**)&Vl, g_Vl);
    cudaGetSymbolAddress((void**)&Oh, g_Oh);   cudaGetSymbolAddress((void**)&Ol, g_Ol);
    cudaGetSymbolAddress((void**)&Wqh, g_Wqh); cudaGetSymbolAddress((void**)&Wql, g_Wql);
    cudaGetSymbolAddress((void**)&Wvh, g_Wvh); cudaGetSymbolAddress((void**)&Wvl, g_Wvl);
    cudaGetSymbolAddress((void**)&Woh, g_Woh); cudaGetSymbolAddress((void**)&Wol, g_Wol);
    cudaGetSymbolAddress((void**)&mbits, g_mbits);

    cudaFuncSetAttribute(mma_gemm_kernel, cudaFuncAttributeMaxDynamicSharedMemorySize,
                         (int)MMG_SMEM);
    cudaFuncSetAttribute(mma_gemm64_kernel, cudaFuncAttributeMaxDynamicSharedMemorySize,
                         (int)MMG64_SMEM);
    cudaFuncSetAttribute(attn_mma_kernel, cudaFuncAttributeMaxDynamicSharedMemorySize,
                         (int)AT_SMEM);

    const dim3 gb(256);

    // fused prepasses
    prep_kernel<<<PREP_TOTAL_B, gb>>>(
        q_in, k_in, v_in, Xqh, Xql, Xkh, Xkl, Xvh, Xvl,
        Wq, Wv, Wo, Wqh, Wql, Wvh, Wvl, Woh, Wol,
        smask, mbits);

    // Q + K + V projections fused in one launch (grid.z = 3)
    const dim3 ggrid3(DD / 128, MM / 128, 3);
    mma_gemm_kernel<<<ggrid3, gb, MMG_SMEM>>>(
        Xqh, Xql, Xkh, Xkl, Xvh, Xvl,
        Wqh, Wql, Wvh, Wvl,
        bq, bv,
        Qh, Ql, Kh, Kl, Vh, Vl);

    // tensor-core attention: 1024 CTAs, heavy-first, 3 CTAs/SM
    attn_mma_kernel<<<1024, 128, AT_SMEM>>>(Qh, Ql, Kh, Kl, Vh, Vl,
                                            Xqh, Xql, Xkh, mbits, gam, Oh, Ol);

    // output projection + bias + residual -> fp32 out (64-row tiles, balanced)
    const dim3 ggrid64(DD / 128, MM / 64);
    mma_gemm64_kernel<<<ggrid64, 128, MMG64_SMEM>>>(
        Oh, Ol, Woh, Wol, bo, q_in, out);

    // in-place LayerNorm
    ln_kernel<<<MM / 8, gb>>>(out, ln_g, ln_b);
}

// round 17
// speedup vs baseline: 1.1874x; 1.0450x over previous
#include <cuda_runtime.h>
#include <cuda_bf16.h>
#include <math.h>
#include <cstdint>

// Problem constants
#define BB 8
#define SS 1024
#define DD 512
#define HH 8
#define DKK 64
#define MM (BB*SS)   // 8192 rows
#define NELEM ((size_t)MM * DD)

// ---------------- scratch (static __device__: allocation-guard safe) --------
__device__ __nv_bfloat16 g_Xqh[NELEM], g_Xql[NELEM];
__device__ __nv_bfloat16 g_Xkh[NELEM], g_Xkl[NELEM];
__device__ __nv_bfloat16 g_Xvh[NELEM], g_Xvl[NELEM];
__device__ __nv_bfloat16 g_Qh[NELEM], g_Ql[NELEM];
__device__ __nv_bfloat16 g_Kh[NELEM], g_Kl[NELEM];
__device__ __nv_bfloat16 g_Vh[NELEM], g_Vl[NELEM];
__device__ __nv_bfloat16 g_Oh[NELEM], g_Ol[NELEM];
__device__ __nv_bfloat16 g_Wqh[DD * DD], g_Wql[DD * DD];
__device__ __nv_bfloat16 g_Wvh[DD * DD], g_Wvl[DD * DD];
__device__ __nv_bfloat16 g_Woh[DD * DD], g_Wol[DD * DD];
__device__ unsigned long long g_mbits[(size_t)MM * 16];

// ---------------- PTX helpers (base sm_103-safe) -----------------------------
__device__ __forceinline__ uint32_t smem_u32(const void* p) {
    uint32_t a;
    asm("{ .reg .u64 t; cvta.to.shared.u64 t, %1; cvt.u32.u64 %0, t; }" : "=r"(a) : "l"(p));
    return a;
}
#define CP_ASYNC16(dst, src) \
    asm volatile("cp.async.cg.shared.global [%0], [%1], 16;" :: "r"(dst), "l"(src) : "memory")
#define CP_COMMIT() asm volatile("cp.async.commit_group;" ::: "memory")
#define CP_WAIT1()  asm volatile("cp.async.wait_group 1;" ::: "memory")
#define CP_WAIT0()  asm volatile("cp.async.wait_group 0;" ::: "memory")

__device__ __forceinline__ void ldm_x4(uint32_t& r0, uint32_t& r1, uint32_t& r2,
                                       uint32_t& r3, uint32_t addr) {
    asm volatile("ldmatrix.sync.aligned.m8n8.x4.shared.b16 {%0,%1,%2,%3}, [%4];"
                 : "=r"(r0), "=r"(r1), "=r"(r2), "=r"(r3) : "r"(addr));
}
__device__ __forceinline__ void ldm_x4t(uint32_t& r0, uint32_t& r1, uint32_t& r2,
                                        uint32_t& r3, uint32_t addr) {
    asm volatile("ldmatrix.sync.aligned.m8n8.x4.trans.shared.b16 {%0,%1,%2,%3}, [%4];"
                 : "=r"(r0), "=r"(r1), "=r"(r2), "=r"(r3) : "r"(addr));
}
__device__ __forceinline__ void mma16816(float* d, const uint32_t* a, const uint32_t* b) {
    asm volatile("mma.sync.aligned.m16n8k16.row.col.f32.bf16.bf16.f32 "
                 "{%0,%1,%2,%3}, {%4,%5,%6,%7}, {%8,%9}, {%0,%1,%2,%3};"
                 : "+f"(d[0]), "+f"(d[1]), "+f"(d[2]), "+f"(d[3])
                 : "r"(a[0]), "r"(a[1]), "r"(a[2]), "r"(a[3]), "r"(b[0]), "r"(b[1]));
}
__device__ __forceinline__ uint32_t pack_bf2(float a, float b) {
    __nv_bfloat162 t = __floats2bfloat162_rn(a, b);
    return *(uint32_t*)&t;
}
__device__ __forceinline__ void split2(float a, float b, uint32_t& hi, uint32_t& lo) {
    const __nv_bfloat16 ha = __float2bfloat16(a), hb = __float2bfloat16(b);
    const float ra = a - __bfloat162float(ha), rb = b - __bfloat162float(hb);
    __nv_bfloat162 th; th.x = ha; th.y = hb;
    hi = *(uint32_t*)&th;
    lo = pack_bf2(ra, rb);
}

// ---------------------------------------------------------------------------
// Fused prepass kernel: split3 + wsplit3 + triangle-only pack_mask.
// ---------------------------------------------------------------------------
#define PREP_SPLIT_B 12288
#define PREP_WSPL_B  768
#define PREP_MASK_B  16384
#define PREP_TOTAL_B (PREP_SPLIT_B + PREP_WSPL_B + PREP_MASK_B)

__global__ __launch_bounds__(256) void prep_kernel(
    const float* __restrict__ Xq, const float* __restrict__ Xk,
    const float* __restrict__ Xv,
    __nv_bfloat16* __restrict__ Xqh, __nv_bfloat16* __restrict__ Xql,
    __nv_bfloat16* __restrict__ Xkh, __nv_bfloat16* __restrict__ Xkl,
    __nv_bfloat16* __restrict__ Xvh, __nv_bfloat16* __restrict__ Xvl,
    const float* __restrict__ Wq, const float* __restrict__ Wv,
    const float* __restrict__ Wo,
    __nv_bfloat16* __restrict__ Wqh, __nv_bfloat16* __restrict__ Wql,
    __nv_bfloat16* __restrict__ Wvh, __nv_bfloat16* __restrict__ Wvl,
    __nv_bfloat16* __restrict__ Woh, __nv_bfloat16* __restrict__ Wol,
    const int* __restrict__ smask, unsigned long long* __restrict__ bits)
{
    __shared__ float tile[32][33];
    const int bid = blockIdx.x;
    const int tid = threadIdx.x;

    if (bid < PREP_SPLIT_B) {
        const int s = bid / 4096;
        const int blk = bid - s * 4096;
        const float* X = (s == 0) ? Xq : (s == 1) ? Xk : Xv;
        __nv_bfloat16* H = (s == 0) ? Xqh : (s == 1) ? Xkh : Xvh;
        __nv_bfloat16* L = (s == 0) ? Xql : (s == 1) ? Xkl : Xvl;
        const size_t i = ((size_t)blk * 256 + tid) * 4;
        float4 v = *(const float4*)(X + i);
        __nv_bfloat16 h[4], l[4];
        float x[4] = {v.x, v.y, v.z, v.w};
#pragma unroll
        for (int j = 0; j < 4; j++) {
            h[j] = __float2bfloat16(x[j]);
            l[j] = __float2bfloat16(x[j] - __bfloat162float(h[j]));
        }
        *(uint2*)(H + i) = *(uint2*)h;
        *(uint2*)(L + i) = *(uint2*)l;
    } else if (bid < PREP_SPLIT_B + PREP_WSPL_B) {
        const int w = bid - PREP_SPLIT_B;
        const int s = w / 256;
        const int rem = w - s * 256;
        const int bx = rem & 15, by = rem >> 4;
        const float* W = (s == 0) ? Wq : (s == 1) ? Wv : Wo;
        __nv_bfloat16* Ht = (s == 0) ? Wqh : (s == 1) ? Wvh : Woh;
        __nv_bfloat16* Lt = (s == 0) ? Wql : (s == 1) ? Wvl : Wol;
        const int tx = tid & 31, ty = tid >> 5;
        const int k0 = by * 32, n0 = bx * 32;
#pragma unroll
        for (int r = 0; r < 4; r++)
            tile[ty * 4 + r][tx] = W[(size_t)(k0 + ty * 4 + r) * DD + n0 + tx];
        __syncthreads();
#pragma unroll
        for (int r = 0; r < 4; r++) {
            const int n = n0 + ty * 4 + r;
            const float x = tile[tx][ty * 4 + r];
            const __nv_bfloat16 h = __float2bfloat16(x);
            Ht[(size_t)n * DD + k0 + tx] = h;
            Lt[(size_t)n * DD + k0 + tx] = __float2bfloat16(x - __bfloat162float(h));
        }
    } else {
        const int pb = bid - PREP_SPLIT_B - PREP_WSPL_B;
        const int gw = pb * 8 + (tid >> 5);
        const int lane = tid & 31;
        const int word = gw & 15;
        const int row  = gw >> 4;
        const int srow = row & (SS - 1);
        if (word * 64 < srow) {
            const int* p = smask + (size_t)row * SS + word * 64;
            const unsigned lo = __ballot_sync(0xffffffffu, p[lane] != 0);
            const unsigned hi = __ballot_sync(0xffffffffu, p[lane + 32] != 0);
            if (lane == 0)
                bits[(size_t)row * 16 + word] = ((unsigned long long)hi << 32) | lo;
        }
    }
}

// ---------------------------------------------------------------------------
// mma.sync GEMM (256 threads, CTA 128x128, warp tile 32x64), K-chunk 32,
// cp.async double buffer. grid.z selects operand set (fused QKV projections).
// z=0 (Q) and z=1 (K) use bf16x2 (Al*Bh pass dropped: outputs feed only the
// softmax-score path); z=2 (V) keeps full bf16x3 (feeds output directly).
// ---------------------------------------------------------------------------
#define LDSP 40
#define OPB  (128 * LDSP * 2)
#define STAGE_B (4 * OPB)
#define MMG_SMEM (2 * STAGE_B)

extern __shared__ char mm_sm[];

__global__ __launch_bounds__(256) void mma_gemm_kernel(
    const __nv_bfloat16* __restrict__ Ah0, const __nv_bfloat16* __restrict__ Al0,
    const __nv_bfloat16* __restrict__ Ah1, const __nv_bfloat16* __restrict__ Al1,
    const __nv_bfloat16* __restrict__ Ah2, const __nv_bfloat16* __restrict__ Al2,
    const __nv_bfloat16* __restrict__ Bh0, const __nv_bfloat16* __restrict__ Bl0,
    const __nv_bfloat16* __restrict__ Bh1, const __nv_bfloat16* __restrict__ Bl1,
    const float* __restrict__ bias0, const float* __restrict__ bias1,
    __nv_bfloat16* __restrict__ Ch0, __nv_bfloat16* __restrict__ Cl0,
    __nv_bfloat16* __restrict__ Ch1, __nv_bfloat16* __restrict__ Cl1,
    __nv_bfloat16* __restrict__ Ch2, __nv_bfloat16* __restrict__ Cl2)
{
    const uint32_t smb = smem_u32(mm_sm);
    const int tid  = threadIdx.x;
    const int wid  = tid >> 5;
    const int lane = tid & 31;
    const int wm   = wid & 3;
    const int wn   = wid >> 2;
    const int m0 = blockIdx.y * 128, n0 = blockIdx.x * 128;
    const int z = blockIdx.z;
    const __nv_bfloat16* Ah = (z == 0) ? Ah0 : (z == 1) ? Ah1 : Ah2;
    const __nv_bfloat16* Al = (z == 0) ? Al0 : (z == 1) ? Al1 : Al2;
    const __nv_bfloat16* Bh = (z == 2) ? Bh1 : Bh0;
    const __nv_bfloat16* Bl = (z == 2) ? Bl1 : Bl0;
    const float* bias = (z == 2) ? bias1 : bias0;
    __nv_bfloat16* Ch = (z == 0) ? Ch0 : (z == 1) ? Ch1 : Ch2;
    __nv_bfloat16* Cl = (z == 0) ? Cl0 : (z == 1) ? Cl1 : Cl2;
    const bool third = (z == 2);   // full bf16x3 only for V projection

    const char* srcs[4] = {
        (const char*)(Ah + (size_t)m0 * DD),
        (const char*)(Al + (size_t)m0 * DD),
        (const char*)(Bh + (size_t)n0 * DD),
        (const char*)(Bl + (size_t)n0 * DD)
    };

    int l_op[8], l_row[8], l_seg[8];
#pragma unroll
    for (int i = 0; i < 8; i++) {
        const int idx = tid + i * 256;
        l_op[i]  = idx >> 9;
        l_row[i] = (idx & 511) >> 2;
        l_seg[i] = idx & 3;
    }

    float acc[2][8][4];
#pragma unroll
    for (int mt = 0; mt < 2; mt++)
#pragma unroll
        for (int nt = 0; nt < 8; nt++)
#pragma unroll
            for (int r = 0; r < 4; r++) acc[mt][nt][r] = 0.f;

    const int lrow = lane & 15;
    const int lkof = (lane >> 4) * 8;

#pragma unroll
    for (int i = 0; i < 8; i++) {
        CP_ASYNC16(smb + l_op[i] * OPB + l_row[i] * 80 + l_seg[i] * 16,
                   srcs[l_op[i]] + (size_t)l_row[i] * 1024 + l_seg[i] * 16);
    }
    CP_COMMIT();

    for (int c = 0; c < 16; c++) {
        if (c + 1 < 16) {
            const uint32_t sb = smb + ((c + 1) & 1) * STAGE_B;
            const int koff = (c + 1) * 64;
#pragma unroll
            for (int i = 0; i < 8; i++) {
                CP_ASYNC16(sb + l_op[i] * OPB + l_row[i] * 80 + l_seg[i] * 16,
                           srcs[l_op[i]] + (size_t)l_row[i] * 1024 + koff + l_seg[i] * 16);
            }
            CP_COMMIT();
            CP_WAIT1();
        } else {
            CP_WAIT0();
        }
        __syncthreads();

        const uint32_t sb = smb + (c & 1) * STAGE_B;
#pragma unroll
        for (int ks = 0; ks < 32; ks += 16) {
            uint32_t ah[2][4], al[2][4];
#pragma unroll
            for (int mt = 0; mt < 2; mt++) {
                const int r = wm * 32 + mt * 16 + lrow;
                const uint32_t ad = sb + r * 80 + (ks + lkof) * 2;
                ldm_x4(ah[mt][0], ah[mt][1], ah[mt][2], ah[mt][3], ad);
                ldm_x4(al[mt][0], al[mt][1], al[mt][2], al[mt][3], ad + OPB);
            }
            uint32_t bh[8][2], bl[8][2];
#pragma unroll
            for (int np = 0; np < 4; np++) {
                const int r = wn * 64 + np * 16 + lrow;
                const uint32_t bd = sb + 2 * OPB + r * 80 + (ks + lkof) * 2;
                uint32_t t0, t1, t2, t3;
                ldm_x4(t0, t1, t2, t3, bd);
                bh[np * 2][0] = t0; bh[np * 2][1] = t2;
                bh[np * 2 + 1][0] = t1; bh[np * 2 + 1][1] = t3;
                ldm_x4(t0, t1, t2, t3, bd + OPB);
                bl[np * 2][0] = t0; bl[np * 2][1] = t2;
                bl[np * 2 + 1][0] = t1; bl[np * 2 + 1][1] = t3;
            }
#pragma unroll
            for (int mt = 0; mt < 2; mt++)
#pragma unroll
                for (int nt = 0; nt < 8; nt++)
                    mma16816(acc[mt][nt], ah[mt], bh[nt]);
#pragma unroll
            for (int mt = 0; mt < 2; mt++)
#pragma unroll
                for (int nt = 0; nt < 8; nt++)
                    mma16816(acc[mt][nt], ah[mt], bl[nt]);
            if (third) {
#pragma unroll
                for (int mt = 0; mt < 2; mt++)
#pragma unroll
                    for (int nt = 0; nt < 8; nt++)
                        mma16816(acc[mt][nt], al[mt], bh[nt]);
            }
        }
        __syncthreads();
    }

    const int qr = lane >> 2;
    const int qc = (lane & 3) * 2;
#pragma unroll
    for (int mt = 0; mt < 2; mt++) {
#pragma unroll
        for (int nt = 0; nt < 8; nt++) {
            const int col = n0 + wn * 64 + nt * 8 + qc;
            const float2 bv = *(const float2*)(bias + col);
#pragma unroll
            for (int half = 0; half < 2; half++) {
                const int row = m0 + wm * 32 + mt * 16 + qr + half * 8;
                float ox = acc[mt][nt][half * 2 + 0] + bv.x;
                float oy = acc[mt][nt][half * 2 + 1] + bv.y;
                uint32_t hi, lo;
                split2(ox, oy, hi, lo);
                *(uint32_t*)(Ch + (size_t)row * DD + col) = hi;
                *(uint32_t*)(Cl + (size_t)row * DD + col) = lo;
            }
        }
    }
}

// ---------------------------------------------------------------------------
// Output projection: CTA 64x128, 128 threads, 3 CTAs/SM. Full bf16x3.
// ---------------------------------------------------------------------------
#define OPA64 (64 * LDSP * 2)
#define STAGE64 (2 * OPA64 + 2 * OPB)
#define MMG64_SMEM (2 * STAGE64)

__global__ __launch_bounds__(128, 3) void mma_gemm64_kernel(
    const __nv_bfloat16* __restrict__ Ah, const __nv_bfloat16* __restrict__ Al,
    const __nv_bfloat16* __restrict__ Bh, const __nv_bfloat16* __restrict__ Bl,
    const float* __restrict__ bias, const float* __restrict__ resid,
    float* __restrict__ C)
{
    const uint32_t smb = smem_u32(mm_sm);
    const int tid  = threadIdx.x;
    const int wid  = tid >> 5;
    const int lane = tid & 31;
    const int wm   = wid & 1;
    const int wn   = wid >> 1;
    const int m0 = blockIdx.y * 64, n0 = blockIdx.x * 128;

    const char* srcA[2] = {(const char*)(Ah + (size_t)m0 * DD),
                           (const char*)(Al + (size_t)m0 * DD)};
    const char* srcB[2] = {(const char*)(Bh + (size_t)n0 * DD),
                           (const char*)(Bl + (size_t)n0 * DD)};

    int l_isA[12], l_op[12], l_row[12], l_seg[12];
#pragma unroll
    for (int i = 0; i < 12; i++) {
        const int idx = tid + i * 128;
        if (idx < 512) {
            l_isA[i] = 1;
            l_op[i]  = idx >> 8;
            l_row[i] = (idx >> 2) & 63;
            l_seg[i] = idx & 3;
        } else {
            const int j = idx - 512;
            l_isA[i] = 0;
            l_op[i]  = j >> 9;
            l_row[i] = (j >> 2) & 127;
            l_seg[i] = j & 3;
        }
    }

    float acc[2][8][4];
#pragma unroll
    for (int mt = 0; mt < 2; mt++)
#pragma unroll
        for (int nt = 0; nt < 8; nt++)
#pragma unroll
            for (int r = 0; r < 4; r++) acc[mt][nt][r] = 0.f;

    const int lrow = lane & 15;
    const int lkof = (lane >> 4) * 8;

#pragma unroll
    for (int i = 0; i < 12; i++) {
        const uint32_t dst = smb +
            (l_isA[i] ? (l_op[i] * OPA64) : (2 * OPA64 + l_op[i] * OPB)) +
            l_row[i] * 80 + l_seg[i] * 16;
        const char* src = (l_isA[i] ? srcA[l_op[i]] : srcB[l_op[i]]) +
                          (size_t)l_row[i] * 1024 + l_seg[i] * 16;
        CP_ASYNC16(dst, src);
    }
    CP_COMMIT();

    for (int c = 0; c < 16; c++) {
        if (c + 1 < 16) {
            const uint32_t sb = smb + ((c + 1) & 1) * STAGE64;
            const int koff = (c + 1) * 64;
#pragma unroll
            for (int i = 0; i < 12; i++) {
                const uint32_t dst = sb +
                    (l_isA[i] ? (l_op[i] * OPA64) : (2 * OPA64 + l_op[i] * OPB)) +
                    l_row[i] * 80 + l_seg[i] * 16;
                const char* src = (l_isA[i] ? srcA[l_op[i]] : srcB[l_op[i]]) +
                                  (size_t)l_row[i] * 1024 + koff + l_seg[i] * 16;
                CP_ASYNC16(dst, src);
            }
            CP_COMMIT();
            CP_WAIT1();
        } else {
            CP_WAIT0();
        }
        __syncthreads();

        const uint32_t sb = smb + (c & 1) * STAGE64;
#pragma unroll
        for (int ks = 0; ks < 32; ks += 16) {
            uint32_t ah[2][4], al[2][4];
#pragma unroll
            for (int mt = 0; mt < 2; mt++) {
                const int r = wm * 32 + mt * 16 + lrow;
                const uint32_t ad = sb + r * 80 + (ks + lkof) * 2;
                ldm_x4(ah[mt][0], ah[mt][1], ah[mt][2], ah[mt][3], ad);
                ldm_x4(al[mt][0], al[mt][1], al[mt][2], al[mt][3], ad + OPA64);
            }
            uint32_t bh[8][2], bl[8][2];
#pragma unroll
            for (int np = 0; np < 4; np++) {
                const int r = wn * 64 + np * 16 + lrow;
                const uint32_t bd = sb + 2 * OPA64 + r * 80 + (ks + lkof) * 2;
                uint32_t t0, t1, t2, t3;
                ldm_x4(t0, t1, t2, t3, bd);
                bh[np * 2][0] = t0; bh[np * 2][1] = t2;
                bh[np * 2 + 1][0] = t1; bh[np * 2 + 1][1] = t3;
                ldm_x4(t0, t1, t2, t3, bd + OPB);
                bl[np * 2][0] = t0; bl[np * 2][1] = t2;
                bl[np * 2 + 1][0] = t1; bl[np * 2 + 1][1] = t3;
            }
#pragma unroll
            for (int mt = 0; mt < 2; mt++)
#pragma unroll
                for (int nt = 0; nt < 8; nt++)
                    mma16816(acc[mt][nt], ah[mt], bh[nt]);
#pragma unroll
            for (int mt = 0; mt < 2; mt++)
#pragma unroll
                for (int nt = 0; nt < 8; nt++)
                    mma16816(acc[mt][nt], ah[mt], bl[nt]);
#pragma unroll
            for (int mt = 0; mt < 2; mt++)
#pragma unroll
                for (int nt = 0; nt < 8; nt++)
                    mma16816(acc[mt][nt], al[mt], bh[nt]);
        }
        __syncthreads();
    }

    const int qr = lane >> 2;
    const int qc = (lane & 3) * 2;
#pragma unroll
    for (int mt = 0; mt < 2; mt++) {
#pragma unroll
        for (int nt = 0; nt < 8; nt++) {
            const int col = n0 + wn * 64 + nt * 8 + qc;
            const float2 bv = *(const float2*)(bias + col);
#pragma unroll
            for (int half = 0; half < 2; half++) {
                const int row = m0 + wm * 32 + mt * 16 + qr + half * 8;
                const float2 rv = *(const float2*)(resid + (size_t)row * DD + col);
                float2 o;
                o.x = acc[mt][nt][half * 2 + 0] + bv.x + rv.x;
                o.y = acc[mt][nt][half * 2 + 1] + bv.y + rv.y;
                *(float2*)(C + (size_t)row * DD + col) = o;
            }
        }
    }
}

// ---------------------------------------------------------------------------
// Tensor-core dual-score causal flash attention.
// s2: bf16x2. s1: bf16x3. PV: bf16x2 (P_hi only).
// Stage ops: 0=Kph 1=Kpl 2=Krh 3=Vh 4=Vl.
// ---------------------------------------------------------------------------
#define ATS   144
#define QOP   9216
#define KOP   4608
#define STG   (5 * KOP)
#define AT_SMEM (2 * QOP + 2 * STG)

extern __shared__ char at_sm[];

__device__ __forceinline__ void at_load_tile32(
    uint32_t smb, int buf, int tid, int b, int kt0, int hc,
    const __nv_bfloat16* Kh, const __nv_bfloat16* Kl,
    const __nv_bfloat16* Rkh,
    const __nv_bfloat16* Vh, const __nv_bfloat16* Vl)
{
    const char* srcs[5] = {(const char*)Kh, (const char*)Kl, (const char*)Rkh,
                           (const char*)Vh, (const char*)Vl};
    const uint32_t base = smb + 2 * QOP + buf * STG;
#pragma unroll
    for (int i = 0; i < 10; i++) {
        const int idx = tid + i * 128;
        const int op = idx >> 8, r = (idx >> 3) & 31, seg = idx & 7;
        CP_ASYNC16(base + op * KOP + r * ATS + seg * 16,
                   srcs[op] + ((size_t)(b * SS + kt0 + r) * DD + hc) * 2 + seg * 16);
    }
}

__global__ __launch_bounds__(128, 3) void attn_mma_kernel(
    const __nv_bfloat16* __restrict__ Qh, const __nv_bfloat16* __restrict__ Ql,
    const __nv_bfloat16* __restrict__ Kh, const __nv_bfloat16* __restrict__ Kl,
    const __nv_bfloat16* __restrict__ Vh, const __nv_bfloat16* __restrict__ Vl,
    const __nv_bfloat16* __restrict__ Rqh, const __nv_bfloat16* __restrict__ Rql,
    const __nv_bfloat16* __restrict__ Rkh,
    const unsigned long long* __restrict__ mbits, const float* __restrict__ gammas,
    __nv_bfloat16* __restrict__ Oh, __nv_bfloat16* __restrict__ Ol)
{
    const uint32_t smb = smem_u32(at_sm);
    const int tid = threadIdx.x, lane = tid & 31, w = tid >> 5;
    const int bh = blockIdx.x & 63;
    const int q0 = (15 - (blockIdx.x >> 6)) * 64;
    const int b  = bh >> 3, h = bh & 7;
    const int hc = h * DKK;

    float g  = gammas[h];
    float sp = (g > 20.f) ? g : log1pf(__expf(g));
    float te = __expf(-sp);
    te = fminf(fmaxf(te, 1e-5f), 1e5f);
    const float f1 = 0.125f;
    const float f2 = te * rsqrtf((float)DD);
    const float f2f1 = f2 * 8.0f;

    const int qcb = (lane & 3) * 2;
    const int gg = lane >> 3, l8 = lane & 7;
    const int mrw = w * 16 + ((gg & 1) << 3) + l8;
    const int r1 = q0 + w * 16 + (lane >> 2);
    const int r2 = r1 + 8;

    {
        const char* qsrc[4] = {(const char*)Qh, (const char*)Ql,
                               (const char*)Rqh, (const char*)Rql};
#pragma unroll
        for (int i = 0; i < 16; i++) {
            const int idx = tid + i * 128;
            const int op = idx >> 9, r = (idx >> 3) & 63, seg = idx & 7;
            const uint32_t base = (op < 2) ? (smb + 2 * QOP + op * QOP)
                                           : (smb + (op - 2) * QOP);
            CP_ASYNC16(base + r * ATS + seg * 16,
                       qsrc[op] + ((size_t)(b * SS + q0 + r) * DD + hc) * 2 + seg * 16);
        }
        CP_COMMIT(); CP_WAIT0();
        __syncthreads();
    }
    uint32_t qph[4][4], qpl[4][4];
#pragma unroll
    for (int ks = 0; ks < 4; ks++) {
        const uint32_t qa = smb + 2 * QOP + mrw * ATS +
                            (ks * 16 + ((gg >> 1) << 3)) * 2;
        ldm_x4(qph[ks][0], qph[ks][1], qph[ks][2], qph[ks][3], qa);
        ldm_x4(qpl[ks][0], qpl[ks][1], qpl[ks][2], qpl[ks][3], qa + QOP);
    }
    __syncthreads();

    float oacc[8][4];
#pragma unroll
    for (int nt = 0; nt < 8; nt++)
#pragma unroll
        for (int e = 0; e < 4; e++) oacc[nt][e] = 0.f;
    float mrow[2] = {-1e30f, -1e30f};
    float lsum[2] = {0.f, 0.f};

    const int T = q0 / 32 + 2;

    at_load_tile32(smb, 0, tid, b, 0, hc, Kh, Kl, Rkh, Vh, Vl);
    CP_COMMIT();

    for (int t = 0; t < T; t++) {
        const int kt0 = t * 32;
        const unsigned long long mw1 =
            mbits[(size_t)(b * SS + r1) * 16 + (kt0 >> 6)];
        const unsigned long long mw2 =
            mbits[(size_t)(b * SS + r2) * 16 + (kt0 >> 6)];
        if (t + 1 < T) {
            at_load_tile32(smb, (t + 1) & 1, tid, b, kt0 + 32, hc, Kh, Kl, Rkh, Vh, Vl);
            CP_COMMIT(); CP_WAIT1();
        } else {
            CP_WAIT0();
        }
        __syncthreads();

        const uint32_t sb = smb + 2 * QOP + (t & 1) * STG;

        float sc[4][4];
#pragma unroll
        for (int nt = 0; nt < 4; nt++)
#pragma unroll
            for (int e = 0; e < 4; e++) sc[nt][e] = 0.f;

        // ---- s2: raw scores (bf16x2) ----
#pragma unroll
        for (int ks = 0; ks < 4; ks++) {
            uint32_t qh4[4], ql4[4];
            const uint32_t qa = smb + mrw * ATS + (ks * 16 + ((gg >> 1) << 3)) * 2;
            ldm_x4(qh4[0], qh4[1], qh4[2], qh4[3], qa);
            ldm_x4(ql4[0], ql4[1], ql4[2], ql4[3], qa + QOP);
            uint32_t bh2[4][2];
#pragma unroll
            for (int np = 0; np < 2; np++) {
                const uint32_t ad = sb + 2 * KOP +
                    (np * 16 + ((gg >> 1) << 3) + l8) * ATS +
                    (ks * 16 + ((gg & 1) << 3)) * 2;
                uint32_t t0, t1, t2, t3;
                ldm_x4(t0, t1, t2, t3, ad);
                bh2[np*2][0] = t0; bh2[np*2][1] = t1;
                bh2[np*2+1][0] = t2; bh2[np*2+1][1] = t3;
            }
#pragma unroll
            for (int nt = 0; nt < 4; nt++)
                mma16816(sc[nt], qh4, bh2[nt]);
#pragma unroll
            for (int nt = 0; nt < 4; nt++)
                mma16816(sc[nt], ql4, bh2[nt]);
        }

        // ---- gate s2 by packed mask ----
        const int msh = kt0 & 32;
#pragma unroll
        for (int nt = 0; nt < 4; nt++) {
            const int j0 = msh + nt * 8 + qcb;
            sc[nt][0] = ((mw1 >> j0) & 1)       ? sc[nt][0] * f2f1 : 0.f;
            sc[nt][1] = ((mw1 >> (j0 + 1)) & 1) ? sc[nt][1] * f2f1 : 0.f;
            sc[nt][2] = ((mw2 >> j0) & 1)       ? sc[nt][2] * f2f1 : 0.f;
            sc[nt][3] = ((mw2 >> (j0 + 1)) & 1) ? sc[nt][3] * f2f1 : 0.f;
        }

        // ---- s1: projected scores (bf16x3) ----
#pragma unroll
        for (int ks = 0; ks < 4; ks++) {
            uint32_t bh2[4][2], bl2[4][2];
#pragma unroll
            for (int np = 0; np < 2; np++) {
                const uint32_t ad = sb +
                    (np * 16 + ((gg >> 1) << 3) + l8) * ATS +
                    (ks * 16 + ((gg & 1) << 3)) * 2;
                uint32_t t0, t1, t2, t3;
                ldm_x4(t0, t1, t2, t3, ad);
                bh2[np*2][0] = t0; bh2[np*2][1] = t1;
                bh2[np*2+1][0] = t2; bh2[np*2+1][1] = t3;
                ldm_x4(t0, t1, t2, t3, ad + KOP);
                bl2[np*2][0] = t0; bl2[np*2][1] = t1;
                bl2[np*2+1][0] = t2; bl2[np*2+1][1] = t3;
            }
#pragma unroll
            for (int nt = 0; nt < 4; nt++)
                mma16816(sc[nt], qph[ks], bh2[nt]);
#pragma unroll
            for (int nt = 0; nt < 4; nt++)
                mma16816(sc[nt], qph[ks], bl2[nt]);
#pragma unroll
            for (int nt = 0; nt < 4; nt++)
                mma16816(sc[nt], qpl[ks], bh2[nt]);
        }

        // ---- causal mask + final scale ----
#pragma unroll
        for (int nt = 0; nt < 4; nt++) {
            const int gj0 = kt0 + nt * 8 + qcb;
            sc[nt][0] = (gj0     < r1) ? sc[nt][0] * f1 : -INFINITY;
            sc[nt][1] = (gj0 + 1 < r1) ? sc[nt][1] * f1 : -INFINITY;
            sc[nt][2] = (gj0     < r2) ? sc[nt][2] * f1 : -INFINITY;
            sc[nt][3] = (gj0 + 1 < r2) ? sc[nt][3] * f1 : -INFINITY;
        }

        // ---- online softmax ----
        float rm1 = -INFINITY, rm2 = -INFINITY;
#pragma unroll
        for (int nt = 0; nt < 4; nt++) {
            rm1 = fmaxf(rm1, fmaxf(sc[nt][0], sc[nt][1]));
            rm2 = fmaxf(rm2, fmaxf(sc[nt][2], sc[nt][3]));
        }
        rm1 = fmaxf(rm1, __shfl_xor_sync(0xffffffffu, rm1, 1));
        rm1 = fmaxf(rm1, __shfl_xor_sync(0xffffffffu, rm1, 2));
        rm2 = fmaxf(rm2, __shfl_xor_sync(0xffffffffu, rm2, 1));
        rm2 = fmaxf(rm2, __shfl_xor_sync(0xffffffffu, rm2, 2));
        const float mn1 = fmaxf(mrow[0], rm1);
        const float mn2 = fmaxf(mrow[1], rm2);
        const float scl1 = __expf(mrow[0] - mn1);
        const float scl2 = __expf(mrow[1] - mn2);
        mrow[0] = mn1; mrow[1] = mn2;

        float ps1 = 0.f, ps2 = 0.f;
#pragma unroll
        for (int nt = 0; nt < 4; nt++) {
            sc[nt][0] = __expf(sc[nt][0] - mn1);
            sc[nt][1] = __expf(sc[nt][1] - mn1);
            sc[nt][2] = __expf(sc[nt][2] - mn2);
            sc[nt][3] = __expf(sc[nt][3] - mn2);
            ps1 += sc[nt][0] + sc[nt][1];
            ps2 += sc[nt][2] + sc[nt][3];
        }
        ps1 += __shfl_xor_sync(0xffffffffu, ps1, 1);
        ps1 += __shfl_xor_sync(0xffffffffu, ps1, 2);
        ps2 += __shfl_xor_sync(0xffffffffu, ps2, 1);
        ps2 += __shfl_xor_sync(0xffffffffu, ps2, 2);
        lsum[0] = lsum[0] * scl1 + ps1;
        lsum[1] = lsum[1] * scl2 + ps2;

#pragma unroll
        for (int nt = 0; nt < 8; nt++) {
            oacc[nt][0] *= scl1; oacc[nt][1] *= scl1;
            oacc[nt][2] *= scl2; oacc[nt][3] *= scl2;
        }

        // ---- pack P (hi only) ----
        uint32_t pha[2][4];
#pragma unroll
        for (int j = 0; j < 2; j++) {
            pha[j][0] = pack_bf2(sc[2*j][0],   sc[2*j][1]);
            pha[j][1] = pack_bf2(sc[2*j][2],   sc[2*j][3]);
            pha[j][2] = pack_bf2(sc[2*j+1][0], sc[2*j+1][1]);
            pha[j][3] = pack_bf2(sc[2*j+1][2], sc[2*j+1][3]);
        }

        // ---- PV (bf16x2: P_hi x V_hi + P_hi x V_lo) ----
#pragma unroll
        for (int j = 0; j < 2; j++) {
            uint32_t vh2[8][2], vl2[8][2];
#pragma unroll
            for (int np = 0; np < 4; np++) {
                const uint32_t ad = sb + 3 * KOP +
                    (j * 16 + ((gg & 1) << 3) + l8) * ATS +
                    (np * 16 + ((gg >> 1) << 3)) * 2;
                uint32_t t0, t1, t2, t3;
                ldm_x4t(t0, t1, t2, t3, ad);
                vh2[np*2][0] = t0; vh2[np*2][1] = t1;
                vh2[np*2+1][0] = t2; vh2[np*2+1][1] = t3;
                ldm_x4t(t0, t1, t2, t3, ad + KOP);
                vl2[np*2][0] = t0; vl2[np*2][1] = t1;
                vl2[np*2+1][0] = t2; vl2[np*2+1][1] = t3;
            }
#pragma unroll
            for (int nt = 0; nt < 8; nt++)
                mma16816(oacc[nt], pha[j], vh2[nt]);
#pragma unroll
            for (int nt = 0; nt < 8; nt++)
                mma16816(oacc[nt], pha[j], vl2[nt]);
        }
        __syncthreads();
    }

    const float rr1 = (lsum[0] > 0.f) ? (1.f / lsum[0]) : 0.f;
    const float rr2 = (lsum[1] > 0.f) ? (1.f / lsum[1]) : 0.f;
    const size_t base1 = (size_t)(b * SS + r1) * DD + hc;
    const size_t base2 = (size_t)(b * SS + r2) * DD + hc;
#pragma unroll
    for (int nt = 0; nt < 8; nt++) {
        const int co = nt * 8 + qcb;
        uint32_t hi, lo;
        split2(oacc[nt][0] * rr1, oacc[nt][1] * rr1, hi, lo);
        *(uint32_t*)(Oh + base1 + co) = hi;
        *(uint32_t*)(Ol + base1 + co) = lo;
        split2(oacc[nt][2] * rr2, oacc[nt][3] * rr2, hi, lo);
        *(uint32_t*)(Oh + base2 + co) = hi;
        *(uint32_t*)(Ol + base2 + co) = lo;
    }
}

// ---------------------------------------------------------------------------
// In-place LayerNorm: one warp per row of 512 floats.
// ---------------------------------------------------------------------------
__global__ __launch_bounds__(256) void ln_kernel(
    float* __restrict__ X, const float* __restrict__ gam, const float* __restrict__ bet)
{
    const int warp = threadIdx.x >> 5, lane = threadIdx.x & 31;
    const size_t row = (size_t)blockIdx.x * 8 + warp;
    float* xr = X + row * DD;

    float4 v[4];
    float s = 0.f, s2 = 0.f;
#pragma unroll
    for (int w = 0; w < 4; w++) {
        v[w] = *(const float4*)(xr + w * 128 + lane * 4);
        s  += v[w].x + v[w].y + v[w].z + v[w].w;
        s2 += v[w].x * v[w].x + v[w].y * v[w].y + v[w].z * v[w].z + v[w].w * v[w].w;
    }
#pragma unroll
    for (int o = 16; o > 0; o >>= 1) {
        s  += __shfl_xor_sync(0xffffffffu, s,  o);
        s2 += __shfl_xor_sync(0xffffffffu, s2, o);
    }
    const float mu  = s * (1.f / DD);
    const float var = s2 * (1.f / DD) - mu * mu;
    const float inv = rsqrtf(var + 1e-5f);
#pragma unroll
    for (int w = 0; w < 4; w++) {
        const int c = w * 128 + lane * 4;
        float4 gv = *(const float4*)(gam + c);
        float4 bv = *(const float4*)(bet + c);
        float4 o;
        o.x = (v[w].x - mu) * inv * gv.x + bv.x;
        o.y = (v[w].y - mu) * inv * gv.y + bv.y;
        o.z = (v[w].z - mu) * inv * gv.z + bv.z;
        o.w = (v[w].w - mu) * inv * gv.w + bv.w;
        *(float4*)(xr + c) = o;
    }
}

// ---------------------------------------------------------------------------
extern "C" void kernel_launch(void* const* d_in, const int* in_sizes, int n_in,
                              void* d_out, int out_size)
{
    const float* q_in  = (const float*)d_in[0];
    const float* k_in  = (const float*)d_in[1];
    const float* v_in  = (const float*)d_in[2];
    const int*   smask = (const int*)  d_in[3];
    const float* Wq    = (const float*)d_in[4];
    const float* bq    = (const float*)d_in[5];
    const float* Wv    = (const float*)d_in[6];
    const float* bv    = (const float*)d_in[7];
    const float* Wo    = (const float*)d_in[8];
    const float* bo    = (const float*)d_in[9];
    const float* gam   = (const float*)d_in[10];
    const float* ln_g  = (const float*)d_in[11];
    const float* ln_b  = (const float*)d_in[12];
    float* out = (float*)d_out;

    __nv_bfloat16 *Xqh, *Xql, *Xkh, *Xkl, *Xvh, *Xvl;
    __nv_bfloat16 *Qh, *Ql, *Kh, *Kl, *Vh, *Vl, *Oh, *Ol;
    __nv_bfloat16 *Wqh, *Wql, *Wvh, *Wvl, *Woh, *Wol;
    unsigned long long* mbits;
    cudaGetSymbolAddress((void**)&Xqh, g_Xqh); cudaGetSymbolAddress((void**)&Xql, g_Xql);
    cudaGetSymbolAddress((void**)&Xkh, g_Xkh); cudaGetSymbolAddress((void**)&Xkl, g_Xkl);
    cudaGetSymbolAddress((void**)&Xvh, g_Xvh); cudaGetSymbolAddress((void**)&Xvl, g_Xvl);
    cudaGetSymbolAddress((void**)&Qh, g_Qh);   cudaGetSymbolAddress((void**)&Ql, g_Ql);
    cudaGetSymbolAddress((void**)&Kh, g_Kh);   cudaGetSymbolAddress((void**)&Kl, g_Kl);
    cudaGetSymbolAddress((void**)&Vh, g_Vh);   cudaGetSymbolAddress((void**)&Vl, g_Vl);
    cudaGetSymbolAddress((void**)&Oh, g_Oh);   cudaGetSymbolAddress((void**)&Ol, g_Ol);
    cudaGetSymbolAddress((void**)&Wqh, g_Wqh); cudaGetSymbolAddress((void**)&Wql, g_Wql);
    cudaGetSymbolAddress((void**)&Wvh, g_Wvh); cudaGetSymbolAddress((void**)&Wvl, g_Wvl);
    cudaGetSymbolAddress((void**)&Woh, g_Woh); cudaGetSymbolAddress((void**)&Wol, g_Wol);
    cudaGetSymbolAddress((void**)&mbits, g_mbits);

    cudaFuncSetAttribute(mma_gemm_kernel, cudaFuncAttributeMaxDynamicSharedMemorySize,
                         (int)MMG_SMEM);
    cudaFuncSetAttribute(mma_gemm64_kernel, cudaFuncAttributeMaxDynamicSharedMemorySize,
                         (int)MMG64_SMEM);
    cudaFuncSetAttribute(attn_mma_kernel, cudaFuncAttributeMaxDynamicSharedMemorySize,
                         (int)AT_SMEM);

    const dim3 gb(256);

    // fused prepasses
    prep_kernel<<<PREP_TOTAL_B, gb>>>(
        q_in, k_in, v_in, Xqh, Xql, Xkh, Xkl, Xvh, Xvl,
        Wq, Wv, Wo, Wqh, Wql, Wvh, Wvl, Woh, Wol,
        smask, mbits);

    // Q + K + V projections fused in one launch (grid.z = 3);
    // Q/K use bf16x2 (score path), V keeps bf16x3.
    const dim3 ggrid3(DD / 128, MM / 128, 3);
    mma_gemm_kernel<<<ggrid3, gb, MMG_SMEM>>>(
        Xqh, Xql, Xkh, Xkl, Xvh, Xvl,
        Wqh, Wql, Wvh, Wvl,
        bq, bv,
        Qh, Ql, Kh, Kl, Vh, Vl);

    // tensor-core attention: 1024 CTAs, heavy-first, 3 CTAs/SM
    attn_mma_kernel<<<1024, 128, AT_SMEM>>>(Qh, Ql, Kh, Kl, Vh, Vl,
                                            Xqh, Xql, Xkh, mbits, gam, Oh, Ol);

    // output projection + bias + residual -> fp32 out (64-row tiles, balanced)
    const dim3 ggrid64(DD / 128, MM / 64);
    mma_gemm64_kernel<<<ggrid64, 128, MMG64_SMEM>>>(
        Oh, Ol, Woh, Wol, bo, q_in, out);

    // in-place LayerNorm
    ln_kernel<<<MM / 8, gb>>>(out, ln_g, ln_b);
}